// round 4
// baseline (speedup 1.0000x reference)
#include <cuda_runtime.h>
#include <cuda_bf16.h>
#include <math.h>

#define BB 4
#define NSEQ 8192
#define DD 512
#define HH 2
#define DH 64
#define INNER 128
#define MM 256
#define LLM 32
#define BH (BB*HH)
#define TOK (BB*NSEQ)
#define KERN 33

typedef unsigned u32;
typedef unsigned short u16;

__device__ float g_xn[(size_t)TOK*DD];
__device__ float g_q[(size_t)BH*NSEQ*DH];
__device__ float g_k[(size_t)BH*NSEQ*DH];
__device__ float g_v[(size_t)BH*NSEQ*DH];
__device__ float g_ql[BH*MM*DH];
__device__ float g_kl[BH*MM*DH];
__device__ float g_a2[BH*MM*MM];
__device__ float g_xz[BH*MM*MM];
__device__ float g_t1[BH*MM*MM];
__device__ float g_t2[BH*MM*MM];
__device__ float g_za[BH*MM*MM];
__device__ float g_zb[BH*MM*MM];
__device__ float g_sim[(size_t)BH*MM*NSEQ];
__device__ float g_a3v[BH*MM*DH];
__device__ float g_w2[BH*MM*DH];
__device__ float g_out1[(size_t)BH*NSEQ*DH];
__device__ float g_part[BH*8*MM*DH];
__device__ unsigned g_max0, g_max1;
__device__ unsigned g_barcnt;
__device__ volatile unsigned g_bargen;

// ---------- bf16 mma helpers ----------
__device__ __forceinline__ u32 pk2(float lo, float hi) {
    u32 r; asm("cvt.rn.bf16x2.f32 %0, %2, %1;" : "=r"(r) : "f"(lo), "f"(hi)); return r;
}
__device__ __forceinline__ u16 bf1(float f) {
    __nv_bfloat16 h = __float2bfloat16(f); return *(u16*)&h;
}
__device__ __forceinline__ void mmab(float* c, const u32* a, const u32* b) {
    asm volatile("mma.sync.aligned.m16n8k16.row.col.f32.bf16.bf16.f32 "
        "{%0,%1,%2,%3}, {%4,%5,%6,%7}, {%8,%9}, {%0,%1,%2,%3};"
        : "+f"(c[0]), "+f"(c[1]), "+f"(c[2]), "+f"(c[3])
        : "r"(a[0]), "r"(a[1]), "r"(a[2]), "r"(a[3]), "r"(b[0]), "r"(b[1]));
}
// A-frag: rows r, r+8; k at ks(=16s+2t) and ks+8.  SR = row stride in u16.
__device__ __forceinline__ void ldA(u32* af, const u16* As, int r, int ks, int SR) {
    af[0] = *(const u32*)&As[r*SR + ks];
    af[1] = *(const u32*)&As[(r+8)*SR + ks];
    af[2] = *(const u32*)&As[r*SR + ks + 8];
    af[3] = *(const u32*)&As[(r+8)*SR + ks + 8];
}
__device__ __forceinline__ void ldB(u32* bf4, const u16* Bs, int n, int ks, int SR) {
    bf4[0] = *(const u32*)&Bs[n*SR + ks];
    bf4[1] = *(const u32*)&Bs[n*SR + ks + 8];
}
__device__ __forceinline__ void st4(u16* S, int row, int c, float4 v, int SR) {
    *(uint2*)&S[row*SR + c] = make_uint2(pk2(v.x, v.y), pk2(v.z, v.w));
}

__global__ void init_kernel() { g_max0 = 0u; g_max1 = 0u; g_barcnt = 0u; g_bargen = 0u; }

__global__ __launch_bounds__(128) void ln_kernel(const float* __restrict__ x,
                                                 const float* __restrict__ gamma,
                                                 const float* __restrict__ beta) {
    int t = blockIdx.x, tid = threadIdx.x;
    const float4* xr = (const float4*)(x + (size_t)t * DD);
    float4 v = xr[tid];
    float s  = v.x + v.y + v.z + v.w;
    float sq = v.x*v.x + v.y*v.y + v.z*v.z + v.w*v.w;
    __shared__ float sb[8];
    #pragma unroll
    for (int o = 16; o; o >>= 1) {
        s  += __shfl_xor_sync(0xffffffffu, s, o);
        sq += __shfl_xor_sync(0xffffffffu, sq, o);
    }
    int w = tid >> 5, l = tid & 31;
    if (l == 0) { sb[w] = s; sb[4 + w] = sq; }
    __syncthreads();
    if (tid == 0) { sb[0] = sb[0]+sb[1]+sb[2]+sb[3]; sb[4] = sb[4]+sb[5]+sb[6]+sb[7]; }
    __syncthreads();
    float mu  = sb[0] * (1.f / DD);
    float var = sb[4] * (1.f / DD) - mu * mu;
    float rs  = rsqrtf(var + 1e-5f);
    float4 g4 = ((const float4*)gamma)[tid];
    float4 b4 = ((const float4*)beta)[tid];
    float4 o;
    o.x = (v.x - mu) * rs * g4.x + b4.x;
    o.y = (v.y - mu) * rs * g4.y + b4.y;
    o.z = (v.z - mu) * rs * g4.z + b4.z;
    o.w = (v.w - mu) * rs * g4.w + b4.w;
    ((float4*)(g_xn + (size_t)t * DD))[tid] = o;
}

__global__ void landmark_kernel() {
    int bh = blockIdx.x, m = blockIdx.y, d = threadIdx.x;
    size_t base = ((size_t)bh * NSEQ + m * LLM) * DH + d;
    float sq = 0.f, sk = 0.f;
    #pragma unroll 8
    for (int i = 0; i < LLM; i++) { sq += g_q[base + (size_t)i * DH]; sk += g_k[base + (size_t)i * DH]; }
    g_ql[(bh * MM + m) * DH + d] = sq * (1.f / LLM);
    g_kl[(bh * MM + m) * DH + d] = sk * (1.f / LLM);
}

__global__ __launch_bounds__(256) void sim2_kernel() {
    int bh = blockIdx.x >> 8, i = blockIdx.x & 255;
    int tid = threadIdx.x;
    __shared__ float qs[DH];
    __shared__ float red[8];
    if (tid < DH) qs[tid] = g_ql[(bh * MM + i) * DH + tid];
    __syncthreads();
    const float* kr = &g_kl[(bh * MM + tid) * DH];
    float s = 0.f;
    #pragma unroll
    for (int d = 0; d < DH; d += 4) {
        float4 kv = *(const float4*)&kr[d];
        s += qs[d]*kv.x + qs[d+1]*kv.y + qs[d+2]*kv.z + qs[d+3]*kv.w;
    }
    float m = s;
    #pragma unroll
    for (int o = 16; o; o >>= 1) m = fmaxf(m, __shfl_xor_sync(0xffffffffu, m, o));
    int w = tid >> 5, l = tid & 31;
    if (l == 0) red[w] = m;
    __syncthreads();
    if (w == 0) {
        float t = red[l & 7];
        #pragma unroll
        for (int o = 4; o; o >>= 1) t = fmaxf(t, __shfl_xor_sync(0xffffffffu, t, o));
        if (l == 0) red[0] = t;
    }
    __syncthreads();
    m = red[0];
    __syncthreads();
    float e = __expf(s - m);
    float su = e;
    #pragma unroll
    for (int o = 16; o; o >>= 1) su += __shfl_xor_sync(0xffffffffu, su, o);
    if (l == 0) red[w] = su;
    __syncthreads();
    if (w == 0) {
        float t = red[l & 7];
        #pragma unroll
        for (int o = 4; o; o >>= 1) t += __shfl_xor_sync(0xffffffffu, t, o);
        if (l == 0) red[0] = t;
    }
    __syncthreads();
    g_a2[((size_t)bh * MM + i) * MM + tid] = e / red[0];
}

__global__ __launch_bounds__(256) void absmax_kernel() {
    int bh = blockIdx.x, mode = blockIdx.y, tid = threadIdx.x;
    const float* A = &g_a2[(size_t)bh * MM * MM];
    float s = 0.f;
    if (mode == 0) { for (int j = 0; j < MM; j++) s += fabsf(A[tid * MM + j]); }
    else           { for (int i = 0; i < MM; i++) s += fabsf(A[i * MM + tid]); }
    float m = s;
    #pragma unroll
    for (int o = 16; o; o >>= 1) m = fmaxf(m, __shfl_xor_sync(0xffffffffu, m, o));
    __shared__ float red[8];
    int w = tid >> 5, l = tid & 31;
    if (l == 0) red[w] = m;
    __syncthreads();
    if (tid == 0) {
        float t = red[0];
        for (int u = 1; u < 8; u++) t = fmaxf(t, red[u]);
        atomicMax(mode == 0 ? &g_max0 : &g_max1, __float_as_uint(t));
    }
}

__global__ __launch_bounds__(256) void softmaxN_kernel() {
    __shared__ float buf[NSEQ];
    __shared__ float red[8];
    int tid = threadIdx.x;
    float* row = &g_sim[(size_t)blockIdx.x * NSEQ];
    float4* b4 = (float4*)buf;
    const float4* r4 = (const float4*)row;
    float lm = -1e30f;
    #pragma unroll
    for (int u = 0; u < 8; u++) {
        float4 v = r4[tid + u * 256];
        b4[tid + u * 256] = v;
        lm = fmaxf(lm, fmaxf(fmaxf(v.x, v.y), fmaxf(v.z, v.w)));
    }
    #pragma unroll
    for (int o = 16; o; o >>= 1) lm = fmaxf(lm, __shfl_xor_sync(0xffffffffu, lm, o));
    int w = tid >> 5, l = tid & 31;
    if (l == 0) red[w] = lm;
    __syncthreads();
    if (tid == 0) { float t = red[0]; for (int u = 1; u < 8; u++) t = fmaxf(t, red[u]); red[0] = t; }
    __syncthreads();
    float m = red[0];
    __syncthreads();
    float ls = 0.f;
    for (int i = tid; i < NSEQ; i += 256) { float e = __expf(buf[i] - m); buf[i] = e; ls += e; }
    #pragma unroll
    for (int o = 16; o; o >>= 1) ls += __shfl_xor_sync(0xffffffffu, ls, o);
    if (l == 0) red[w] = ls;
    __syncthreads();
    if (tid == 0) { float t = 0.f; for (int u = 0; u < 8; u++) t += red[u]; red[0] = 1.f / t; }
    __syncthreads();
    float inv = red[0];
    float4* o4 = (float4*)row;
    #pragma unroll
    for (int u = 0; u < 8; u++) {
        float4 v = b4[tid + u * 256];
        v.x *= inv; v.y *= inv; v.z *= inv; v.w *= inv;
        o4[tid + u * 256] = v;
    }
}

__global__ __launch_bounds__(256) void softmax256_kernel() {
    int row = blockIdx.x * 8 + (threadIdx.x >> 5);
    int lane = threadIdx.x & 31;
    float4* r = (float4*)&g_sim[(size_t)row * 256];
    float4 v0 = r[lane], v1 = r[lane + 32];
    float m = fmaxf(fmaxf(fmaxf(v0.x, v0.y), fmaxf(v0.z, v0.w)),
                    fmaxf(fmaxf(v1.x, v1.y), fmaxf(v1.z, v1.w)));
    #pragma unroll
    for (int o = 16; o; o >>= 1) m = fmaxf(m, __shfl_xor_sync(0xffffffffu, m, o));
    v0.x = __expf(v0.x-m); v0.y = __expf(v0.y-m); v0.z = __expf(v0.z-m); v0.w = __expf(v0.w-m);
    v1.x = __expf(v1.x-m); v1.y = __expf(v1.y-m); v1.z = __expf(v1.z-m); v1.w = __expf(v1.w-m);
    float s = v0.x+v0.y+v0.z+v0.w+v1.x+v1.y+v1.z+v1.w;
    #pragma unroll
    for (int o = 16; o; o >>= 1) s += __shfl_xor_sync(0xffffffffu, s, o);
    float inv = 1.f / s;
    v0.x*=inv; v0.y*=inv; v0.z*=inv; v0.w*=inv;
    v1.x*=inv; v1.y*=inv; v1.z*=inv; v1.w*=inv;
    r[lane] = v0; r[lane + 32] = v1;
}

__global__ void a3vred_kernel() {
    int e = blockIdx.x * 256 + threadIdx.x;
    int bh = e >> 14, r = e & 16383;
    float s = 0.f;
    #pragma unroll
    for (int ks = 0; ks < 8; ks++) s += g_part[((size_t)bh * 8 + ks) * 16384 + r];
    g_a3v[e] = s;
}

__global__ __launch_bounds__(256) void conv_kernel(const float* __restrict__ wres) {
    __shared__ float sv[160 * 64];
    __shared__ float wl[KERN];
    int bh = blockIdx.y, h = bh & 1;
    int n0 = blockIdx.x * 128;
    int tid = threadIdx.x;
    if (tid < KERN) wl[tid] = wres[h * KERN + tid];
    #pragma unroll
    for (int u = 0; u < 10; u++) {
        int e4 = tid + u * 256;
        int li = e4 >> 4, d4 = (e4 & 15) * 4;
        int n = n0 - 16 + li;
        float4 val = make_float4(0.f, 0.f, 0.f, 0.f);
        if (n >= 0 && n < NSEQ) val = *(const float4*)&g_v[((size_t)bh * NSEQ + n) * DH + d4];
        *(float4*)&sv[li * 64 + d4] = val;
    }
    __syncthreads();
    int d = tid & 63, rg = tid >> 6;
    for (int i = 0; i < 32; i++) {
        int rl = rg * 32 + i;
        float s = 0.f;
        #pragma unroll
        for (int t = 0; t < KERN; t++) s += wl[t] * sv[(rl + t) * 64 + d];
        g_out1[((size_t)bh * NSEQ + n0 + rl) * DH + d] += s;
    }
}

// ---------- bf16 MMA kernels ----------

// qkv: xn(32768x512)@wqkv(512x384). BM=128 BN=128 BK=32, double-buffered smem.
__global__ __launch_bounds__(256) void qkv_mma(const float* __restrict__ wqkv) {
    __shared__ u16 SA[2][128*40], SB[2][128*40];
    int tid = threadIdx.x;
    int row0 = blockIdx.x * 128, col0 = blockIdx.y * 128;
    int lane = tid & 31, wid = tid >> 5;
    int g = lane >> 2, t = lane & 3;
    int wm = (wid & 1) * 64, wn = (wid >> 1) * 32;
    float acc[4][4][4];
    #pragma unroll
    for (int i = 0; i < 4; i++) for (int j = 0; j < 4; j++) for (int u = 0; u < 4; u++) acc[i][j][u] = 0.f;
    float4 aR[4], bR[4];
    auto LOAD = [&](int kt) {
        #pragma unroll
        for (int p = 0; p < 4; p++) {
            int idx = tid + p * 256; int m = idx >> 3, c = (idx & 7) * 4;
            aR[p] = *(const float4*)&g_xn[(size_t)(row0 + m) * DD + kt + c];
        }
        #pragma unroll
        for (int p = 0; p < 4; p++) {
            int idx = tid + p * 256; int k = idx >> 5, n4 = (idx & 31) * 4;
            bR[p] = *(const float4*)&wqkv[(size_t)(kt + k) * 384 + col0 + n4];
        }
    };
    auto STS = [&](int buf) {
        #pragma unroll
        for (int p = 0; p < 4; p++) {
            int idx = tid + p * 256; int m = idx >> 3, c = (idx & 7) * 4;
            st4(SA[buf], m, c, aR[p], 40);
        }
        #pragma unroll
        for (int p = 0; p < 4; p++) {
            int idx = tid + p * 256; int k = idx >> 5, n4 = (idx & 31) * 4;
            SB[buf][(n4+0)*40+k] = bf1(bR[p].x);
            SB[buf][(n4+1)*40+k] = bf1(bR[p].y);
            SB[buf][(n4+2)*40+k] = bf1(bR[p].z);
            SB[buf][(n4+3)*40+k] = bf1(bR[p].w);
        }
    };
    auto COMP = [&](int buf) {
        #pragma unroll
        for (int s = 0; s < 2; s++) {
            int ks = 16*s + 2*t;
            u32 af[4][4], bf4[4][2];
            #pragma unroll
            for (int i = 0; i < 4; i++) ldA(af[i], SA[buf], wm + 16*i + g, ks, 40);
            #pragma unroll
            for (int j = 0; j < 4; j++) ldB(bf4[j], SB[buf], wn + 8*j + g, ks, 40);
            #pragma unroll
            for (int i = 0; i < 4; i++)
                #pragma unroll
                for (int j = 0; j < 4; j++) mmab(acc[i][j], af[i], bf4[j]);
        }
    };
    LOAD(0); STS(0); __syncthreads();
    for (int it = 0; it < 16; it++) {
        if (it + 1 < 16) LOAD((it + 1) * 32);
        COMP(it & 1);
        if (it + 1 < 16) { STS((it + 1) & 1); __syncthreads(); }
    }
    auto STORE = [&](int tok, int c, float v) {
        int bb = tok >> 13, n = tok & 8191;
        int which = c >> 7, hd = c & 127, h = hd >> 6, d = hd & 63;
        size_t dst = (((size_t)(bb * HH + h)) * NSEQ + n) * DH + d;
        if (which == 0)      g_q[dst] = v * 0.125f;
        else if (which == 1) g_k[dst] = v;
        else                 g_v[dst] = v;
    };
    #pragma unroll
    for (int i = 0; i < 4; i++) {
        int row = row0 + wm + 16*i + g;
        #pragma unroll
        for (int j = 0; j < 4; j++) {
            int col = col0 + wn + 8*j + 2*t;
            STORE(row, col, acc[i][j][0]);
            STORE(row, col + 1, acc[i][j][1]);
            STORE(row + 8, col, acc[i][j][2]);
            STORE(row + 8, col + 1, acc[i][j][3]);
        }
    }
}

// outgemm: gather(out1)(32768x128)@wout(128x512) + bias + x
__global__ __launch_bounds__(256) void outgemm_mma(const float* __restrict__ x,
                                                   const float* __restrict__ wout,
                                                   const float* __restrict__ bout,
                                                   float* __restrict__ out) {
    __shared__ u16 SA[2][128*40], SB[2][128*40];
    int tid = threadIdx.x;
    int row0 = blockIdx.x * 128, col0 = blockIdx.y * 128;
    int lane = tid & 31, wid = tid >> 5;
    int g = lane >> 2, t = lane & 3;
    int wm = (wid & 1) * 64, wn = (wid >> 1) * 32;
    float acc[4][4][4];
    #pragma unroll
    for (int i = 0; i < 4; i++) for (int j = 0; j < 4; j++) for (int u = 0; u < 4; u++) acc[i][j][u] = 0.f;
    float4 aR[4], bR[4];
    auto LOAD = [&](int kt) {
        #pragma unroll
        for (int p = 0; p < 4; p++) {
            int idx = tid + p * 256; int m = idx >> 3, c = (idx & 7) * 4;
            int tok = row0 + m; int bb = tok >> 13, n = tok & 8191;
            int k = kt + c; int h = k >> 6, d = k & 63;
            aR[p] = *(const float4*)&g_out1[(((size_t)(bb * HH + h)) * NSEQ + n) * DH + d];
        }
        #pragma unroll
        for (int p = 0; p < 4; p++) {
            int idx = tid + p * 256; int k = idx >> 5, n4 = (idx & 31) * 4;
            bR[p] = *(const float4*)&wout[(size_t)(kt + k) * DD + col0 + n4];
        }
    };
    auto STS = [&](int buf) {
        #pragma unroll
        for (int p = 0; p < 4; p++) {
            int idx = tid + p * 256; int m = idx >> 3, c = (idx & 7) * 4;
            st4(SA[buf], m, c, aR[p], 40);
        }
        #pragma unroll
        for (int p = 0; p < 4; p++) {
            int idx = tid + p * 256; int k = idx >> 5, n4 = (idx & 31) * 4;
            SB[buf][(n4+0)*40+k] = bf1(bR[p].x);
            SB[buf][(n4+1)*40+k] = bf1(bR[p].y);
            SB[buf][(n4+2)*40+k] = bf1(bR[p].z);
            SB[buf][(n4+3)*40+k] = bf1(bR[p].w);
        }
    };
    auto COMP = [&](int buf) {
        #pragma unroll
        for (int s = 0; s < 2; s++) {
            int ks = 16*s + 2*t;
            u32 af[4][4], bf4[4][2];
            #pragma unroll
            for (int i = 0; i < 4; i++) ldA(af[i], SA[buf], wm + 16*i + g, ks, 40);
            #pragma unroll
            for (int j = 0; j < 4; j++) ldB(bf4[j], SB[buf], wn + 8*j + g, ks, 40);
            #pragma unroll
            for (int i = 0; i < 4; i++)
                #pragma unroll
                for (int j = 0; j < 4; j++) mmab(acc[i][j], af[i], bf4[j]);
        }
    };
    LOAD(0); STS(0); __syncthreads();
    for (int it = 0; it < 4; it++) {
        if (it + 1 < 4) LOAD((it + 1) * 32);
        COMP(it & 1);
        if (it + 1 < 4) { STS((it + 1) & 1); __syncthreads(); }
    }
    #pragma unroll
    for (int i = 0; i < 4; i++) {
        int row = row0 + wm + 16*i + g;
        #pragma unroll
        for (int j = 0; j < 4; j++) {
            int col = col0 + wn + 8*j + 2*t;
            out[(size_t)row*DD + col]       = acc[i][j][0] + bout[col]   + x[(size_t)row*DD + col];
            out[(size_t)row*DD + col+1]     = acc[i][j][1] + bout[col+1] + x[(size_t)row*DD + col+1];
            out[(size_t)(row+8)*DD + col]   = acc[i][j][2] + bout[col]   + x[(size_t)(row+8)*DD + col];
            out[(size_t)(row+8)*DD + col+1] = acc[i][j][3] + bout[col+1] + x[(size_t)(row+8)*DD + col+1];
        }
    }
}

// NT, K=64: C[M x N] = A[M x 64] @ B[N x 64]^T per batch. grid(M/128, N/128, BH)
__global__ __launch_bounds__(256) void nt64_mma(const float* __restrict__ A,
                                                const float* __restrict__ B,
                                                float* __restrict__ C) {
    __shared__ u16 As[128*72], Bs[128*72];
    int M = gridDim.x * 128, N = gridDim.y * 128;
    int bh = blockIdx.z;
    const float* Ab = A + (size_t)bh * M * 64 + (size_t)blockIdx.x * 128 * 64;
    const float* Bb = B + (size_t)bh * N * 64 + (size_t)blockIdx.y * 128 * 64;
    int tid = threadIdx.x;
    #pragma unroll
    for (int p = 0; p < 8; p++) {
        int idx = tid + p * 256; int m = idx >> 4, c = (idx & 15) * 4;
        st4(As, m, c, *(const float4*)&Ab[(size_t)m * 64 + c], 72);
        st4(Bs, m, c, *(const float4*)&Bb[(size_t)m * 64 + c], 72);
    }
    __syncthreads();
    int lane = tid & 31, wid = tid >> 5;
    int g = lane >> 2, t = lane & 3;
    int wm = (wid & 1) * 64, wn = (wid >> 1) * 32;
    float acc[4][4][4];
    #pragma unroll
    for (int i = 0; i < 4; i++) for (int j = 0; j < 4; j++) for (int u = 0; u < 4; u++) acc[i][j][u] = 0.f;
    #pragma unroll
    for (int s = 0; s < 4; s++) {
        int ks = 16*s + 2*t;
        u32 af[4][4], bf4[4][2];
        #pragma unroll
        for (int i = 0; i < 4; i++) ldA(af[i], As, wm + 16*i + g, ks, 72);
        #pragma unroll
        for (int j = 0; j < 4; j++) ldB(bf4[j], Bs, wn + 8*j + g, ks, 72);
        #pragma unroll
        for (int i = 0; i < 4; i++)
            #pragma unroll
            for (int j = 0; j < 4; j++) mmab(acc[i][j], af[i], bf4[j]);
    }
    float* Cb = C + (size_t)bh * M * N + (size_t)blockIdx.x * 128 * N + blockIdx.y * 128;
    #pragma unroll
    for (int i = 0; i < 4; i++) {
        int row = wm + 16*i + g;
        #pragma unroll
        for (int j = 0; j < 4; j++) {
            int col = wn + 8*j + 2*t;
            Cb[(size_t)row*N + col]       = acc[i][j][0];
            Cb[(size_t)row*N + col+1]     = acc[i][j][1];
            Cb[(size_t)(row+8)*N + col]   = acc[i][j][2];
            Cb[(size_t)(row+8)*N + col+1] = acc[i][j][3];
        }
    }
}

// NN, N=64: 64x64 tile = A[M x K] @ B[K x 64], optional split-K. grid(M/64, ks, BH), 128 thr.
__global__ __launch_bounds__(128) void nn64_mma(const float* __restrict__ A,
                                                const float* __restrict__ B,
                                                float* __restrict__ C,
                                                int lda, size_t aBatch, size_t bBatch,
                                                size_t cBatch, size_t cSplit, int kchunk) {
    __shared__ u16 As[64*40], Bs[64*40];
    int bh = blockIdx.z, ks2 = blockIdx.y;
    int m0 = blockIdx.x * 64;
    int kbeg = ks2 * kchunk;
    const float* Ab = A + (size_t)bh * aBatch + (size_t)m0 * lda + kbeg;
    const float* Bb = B + (size_t)bh * bBatch + (size_t)kbeg * 64;
    int tid = threadIdx.x;
    int lane = tid & 31, wid = tid >> 5;
    int g = lane >> 2, t = lane & 3;
    int wm = (wid & 1) * 32, wn = (wid >> 1) * 32;
    float acc[2][4][4];
    #pragma unroll
    for (int i = 0; i < 2; i++) for (int j = 0; j < 4; j++) for (int u = 0; u < 4; u++) acc[i][j][u] = 0.f;
    int iters = kchunk / 32;
    for (int it = 0; it < iters; it++) {
        #pragma unroll
        for (int p = 0; p < 4; p++) {
            int idx = tid + p * 128; int m = idx >> 3, c = (idx & 7) * 4;
            st4(As, m, c, *(const float4*)&Ab[(size_t)m * lda + it*32 + c], 40);
        }
        #pragma unroll
        for (int p = 0; p < 4; p++) {
            int idx = tid + p * 128; int k = idx >> 4, n4 = (idx & 15) * 4;
            float4 v = *(const float4*)&Bb[(size_t)(it*32 + k) * 64 + n4];
            Bs[(n4+0)*40+k] = bf1(v.x);
            Bs[(n4+1)*40+k] = bf1(v.y);
            Bs[(n4+2)*40+k] = bf1(v.z);
            Bs[(n4+3)*40+k] = bf1(v.w);
        }
        __syncthreads();
        #pragma unroll
        for (int s = 0; s < 2; s++) {
            int ko = 16*s + 2*t;
            u32 af[2][4], bf4[4][2];
            #pragma unroll
            for (int i = 0; i < 2; i++) ldA(af[i], As, wm + 16*i + g, ko, 40);
            #pragma unroll
            for (int j = 0; j < 4; j++) ldB(bf4[j], Bs, wn + 8*j + g, ko, 40);
            #pragma unroll
            for (int i = 0; i < 2; i++)
                #pragma unroll
                for (int j = 0; j < 4; j++) mmab(acc[i][j], af[i], bf4[j]);
        }
        __syncthreads();
    }
    float* Cb = C + (size_t)bh * cBatch + (size_t)ks2 * cSplit + (size_t)m0 * 64;
    #pragma unroll
    for (int i = 0; i < 2; i++) {
        int row = wm + 16*i + g;
        #pragma unroll
        for (int j = 0; j < 4; j++) {
            int col = wn + 8*j + 2*t;
            Cb[(size_t)row*64 + col]       = acc[i][j][0];
            Cb[(size_t)row*64 + col+1]     = acc[i][j][1];
            Cb[(size_t)(row+8)*64 + col]   = acc[i][j][2];
            Cb[(size_t)(row+8)*64 + col+1] = acc[i][j][3];
        }
    }
}

// ---------- persistent pinv ----------
__device__ __forceinline__ void gridbar() {
    __syncthreads();
    if (threadIdx.x == 0) {
        __threadfence();
        unsigned gen = g_bargen;
        if (atomicAdd(&g_barcnt, 1u) == 127u) {
            g_barcnt = 0u;
            __threadfence();
            g_bargen = gen + 1u;
        } else {
            while (g_bargen == gen) { }
        }
    }
    __syncthreads();
}

// C_tile = alpha*(A@B) + beta*A + gamma*I  on one 64x64 tile; K=256. All loads L2-only.
__device__ __forceinline__ void pinv_phase(const float* A, const float* B, float* C,
                                           float alpha, float beta, float gam,
                                           int i0, int j0, size_t base,
                                           u16* As, u16* Bs) {
    int tid = threadIdx.x;
    int lane = tid & 31, wid = tid >> 5;
    int g = lane >> 2, t = lane & 3;
    int wm = (wid & 1) * 32, wn = (wid >> 1) * 32;
    float acc[2][4][4];
    #pragma unroll
    for (int i = 0; i < 2; i++) for (int j = 0; j < 4; j++) for (int u = 0; u < 4; u++) acc[i][j][u] = 0.f;
    for (int kc = 0; kc < 8; kc++) {
        #pragma unroll
        for (int p = 0; p < 4; p++) {
            int idx = tid + p * 128; int m = idx >> 3, c = (idx & 7) * 4;
            float4 v = __ldcg((const float4*)&A[base + (size_t)(i0 + m) * MM + kc*32 + c]);
            st4(As, m, c, v, 40);
        }
        #pragma unroll
        for (int p = 0; p < 4; p++) {
            int idx = tid + p * 128; int k = idx >> 4, n4 = (idx & 15) * 4;
            float4 v = __ldcg((const float4*)&B[base + (size_t)(kc*32 + k) * MM + j0 + n4]);
            Bs[(n4+0)*40+k] = bf1(v.x);
            Bs[(n4+1)*40+k] = bf1(v.y);
            Bs[(n4+2)*40+k] = bf1(v.z);
            Bs[(n4+3)*40+k] = bf1(v.w);
        }
        __syncthreads();
        #pragma unroll
        for (int s = 0; s < 2; s++) {
            int ko = 16*s + 2*t;
            u32 af[2][4], bf4[4][2];
            #pragma unroll
            for (int i = 0; i < 2; i++) ldA(af[i], As, wm + 16*i + g, ko, 40);
            #pragma unroll
            for (int j = 0; j < 4; j++) ldB(bf4[j], Bs, wn + 8*j + g, ko, 40);
            #pragma unroll
            for (int i = 0; i < 2; i++)
                #pragma unroll
                for (int j = 0; j < 4; j++) mmab(acc[i][j], af[i], bf4[j]);
        }
        __syncthreads();
    }
    #pragma unroll
    for (int i = 0; i < 2; i++) {
        #pragma unroll
        for (int j = 0; j < 4; j++) {
            #pragma unroll
            for (int u = 0; u < 4; u++) {
                int row = i0 + wm + 16*i + g + (u >> 1) * 8;
                int col = j0 + wn + 8*j + 2*t + (u & 1);
                float r = alpha * acc[i][j][u];
                if (beta != 0.f) r += beta * __ldcg(&A[base + (size_t)row * MM + col]);
                if (row == col) r += gam;
                C[base + (size_t)row * MM + col] = r;
            }
        }
    }
}

__global__ __launch_bounds__(128) void pinv_kernel() {
    __shared__ u16 As[64*40], Bs[64*40];
    int cta = blockIdx.x;
    int bh = cta >> 4, tile = cta & 15;
    int i0 = (tile >> 2) * 64, j0 = (tile & 3) * 64;
    size_t base = (size_t)bh * MM * MM;
    float inv = 1.f / (__uint_as_float(g_max0) * __uint_as_float(g_max1));
    for (int e = threadIdx.x; e < 64 * 64; e += 128) {
        int r = e >> 6, c = e & 63;
        g_za[base + (size_t)(i0 + r) * MM + j0 + c] =
            __ldcg(&g_a2[base + (size_t)(j0 + c) * MM + i0 + r]) * inv;
    }
    gridbar();
    float* zc = g_za;
    float* zn = g_zb;
    for (int it = 0; it < 6; it++) {
        pinv_phase(g_a2, zc, g_xz, 1.f, 0.f, 0.f, i0, j0, base, As, Bs); gridbar();
        pinv_phase(g_xz, g_xz, g_t1, 1.f, -7.f, 15.f, i0, j0, base, As, Bs); gridbar();
        pinv_phase(g_xz, g_t1, g_t2, -1.f, 0.f, 13.f, i0, j0, base, As, Bs); gridbar();
        pinv_phase(zc, g_t2, zn, 0.25f, 0.f, 0.f, i0, j0, base, As, Bs); gridbar();
        float* tt = zc; zc = zn; zn = tt;
    }
}

// ---------------- launch ----------------
extern "C" void kernel_launch(void* const* d_in, const int* in_sizes, int n_in,
                              void* d_out, int out_size) {
    const float* x     = (const float*)d_in[0];
    const float* gamma = (const float*)d_in[1];
    const float* beta  = (const float*)d_in[2];
    const float* wqkv  = (const float*)d_in[3];
    const float* wout  = (const float*)d_in[4];
    const float* bout  = (const float*)d_in[5];
    const float* wres  = (const float*)d_in[6];
    float* out = (float*)d_out;

    float *pQL, *pKL, *pQ, *pK, *pV, *pSIM, *pPART, *pA3V, *pW2, *pOUT1, *pZA;
    cudaGetSymbolAddress((void**)&pQL, g_ql);
    cudaGetSymbolAddress((void**)&pKL, g_kl);
    cudaGetSymbolAddress((void**)&pQ, g_q);
    cudaGetSymbolAddress((void**)&pK, g_k);
    cudaGetSymbolAddress((void**)&pV, g_v);
    cudaGetSymbolAddress((void**)&pSIM, g_sim);
    cudaGetSymbolAddress((void**)&pPART, g_part);
    cudaGetSymbolAddress((void**)&pA3V, g_a3v);
    cudaGetSymbolAddress((void**)&pW2, g_w2);
    cudaGetSymbolAddress((void**)&pOUT1, g_out1);
    cudaGetSymbolAddress((void**)&pZA, g_za);

    init_kernel<<<1, 1>>>();
    ln_kernel<<<TOK, 128>>>(x, gamma, beta);
    qkv_mma<<<dim3(TOK / 128, 3), 256>>>(wqkv);
    landmark_kernel<<<dim3(BH, MM), 64>>>();
    sim2_kernel<<<BH * MM, 256>>>();
    absmax_kernel<<<dim3(BH, 2), 256>>>();
    pinv_kernel<<<128, 128>>>();               // z ends in g_za (6 swaps)

    // sim3 = q_l @ k^T
    nt64_mma<<<dim3(2, 64, BH), 256>>>(pQL, pK, pSIM);
    softmaxN_kernel<<<BH * MM, 256>>>();
    // a3 @ v split-K partials
    nn64_mma<<<dim3(4, 8, BH), 128>>>(pSIM, pV, pPART, NSEQ,
        (size_t)MM * NSEQ, (size_t)NSEQ * 64, (size_t)8 * MM * 64, (size_t)MM * 64, 1024);
    a3vred_kernel<<<512, 256>>>();
    // W2 = Z @ a3v
    nn64_mma<<<dim3(4, 1, BH), 128>>>(pZA, pA3V, pW2, MM,
        (size_t)MM * MM, (size_t)MM * 64, (size_t)MM * 64, 0, MM);
    // sim1 = q @ k_l^T
    nt64_mma<<<dim3(64, 2, BH), 256>>>(pQ, pKL, pSIM);
    softmax256_kernel<<<BH * NSEQ / 8, 256>>>();
    // out1 = a1 @ W2
    nn64_mma<<<dim3(128, 1, BH), 128>>>(pSIM, pW2, pOUT1, MM,
        (size_t)NSEQ * MM, (size_t)MM * 64, (size_t)NSEQ * 64, 0, MM);
    conv_kernel<<<dim3(NSEQ / 128, BH), 256>>>(wres);
    outgemm_mma<<<dim3(TOK / 128, 4), 256>>>(x, wout, bout, out);
}

// round 5
// speedup vs baseline: 1.2412x; 1.2412x over previous
#include <cuda_runtime.h>
#include <math.h>

#define BB 4
#define NSEQ 8192
#define DD 512
#define HH 2
#define DH 64
#define INNER 128
#define MM 256
#define LLM 32
#define BH (BB*HH)
#define TOK (BB*NSEQ)
#define KERN 33

typedef unsigned u32;

__device__ float g_xn[(size_t)TOK*DD];
__device__ float g_q[(size_t)BH*NSEQ*DH];
__device__ float g_k[(size_t)BH*NSEQ*DH];
__device__ float g_v[(size_t)BH*NSEQ*DH];
__device__ float g_ql[BH*MM*DH];
__device__ float g_kl[BH*MM*DH];
__device__ float g_a2[BH*MM*MM];
__device__ float g_xz[BH*MM*MM];
__device__ float g_t1[BH*MM*MM];
__device__ float g_t2[BH*MM*MM];
__device__ float g_za[BH*MM*MM];
__device__ float g_zb[BH*MM*MM];
__device__ float g_a3v[BH*MM*DH];
__device__ float g_w2[BH*MM*DH];
__device__ float g_out1[(size_t)BH*NSEQ*DH];
__device__ float g_part[BH*8*MM*DH];
__device__ float g_m[BH*4*MM];
__device__ float g_l[BH*4*MM];
__device__ unsigned g_max0, g_max1;

__device__ __forceinline__ unsigned f2tf(float f) {
    unsigned r; asm("cvt.rna.tf32.f32 %0, %1;" : "=r"(r) : "f"(f)); return r;
}
__device__ __forceinline__ void mma8(float* c, const unsigned* a, const unsigned* b) {
    asm volatile("mma.sync.aligned.m16n8k8.row.col.f32.tf32.tf32.f32 "
        "{%0,%1,%2,%3}, {%4,%5,%6,%7}, {%8,%9}, {%0,%1,%2,%3};"
        : "+f"(c[0]), "+f"(c[1]), "+f"(c[2]), "+f"(c[3])
        : "r"(a[0]), "r"(a[1]), "r"(a[2]), "r"(a[3]), "r"(b[0]), "r"(b[1]));
}

__global__ void init_kernel() { g_max0 = 0u; g_max1 = 0u; }

__global__ __launch_bounds__(128) void ln_kernel(const float* __restrict__ x,
                                                 const float* __restrict__ gamma,
                                                 const float* __restrict__ beta) {
    int t = blockIdx.x, tid = threadIdx.x;
    const float4* xr = (const float4*)(x + (size_t)t * DD);
    float4 v = xr[tid];
    float s  = v.x + v.y + v.z + v.w;
    float sq = v.x*v.x + v.y*v.y + v.z*v.z + v.w*v.w;
    __shared__ float sb[8];
    #pragma unroll
    for (int o = 16; o; o >>= 1) {
        s  += __shfl_xor_sync(0xffffffffu, s, o);
        sq += __shfl_xor_sync(0xffffffffu, sq, o);
    }
    int w = tid >> 5, l = tid & 31;
    if (l == 0) { sb[w] = s; sb[4 + w] = sq; }
    __syncthreads();
    if (tid == 0) { sb[0] = sb[0]+sb[1]+sb[2]+sb[3]; sb[4] = sb[4]+sb[5]+sb[6]+sb[7]; }
    __syncthreads();
    float mu  = sb[0] * (1.f / DD);
    float var = sb[4] * (1.f / DD) - mu * mu;
    float rs  = rsqrtf(var + 1e-5f);
    float4 g4 = ((const float4*)gamma)[tid];
    float4 b4 = ((const float4*)beta)[tid];
    float4 o;
    o.x = (v.x - mu) * rs * g4.x + b4.x;
    o.y = (v.y - mu) * rs * g4.y + b4.y;
    o.z = (v.z - mu) * rs * g4.z + b4.z;
    o.w = (v.w - mu) * rs * g4.w + b4.w;
    ((float4*)(g_xn + (size_t)t * DD))[tid] = o;
}

__global__ void landmark_kernel() {
    int bh = blockIdx.x, m = blockIdx.y, d = threadIdx.x;
    size_t base = ((size_t)bh * NSEQ + m * LLM) * DH + d;
    float sq = 0.f, sk = 0.f;
    #pragma unroll 8
    for (int i = 0; i < LLM; i++) { sq += g_q[base + (size_t)i * DH]; sk += g_k[base + (size_t)i * DH]; }
    g_ql[(bh * MM + m) * DH + d] = sq * (1.f / LLM);
    g_kl[(bh * MM + m) * DH + d] = sk * (1.f / LLM);
}

__global__ __launch_bounds__(256) void sim2_kernel() {
    int bh = blockIdx.x >> 8, i = blockIdx.x & 255;
    int tid = threadIdx.x;
    __shared__ float qs[DH];
    __shared__ float red[8];
    if (tid < DH) qs[tid] = g_ql[(bh * MM + i) * DH + tid];
    __syncthreads();
    const float* kr = &g_kl[(bh * MM + tid) * DH];
    float s = 0.f;
    #pragma unroll
    for (int d = 0; d < DH; d += 4) {
        float4 kv = *(const float4*)&kr[d];
        s += qs[d]*kv.x + qs[d+1]*kv.y + qs[d+2]*kv.z + qs[d+3]*kv.w;
    }
    float m = s;
    #pragma unroll
    for (int o = 16; o; o >>= 1) m = fmaxf(m, __shfl_xor_sync(0xffffffffu, m, o));
    int w = tid >> 5, l = tid & 31;
    if (l == 0) red[w] = m;
    __syncthreads();
    if (w == 0) {
        float t = red[l & 7];
        #pragma unroll
        for (int o = 4; o; o >>= 1) t = fmaxf(t, __shfl_xor_sync(0xffffffffu, t, o));
        if (l == 0) red[0] = t;
    }
    __syncthreads();
    m = red[0];
    __syncthreads();
    float e = __expf(s - m);
    float su = e;
    #pragma unroll
    for (int o = 16; o; o >>= 1) su += __shfl_xor_sync(0xffffffffu, su, o);
    if (l == 0) red[w] = su;
    __syncthreads();
    if (w == 0) {
        float t = red[l & 7];
        #pragma unroll
        for (int o = 4; o; o >>= 1) t += __shfl_xor_sync(0xffffffffu, t, o);
        if (l == 0) red[0] = t;
    }
    __syncthreads();
    g_a2[((size_t)bh * MM + i) * MM + tid] = e / red[0];
}

__global__ __launch_bounds__(256) void absmax_kernel() {
    int bh = blockIdx.x, mode = blockIdx.y, tid = threadIdx.x;
    const float* A = &g_a2[(size_t)bh * MM * MM];
    float s = 0.f;
    if (mode == 0) { for (int j = 0; j < MM; j++) s += fabsf(A[tid * MM + j]); }
    else           { for (int i = 0; i < MM; i++) s += fabsf(A[i * MM + tid]); }
    float m = s;
    #pragma unroll
    for (int o = 16; o; o >>= 1) m = fmaxf(m, __shfl_xor_sync(0xffffffffu, m, o));
    __shared__ float red[8];
    int w = tid >> 5, l = tid & 31;
    if (l == 0) red[w] = m;
    __syncthreads();
    if (tid == 0) {
        float t = red[0];
        for (int u = 1; u < 8; u++) t = fmaxf(t, red[u]);
        atomicMax(mode == 0 ? &g_max0 : &g_max1, __float_as_uint(t));
    }
}

__global__ __launch_bounds__(256) void zinit_kernel() {
    int bh = blockIdx.x >> 8, i = blockIdx.x & 255, j = threadIdx.x;
    float inv = 1.f / (__uint_as_float(g_max0) * __uint_as_float(g_max1));
    g_za[((size_t)bh * MM + i) * MM + j] = g_a2[((size_t)bh * MM + j) * MM + i] * inv;
}

__global__ __launch_bounds__(256) void conv_kernel(const float* __restrict__ wres) {
    __shared__ float sv[160 * 64];
    __shared__ float wl[KERN];
    int bh = blockIdx.y, h = bh & 1;
    int n0 = blockIdx.x * 128;
    int tid = threadIdx.x;
    if (tid < KERN) wl[tid] = wres[h * KERN + tid];
    #pragma unroll
    for (int u = 0; u < 10; u++) {
        int e4 = tid + u * 256;
        int li = e4 >> 4, d4 = (e4 & 15) * 4;
        int n = n0 - 16 + li;
        float4 val = make_float4(0.f, 0.f, 0.f, 0.f);
        if (n >= 0 && n < NSEQ) val = *(const float4*)&g_v[((size_t)bh * NSEQ + n) * DH + d4];
        *(float4*)&sv[li * 64 + d4] = val;
    }
    __syncthreads();
    int d = tid & 63, rg = tid >> 6;
    for (int i = 0; i < 32; i++) {
        int rl = rg * 32 + i;
        float s = 0.f;
        #pragma unroll
        for (int t = 0; t < KERN; t++) s += wl[t] * sv[(rl + t) * 64 + d];
        g_out1[((size_t)bh * NSEQ + n0 + rl) * DH + d] += s;
    }
}

// ---------- tf32 MMA kernels (R3-proven) ----------

__global__ __launch_bounds__(256) void qkv_mma(const float* __restrict__ wqkv) {
    extern __shared__ unsigned sm[];
    int tid = threadIdx.x;
    int row0 = blockIdx.x * 128, col0 = blockIdx.y * 128;
    int lane = tid & 31, wid = tid >> 5;
    int g = lane >> 2, t = lane & 3;
    int wm = (wid & 1) * 64, wn = (wid >> 1) * 32;
    float acc[4][4][4];
    #pragma unroll
    for (int i = 0; i < 4; i++) for (int j = 0; j < 4; j++) for (int u = 0; u < 4; u++) acc[i][j][u] = 0.f;
    float4 aR[4], bR[4];
    auto LOAD = [&](int kt) {
        #pragma unroll
        for (int p = 0; p < 4; p++) {
            int idx = tid + p * 256; int m = idx >> 3, c = (idx & 7) * 4;
            aR[p] = *(const float4*)&g_xn[(size_t)(row0 + m) * DD + kt + c];
        }
        #pragma unroll
        for (int p = 0; p < 4; p++) {
            int idx = tid + p * 256; int k = idx >> 5, c = (idx & 31) * 4;
            bR[p] = *(const float4*)&wqkv[(size_t)(kt + k) * 384 + col0 + c];
        }
    };
    auto STS = [&](unsigned* st) {
        unsigned* As = st; unsigned* Bs = st + 4608;
        #pragma unroll
        for (int p = 0; p < 4; p++) {
            int idx = tid + p * 256; int m = idx >> 3, c = (idx & 7) * 4;
            *(uint4*)&As[m * 36 + c] = make_uint4(f2tf(aR[p].x), f2tf(aR[p].y), f2tf(aR[p].z), f2tf(aR[p].w));
        }
        #pragma unroll
        for (int p = 0; p < 4; p++) {
            int idx = tid + p * 256; int k = idx >> 5, c = (idx & 31) * 4;
            *(uint4*)&Bs[k * 136 + c] = make_uint4(f2tf(bR[p].x), f2tf(bR[p].y), f2tf(bR[p].z), f2tf(bR[p].w));
        }
    };
    auto COMP = [&](const unsigned* st) {
        const unsigned* As = st; const unsigned* Bs = st + 4608;
        #pragma unroll
        for (int s = 0; s < 4; s++) {
            unsigned af[4][4], bf[4][2];
            #pragma unroll
            for (int i = 0; i < 4; i++) {
                const unsigned* p = &As[(wm + 16 * i + g) * 36 + 8 * s + t];
                af[i][0] = p[0]; af[i][1] = p[288]; af[i][2] = p[4]; af[i][3] = p[292];
            }
            #pragma unroll
            for (int j = 0; j < 4; j++) {
                const unsigned* p = &Bs[(8 * s + t) * 136 + wn + 8 * j + g];
                bf[j][0] = p[0]; bf[j][1] = p[544];
            }
            #pragma unroll
            for (int i = 0; i < 4; i++)
                #pragma unroll
                for (int j = 0; j < 4; j++) mma8(acc[i][j], af[i], bf[j]);
        }
    };
    LOAD(0); STS(sm); __syncthreads();
    for (int it = 0; it < 16; it++) {
        if (it + 1 < 16) LOAD((it + 1) * 32);
        COMP(sm + (it & 1) * 8960);
        if (it + 1 < 16) { STS(sm + ((it + 1) & 1) * 8960); __syncthreads(); }
    }
    auto STORE = [&](int tok, int c, float v) {
        int bb = tok >> 13, n = tok & 8191;
        int which = c >> 7, hd = c & 127, h = hd >> 6, d = hd & 63;
        size_t dst = (((size_t)(bb * HH + h)) * NSEQ + n) * DH + d;
        if (which == 0)      g_q[dst] = v * 0.125f;
        else if (which == 1) g_k[dst] = v;
        else                 g_v[dst] = v;
    };
    #pragma unroll
    for (int i = 0; i < 4; i++) {
        int row = row0 + wm + 16 * i + g;
        #pragma unroll
        for (int j = 0; j < 4; j++) {
            int col = col0 + wn + 8 * j + 2 * t;
            STORE(row, col, acc[i][j][0]);
            STORE(row, col + 1, acc[i][j][1]);
            STORE(row + 8, col, acc[i][j][2]);
            STORE(row + 8, col + 1, acc[i][j][3]);
        }
    }
}

__global__ __launch_bounds__(256) void outgemm_mma(const float* __restrict__ x,
                                                   const float* __restrict__ wout,
                                                   const float* __restrict__ bout,
                                                   float* __restrict__ out) {
    extern __shared__ unsigned sm[];
    int tid = threadIdx.x;
    int row0 = blockIdx.x * 128, col0 = blockIdx.y * 128;
    int lane = tid & 31, wid = tid >> 5;
    int g = lane >> 2, t = lane & 3;
    int wm = (wid & 1) * 64, wn = (wid >> 1) * 32;
    float acc[4][4][4];
    #pragma unroll
    for (int i = 0; i < 4; i++) for (int j = 0; j < 4; j++) for (int u = 0; u < 4; u++) acc[i][j][u] = 0.f;
    float4 aR[4], bR[4];
    auto LOAD = [&](int kt) {
        #pragma unroll
        for (int p = 0; p < 4; p++) {
            int idx = tid + p * 256; int m = idx >> 3, c = (idx & 7) * 4;
            int tok = row0 + m; int bb = tok >> 13, n = tok & 8191;
            int k = kt + c; int h = k >> 6, d = k & 63;
            aR[p] = *(const float4*)&g_out1[(((size_t)(bb * HH + h)) * NSEQ + n) * DH + d];
        }
        #pragma unroll
        for (int p = 0; p < 4; p++) {
            int idx = tid + p * 256; int k = idx >> 5, c = (idx & 31) * 4;
            bR[p] = *(const float4*)&wout[(size_t)(kt + k) * DD + col0 + c];
        }
    };
    auto STS = [&](unsigned* st) {
        unsigned* As = st; unsigned* Bs = st + 4608;
        #pragma unroll
        for (int p = 0; p < 4; p++) {
            int idx = tid + p * 256; int m = idx >> 3, c = (idx & 7) * 4;
            *(uint4*)&As[m * 36 + c] = make_uint4(f2tf(aR[p].x), f2tf(aR[p].y), f2tf(aR[p].z), f2tf(aR[p].w));
        }
        #pragma unroll
        for (int p = 0; p < 4; p++) {
            int idx = tid + p * 256; int k = idx >> 5, c = (idx & 31) * 4;
            *(uint4*)&Bs[k * 136 + c] = make_uint4(f2tf(bR[p].x), f2tf(bR[p].y), f2tf(bR[p].z), f2tf(bR[p].w));
        }
    };
    auto COMP = [&](const unsigned* st) {
        const unsigned* As = st; const unsigned* Bs = st + 4608;
        #pragma unroll
        for (int s = 0; s < 4; s++) {
            unsigned af[4][4], bf[4][2];
            #pragma unroll
            for (int i = 0; i < 4; i++) {
                const unsigned* p = &As[(wm + 16 * i + g) * 36 + 8 * s + t];
                af[i][0] = p[0]; af[i][1] = p[288]; af[i][2] = p[4]; af[i][3] = p[292];
            }
            #pragma unroll
            for (int j = 0; j < 4; j++) {
                const unsigned* p = &Bs[(8 * s + t) * 136 + wn + 8 * j + g];
                bf[j][0] = p[0]; bf[j][1] = p[544];
            }
            #pragma unroll
            for (int i = 0; i < 4; i++)
                #pragma unroll
                for (int j = 0; j < 4; j++) mma8(acc[i][j], af[i], bf[j]);
        }
    };
    LOAD(0); STS(sm); __syncthreads();
    for (int it = 0; it < 4; it++) {
        if (it + 1 < 4) LOAD((it + 1) * 32);
        COMP(sm + (it & 1) * 8960);
        if (it + 1 < 4) { STS(sm + ((it + 1) & 1) * 8960); __syncthreads(); }
    }
    #pragma unroll
    for (int i = 0; i < 4; i++) {
        int row = row0 + wm + 16 * i + g;
        #pragma unroll
        for (int j = 0; j < 4; j++) {
            int col = col0 + wn + 8 * j + 2 * t;
            out[(size_t)row*DD + col]       = acc[i][j][0] + bout[col]   + x[(size_t)row*DD + col];
            out[(size_t)row*DD + col+1]     = acc[i][j][1] + bout[col+1] + x[(size_t)row*DD + col+1];
            out[(size_t)(row+8)*DD + col]   = acc[i][j][2] + bout[col]   + x[(size_t)(row+8)*DD + col];
            out[(size_t)(row+8)*DD + col+1] = acc[i][j][3] + bout[col+1] + x[(size_t)(row+8)*DD + col+1];
        }
    }
}

// NN, N=64 (used for W2 = Z @ a3v only)
__global__ __launch_bounds__(128) void nn64_mma(const float* __restrict__ A,
                                                const float* __restrict__ B,
                                                float* __restrict__ C,
                                                int lda, size_t aBatch, size_t bBatch,
                                                size_t cBatch, int kchunk) {
    __shared__ unsigned As[64*36];
    __shared__ unsigned Bs[32*72];
    int bh = blockIdx.z;
    int m0 = blockIdx.x * 64;
    const float* Ab = A + (size_t)bh * aBatch + (size_t)m0 * lda;
    const float* Bb = B + (size_t)bh * bBatch;
    int tid = threadIdx.x;
    int lane = tid & 31, wid = tid >> 5;
    int g = lane >> 2, t = lane & 3;
    int wm = (wid & 1) * 32, wn = (wid >> 1) * 32;
    float acc[2][4][4];
    #pragma unroll
    for (int i = 0; i < 2; i++) for (int j = 0; j < 4; j++) for (int u = 0; u < 4; u++) acc[i][j][u] = 0.f;
    int iters = kchunk / 32;
    for (int it = 0; it < iters; it++) {
        #pragma unroll
        for (int p = 0; p < 4; p++) {
            int idx = tid + p * 128; int m = idx >> 3, c = (idx & 7) * 4;
            float4 v = *(const float4*)&Ab[(size_t)m * lda + it*32 + c];
            *(uint4*)&As[m*36+c] = make_uint4(f2tf(v.x), f2tf(v.y), f2tf(v.z), f2tf(v.w));
        }
        #pragma unroll
        for (int p = 0; p < 4; p++) {
            int idx = tid + p * 128; int k = idx >> 4, c = (idx & 15) * 4;
            float4 v = *(const float4*)&Bb[(size_t)(it*32 + k) * 64 + c];
            *(uint4*)&Bs[k*72+c] = make_uint4(f2tf(v.x), f2tf(v.y), f2tf(v.z), f2tf(v.w));
        }
        __syncthreads();
        #pragma unroll
        for (int s = 0; s < 4; s++) {
            unsigned af[2][4], bf[4][2];
            #pragma unroll
            for (int i = 0; i < 2; i++) {
                const unsigned* p = &As[(wm + 16*i + g)*36 + 8*s + t];
                af[i][0] = p[0]; af[i][1] = p[288]; af[i][2] = p[4]; af[i][3] = p[292];
            }
            #pragma unroll
            for (int j = 0; j < 4; j++) {
                const unsigned* p = &Bs[(8*s + t)*72 + wn + 8*j + g];
                bf[j][0] = p[0]; bf[j][1] = p[288];
            }
            #pragma unroll
            for (int i = 0; i < 2; i++)
                #pragma unroll
                for (int j = 0; j < 4; j++) mma8(acc[i][j], af[i], bf[j]);
        }
        __syncthreads();
    }
    float* Cb = C + (size_t)bh * cBatch + (size_t)m0 * 64;
    #pragma unroll
    for (int i = 0; i < 2; i++) {
        int row = wm + 16*i + g;
        #pragma unroll
        for (int j = 0; j < 4; j++) {
            int col = wn + 8*j + 2*t;
            Cb[(size_t)row*64 + col]       = acc[i][j][0];
            Cb[(size_t)row*64 + col+1]     = acc[i][j][1];
            Cb[(size_t)(row+8)*64 + col]   = acc[i][j][2];
            Cb[(size_t)(row+8)*64 + col+1] = acc[i][j][3];
        }
    }
}

// batched 256x256x256: C = alpha*(A@B) + beta*A + gamma*I (pinv chain)
__global__ __launch_bounds__(128) void bmm_mma(const float* __restrict__ A,
                                               const float* __restrict__ Bm,
                                               float* __restrict__ C,
                                               float alpha, float beta, float gam) {
    __shared__ unsigned As[64*36];
    __shared__ unsigned Bs[32*72];
    int bh = blockIdx.z;
    size_t base = (size_t)bh * MM * MM;
    int i0 = blockIdx.x * 64, j0 = blockIdx.y * 64;
    int tid = threadIdx.x;
    int lane = tid & 31, wid = tid >> 5;
    int g = lane >> 2, t = lane & 3;
    int wm = (wid & 1) * 32, wn = (wid >> 1) * 32;
    float acc[2][4][4];
    #pragma unroll
    for (int i = 0; i < 2; i++) for (int j = 0; j < 4; j++) for (int u = 0; u < 4; u++) acc[i][j][u] = 0.f;
    for (int it = 0; it < 8; it++) {
        #pragma unroll
        for (int p = 0; p < 4; p++) {
            int idx = tid + p * 128; int m = idx >> 3, c = (idx & 7) * 4;
            float4 v = *(const float4*)&A[base + (size_t)(i0 + m) * MM + it*32 + c];
            *(uint4*)&As[m*36+c] = make_uint4(f2tf(v.x), f2tf(v.y), f2tf(v.z), f2tf(v.w));
        }
        #pragma unroll
        for (int p = 0; p < 4; p++) {
            int idx = tid + p * 128; int k = idx >> 4, c = (idx & 15) * 4;
            float4 v = *(const float4*)&Bm[base + (size_t)(it*32 + k) * MM + j0 + c];
            *(uint4*)&Bs[k*72+c] = make_uint4(f2tf(v.x), f2tf(v.y), f2tf(v.z), f2tf(v.w));
        }
        __syncthreads();
        #pragma unroll
        for (int s = 0; s < 4; s++) {
            unsigned af[2][4], bf[4][2];
            #pragma unroll
            for (int i = 0; i < 2; i++) {
                const unsigned* p = &As[(wm + 16*i + g)*36 + 8*s + t];
                af[i][0] = p[0]; af[i][1] = p[288]; af[i][2] = p[4]; af[i][3] = p[292];
            }
            #pragma unroll
            for (int j = 0; j < 4; j++) {
                const unsigned* p = &Bs[(8*s + t)*72 + wn + 8*j + g];
                bf[j][0] = p[0]; bf[j][1] = p[288];
            }
            #pragma unroll
            for (int i = 0; i < 2; i++)
                #pragma unroll
                for (int j = 0; j < 4; j++) mma8(acc[i][j], af[i], bf[j]);
        }
        __syncthreads();
    }
    #pragma unroll
    for (int i = 0; i < 2; i++) {
        #pragma unroll
        for (int j = 0; j < 4; j++) {
            #pragma unroll
            for (int u = 0; u < 4; u++) {
                int row = i0 + wm + 16*i + g + (u >> 1) * 8;
                int col = j0 + wn + 8*j + 2*t + (u & 1);
                float r = alpha * acc[i][j][u];
                if (beta != 0.f) r += beta * A[base + (size_t)row * MM + col];
                if (row == col) r += gam;
                C[base + (size_t)row * MM + col] = r;
            }
        }
    }
}

// ---------- fused flash kernels ----------

// attn3: partial_s = online-softmax(ql @ k^T) @ v over keys [sp*2048, +2048)
// grid (4 rowtiles, 4 kvsplits, BH), 256 threads.
__global__ __launch_bounds__(256) void attn3_kernel() {
    extern __shared__ float smf[];
    u32* QS = (u32*)smf;            // [64][68]
    u32* KS = QS + 64*68;           // [128][72]  (key, dim) NT-B
    u32* VS = KS + 128*72;          // [128][72]  (key, dim) NN-B
    float* SS = (float*)(VS + 128*72);  // [64][132] scores -> P (tf32, in place)
    float* sm_m = SS + 64*132;
    float* sm_l = sm_m + 64;
    float* sm_sc = sm_l + 64;
    int tid = threadIdx.x;
    int r0 = blockIdx.x * 64;
    int sp = blockIdx.y;
    int bh = blockIdx.z;
    int lane = tid & 31, wid = tid >> 5;
    int g = lane >> 2, t = lane & 3;
    #pragma unroll
    for (int p = 0; p < 4; p++) {
        int idx = tid + p * 256; int m = idx >> 4, c = (idx & 15) * 4;
        float4 v = *(const float4*)&g_ql[((size_t)bh * MM + r0 + m) * DH + c];
        *(uint4*)&QS[m*68 + c] = make_uint4(f2tf(v.x), f2tf(v.y), f2tf(v.z), f2tf(v.w));
    }
    if (tid < 64) { sm_m[tid] = -1e30f; sm_l[tid] = 0.f; }
    int m0 = (wid & 3) * 16;
    int n0s = (wid >> 2) * 64;
    int n0o = (wid >> 2) * 32;
    float acco[4][4];
    #pragma unroll
    for (int j = 0; j < 4; j++) for (int u = 0; u < 4; u++) acco[j][u] = 0.f;
    __syncthreads();
    for (int ch = 0; ch < 16; ch++) {
        int k0 = sp * 2048 + ch * 128;
        #pragma unroll
        for (int p = 0; p < 8; p++) {
            int idx = tid + p * 256; int key = idx >> 4, c = (idx & 15) * 4;
            float4 kv = *(const float4*)&g_k[((size_t)bh * NSEQ + k0 + key) * DH + c];
            *(uint4*)&KS[key*72 + c] = make_uint4(f2tf(kv.x), f2tf(kv.y), f2tf(kv.z), f2tf(kv.w));
            float4 vv = *(const float4*)&g_v[((size_t)bh * NSEQ + k0 + key) * DH + c];
            *(uint4*)&VS[key*72 + c] = make_uint4(f2tf(vv.x), f2tf(vv.y), f2tf(vv.z), f2tf(vv.w));
        }
        __syncthreads();
        float accs[8][4];
        #pragma unroll
        for (int j = 0; j < 8; j++) for (int u = 0; u < 4; u++) accs[j][u] = 0.f;
        #pragma unroll
        for (int s = 0; s < 8; s++) {
            int ks = 8*s + t;
            u32 af[4];
            af[0] = QS[(m0+g)*68 + ks];   af[1] = QS[(m0+g+8)*68 + ks];
            af[2] = QS[(m0+g)*68 + ks+4]; af[3] = QS[(m0+g+8)*68 + ks+4];
            #pragma unroll
            for (int j = 0; j < 8; j++) {
                int n = n0s + 8*j + g;
                u32 bf2[2];
                bf2[0] = KS[n*72 + ks]; bf2[1] = KS[n*72 + ks + 4];
                mma8(accs[j], af, bf2);
            }
        }
        #pragma unroll
        for (int j = 0; j < 8; j++) {
            int col = n0s + 8*j + 2*t;
            *(float2*)&SS[(m0+g)*132 + col]   = make_float2(accs[j][0], accs[j][1]);
            *(float2*)&SS[(m0+g+8)*132 + col] = make_float2(accs[j][2], accs[j][3]);
        }
        __syncthreads();
        {
            int row = tid >> 2, t2 = tid & 3;
            float* Sr = &SS[row*132 + t2*32];
            float cmax = -1e30f;
            #pragma unroll
            for (int c = 0; c < 32; c++) cmax = fmaxf(cmax, Sr[c]);
            cmax = fmaxf(cmax, __shfl_xor_sync(0xffffffffu, cmax, 1));
            cmax = fmaxf(cmax, __shfl_xor_sync(0xffffffffu, cmax, 2));
            float mold = sm_m[row];
            float mnew = fmaxf(mold, cmax);
            float csum = 0.f;
            u32* Pr = (u32*)Sr;
            #pragma unroll
            for (int c = 0; c < 32; c++) {
                float pv = __expf(Sr[c] - mnew);
                csum += pv;
                Pr[c] = f2tf(pv);
            }
            csum += __shfl_xor_sync(0xffffffffu, csum, 1);
            csum += __shfl_xor_sync(0xffffffffu, csum, 2);
            if (t2 == 0) {
                float scv = __expf(mold - mnew);
                sm_sc[row] = scv;
                sm_l[row] = sm_l[row] * scv + csum;
                sm_m[row] = mnew;
            }
        }
        __syncthreads();
        {
            float s0 = sm_sc[m0 + g], s1 = sm_sc[m0 + g + 8];
            #pragma unroll
            for (int j = 0; j < 4; j++) {
                acco[j][0] *= s0; acco[j][1] *= s0;
                acco[j][2] *= s1; acco[j][3] *= s1;
            }
            const u32* PS = (const u32*)SS;
            #pragma unroll
            for (int s = 0; s < 16; s++) {
                int ks = 8*s + t;
                u32 af[4];
                af[0] = PS[(m0+g)*132 + ks];   af[1] = PS[(m0+g+8)*132 + ks];
                af[2] = PS[(m0+g)*132 + ks+4]; af[3] = PS[(m0+g+8)*132 + ks+4];
                #pragma unroll
                for (int j = 0; j < 4; j++) {
                    int n = n0o + 8*j + g;
                    u32 bf2[2];
                    bf2[0] = VS[ks*72 + n]; bf2[1] = VS[(ks+4)*72 + n];
                    mma8(acco[j], af, bf2);
                }
            }
        }
        __syncthreads();
    }
    size_t pb = ((size_t)(bh*4 + sp) * MM + r0);
    #pragma unroll
    for (int j = 0; j < 4; j++) {
        int col = n0o + 8*j + 2*t;
        *(float2*)&g_part[(pb + m0 + g) * DH + col]     = make_float2(acco[j][0], acco[j][1]);
        *(float2*)&g_part[(pb + m0 + g + 8) * DH + col] = make_float2(acco[j][2], acco[j][3]);
    }
    if (tid < 64) {
        g_m[(bh*4 + sp) * MM + r0 + tid] = sm_m[tid];
        g_l[(bh*4 + sp) * MM + r0 + tid] = sm_l[tid];
    }
}

__global__ void attn_combine() {
    int idx = blockIdx.x * 256 + threadIdx.x;   // BH*MM*DH = 131072
    int bh = idx >> 14, rem = idx & 16383, row = rem >> 6, d = rem & 63;
    float ms = -1e30f;
    #pragma unroll
    for (int s = 0; s < 4; s++) ms = fmaxf(ms, g_m[(bh*4+s)*MM + row]);
    float num = 0.f, den = 0.f;
    #pragma unroll
    for (int s = 0; s < 4; s++) {
        float e = __expf(g_m[(bh*4+s)*MM + row] - ms);
        num += g_part[((size_t)(bh*4+s)*MM + row)*DH + d] * e;
        den += g_l[(bh*4+s)*MM + row] * e;
    }
    g_a3v[((size_t)bh*MM + row)*DH + d] = num / den;
}

// attn1: out1 = softmax(q @ kl^T) @ W2. grid(128 rowtiles, BH), 256 threads.
__global__ __launch_bounds__(256) void attn1_kernel() {
    extern __shared__ float smf[];
    u32* QS  = (u32*)smf;            // [64][68]
    u32* KLS = QS + 64*68;           // [256][72] -> reused as SS/PS [64][264]
    u32* W2S = KLS + 256*72;         // [256][72]
    float* sm_l = (float*)(W2S + 256*72);  // [64]
    float* SS = (float*)KLS;
    int tid = threadIdx.x;
    int r0 = blockIdx.x * 64;
    int bh = blockIdx.y;
    int lane = tid & 31, wid = tid >> 5;
    int g = lane >> 2, t = lane & 3;
    #pragma unroll
    for (int p = 0; p < 4; p++) {
        int idx = tid + p * 256; int m = idx >> 4, c = (idx & 15) * 4;
        float4 v = *(const float4*)&g_q[((size_t)bh * NSEQ + r0 + m) * DH + c];
        *(uint4*)&QS[m*68 + c] = make_uint4(f2tf(v.x), f2tf(v.y), f2tf(v.z), f2tf(v.w));
    }
    #pragma unroll
    for (int p = 0; p < 16; p++) {
        int idx = tid + p * 256; int m = idx >> 4, c = (idx & 15) * 4;
        float4 v = *(const float4*)&g_kl[((size_t)bh * MM + m) * DH + c];
        *(uint4*)&KLS[m*72 + c] = make_uint4(f2tf(v.x), f2tf(v.y), f2tf(v.z), f2tf(v.w));
        float4 w = *(const float4*)&g_w2[((size_t)bh * MM + m) * DH + c];
        *(uint4*)&W2S[m*72 + c] = make_uint4(f2tf(w.x), f2tf(w.y), f2tf(w.z), f2tf(w.w));
    }
    __syncthreads();
    int m0 = (wid & 3) * 16;
    int n0s = (wid >> 2) * 128;
    float accs[16][4];
    #pragma unroll
    for (int j = 0; j < 16; j++) for (int u = 0; u < 4; u++) accs[j][u] = 0.f;
    #pragma unroll
    for (int s = 0; s < 8; s++) {
        int ks = 8*s + t;
        u32 af[4];
        af[0] = QS[(m0+g)*68 + ks];   af[1] = QS[(m0+g+8)*68 + ks];
        af[2] = QS[(m0+g)*68 + ks+4]; af[3] = QS[(m0+g+8)*68 + ks+4];
        #pragma unroll
        for (int j = 0; j < 16; j++) {
            int n = n0s + 8*j + g;
            u32 bf2[2];
            bf2[0] = KLS[n*72 + ks]; bf2[1] = KLS[n*72 + ks + 4];
            mma8(accs[j], af, bf2);
        }
    }
    __syncthreads();   // all warps done reading KLS before SS overwrites it
    #pragma unroll
    for (int j = 0; j < 16; j++) {
        int col = n0s + 8*j + 2*t;
        *(float2*)&SS[(m0+g)*264 + col]   = make_float2(accs[j][0], accs[j][1]);
        *(float2*)&SS[(m0+g+8)*264 + col] = make_float2(accs[j][2], accs[j][3]);
    }
    __syncthreads();
    {
        int row = tid >> 2, t2 = tid & 3;
        float* Sr = &SS[row*264 + t2*64];
        float cmax = -1e30f;
        #pragma unroll
        for (int c = 0; c < 64; c++) cmax = fmaxf(cmax, Sr[c]);
        cmax = fmaxf(cmax, __shfl_xor_sync(0xffffffffu, cmax, 1));
        cmax = fmaxf(cmax, __shfl_xor_sync(0xffffffffu, cmax, 2));
        float csum = 0.f;
        u32* Pr = (u32*)Sr;
        #pragma unroll
        for (int c = 0; c < 64; c++) {
            float pv = __expf(Sr[c] - cmax);
            csum += pv;
            Pr[c] = f2tf(pv);
        }
        csum += __shfl_xor_sync(0xffffffffu, csum, 1);
        csum += __shfl_xor_sync(0xffffffffu, csum, 2);
        if (t2 == 0) sm_l[row] = csum;
    }
    __syncthreads();
    int n0o = (wid >> 2) * 32;
    float acco[4][4];
    #pragma unroll
    for (int j = 0; j < 4; j++) for (int u = 0; u < 4; u++) acco[j][u] = 0.f;
    const u32* PS = (const u32*)SS;
    #pragma unroll
    for (int s = 0; s < 32; s++) {
        int ks = 8*s + t;
        u32 af[4];
        af[0] = PS[(m0+g)*264 + ks];   af[1] = PS[(m0+g+8)*264 + ks];
        af[2] = PS[(m0+g)*264 + ks+4]; af[3] = PS[(m0+g+8)*264 + ks+4];
        #pragma unroll
        for (int j = 0; j < 4; j++) {
            int n = n0o + 8*j + g;
            u32 bf2[2];
            bf2[0] = W2S[ks*72 + n]; bf2[1] = W2S[(ks+4)*72 + n];
            mma8(acco[j], af, bf2);
        }
    }
    float il0 = 1.f / sm_l[m0 + g], il1 = 1.f / sm_l[m0 + g + 8];
    size_t ob = (size_t)bh * NSEQ + r0;
    #pragma unroll
    for (int j = 0; j < 4; j++) {
        int col = n0o + 8*j + 2*t;
        *(float2*)&g_out1[(ob + m0 + g) * DH + col]     = make_float2(acco[j][0]*il0, acco[j][1]*il0);
        *(float2*)&g_out1[(ob + m0 + g + 8) * DH + col] = make_float2(acco[j][2]*il1, acco[j][3]*il1);
    }
}

// ---------------- launch ----------------
extern "C" void kernel_launch(void* const* d_in, const int* in_sizes, int n_in,
                              void* d_out, int out_size) {
    const float* x     = (const float*)d_in[0];
    const float* gamma = (const float*)d_in[1];
    const float* beta  = (const float*)d_in[2];
    const float* wqkv  = (const float*)d_in[3];
    const float* wout  = (const float*)d_in[4];
    const float* bout  = (const float*)d_in[5];
    const float* wres  = (const float*)d_in[6];
    float* out = (float*)d_out;

    float *pA2, *pXZ, *pT1, *pT2, *pZA, *pZB, *pA3V, *pW2;
    cudaGetSymbolAddress((void**)&pA2, g_a2);
    cudaGetSymbolAddress((void**)&pXZ, g_xz);
    cudaGetSymbolAddress((void**)&pT1, g_t1);
    cudaGetSymbolAddress((void**)&pT2, g_t2);
    cudaGetSymbolAddress((void**)&pZA, g_za);
    cudaGetSymbolAddress((void**)&pZB, g_zb);
    cudaGetSymbolAddress((void**)&pA3V, g_a3v);
    cudaGetSymbolAddress((void**)&pW2, g_w2);

    cudaFuncSetAttribute(qkv_mma, cudaFuncAttributeMaxDynamicSharedMemorySize, 71680);
    cudaFuncSetAttribute(outgemm_mma, cudaFuncAttributeMaxDynamicSharedMemorySize, 71680);
    cudaFuncSetAttribute(attn3_kernel, cudaFuncAttributeMaxDynamicSharedMemorySize, 125696);
    cudaFuncSetAttribute(attn1_kernel, cudaFuncAttributeMaxDynamicSharedMemorySize, 165120);

    init_kernel<<<1, 1>>>();
    ln_kernel<<<TOK, 128>>>(x, gamma, beta);
    qkv_mma<<<dim3(TOK / 128, 3), 256, 71680>>>(wqkv);
    landmark_kernel<<<dim3(BH, MM), 64>>>();
    sim2_kernel<<<BH * MM, 256>>>();
    absmax_kernel<<<dim3(BH, 2), 256>>>();
    zinit_kernel<<<BH * MM, 256>>>();

    float* zc = pZA;
    float* zn = pZB;
    for (int it = 0; it < 6; it++) {
        bmm_mma<<<dim3(4, 4, BH), 128>>>(pA2, zc, pXZ, 1.f, 0.f, 0.f);
        bmm_mma<<<dim3(4, 4, BH), 128>>>(pXZ, pXZ, pT1, 1.f, -7.f, 15.f);
        bmm_mma<<<dim3(4, 4, BH), 128>>>(pXZ, pT1, pT2, -1.f, 0.f, 13.f);
        bmm_mma<<<dim3(4, 4, BH), 128>>>(zc, pT2, zn, 0.25f, 0.f, 0.f);
        float* t = zc; zc = zn; zn = t;
    }

    attn3_kernel<<<dim3(4, 4, BH), 256, 125696>>>();
    attn_combine<<<512, 256>>>();
    nn64_mma<<<dim3(4, 1, BH), 128>>>(zc, pA3V, pW2, MM,
        (size_t)MM * MM, (size_t)MM * 64, (size_t)MM * 64, MM);
    attn1_kernel<<<dim3(NSEQ / 64, BH), 256, 165120>>>();
    conv_kernel<<<dim3(NSEQ / 128, BH), 256>>>(wres);
    outgemm_mma<<<dim3(TOK / 128, 4), 256, 71680>>>(x, wout, bout, out);
}

// round 6
// speedup vs baseline: 1.4534x; 1.1709x over previous
#include <cuda_runtime.h>
#include <math.h>

#define BB 4
#define NSEQ 8192
#define DD 512
#define HH 2
#define DH 64
#define INNER 128
#define MM 256
#define LLM 32
#define BH (BB*HH)
#define TOK (BB*NSEQ)
#define KERN 33

typedef unsigned u32;

__device__ float g_xn[(size_t)TOK*DD];
__device__ float g_q[(size_t)BH*NSEQ*DH];
__device__ float g_k[(size_t)BH*NSEQ*DH];
__device__ float g_v[(size_t)BH*NSEQ*DH];
__device__ float g_ql[BH*MM*DH];
__device__ float g_kl[BH*MM*DH];
__device__ float g_a2[BH*MM*MM];
__device__ float g_xz[BH*MM*MM];
__device__ float g_t1[BH*MM*MM];
__device__ float g_t2[BH*MM*MM];
__device__ float g_za[BH*MM*MM];
__device__ float g_zb[BH*MM*MM];
__device__ float g_a3v[BH*MM*DH];
__device__ float g_w2[BH*MM*DH];
__device__ float g_out1[(size_t)BH*NSEQ*DH];
__device__ float g_part[BH*8*MM*DH];
__device__ float g_m[BH*4*MM];
__device__ float g_l[BH*4*MM];
__device__ unsigned g_max0, g_max1;

// ---- tf32 helpers (attn kernels) ----
__device__ __forceinline__ unsigned f2tf(float f) {
    unsigned r; asm("cvt.rna.tf32.f32 %0, %1;" : "=r"(r) : "f"(f)); return r;
}
__device__ __forceinline__ void mma8(float* c, const unsigned* a, const unsigned* b) {
    asm volatile("mma.sync.aligned.m16n8k8.row.col.f32.tf32.tf32.f32 "
        "{%0,%1,%2,%3}, {%4,%5,%6,%7}, {%8,%9}, {%0,%1,%2,%3};"
        : "+f"(c[0]), "+f"(c[1]), "+f"(c[2]), "+f"(c[3])
        : "r"(a[0]), "r"(a[1]), "r"(a[2]), "r"(a[3]), "r"(b[0]), "r"(b[1]));
}
// ---- bf16 helpers (big GEMMs + pinv) ----
__device__ __forceinline__ u32 pk2(float lo, float hi) {
    u32 r; asm("cvt.rn.bf16x2.f32 %0, %2, %1;" : "=r"(r) : "f"(lo), "f"(hi)); return r;
}
__device__ __forceinline__ void mmab(float* c, const u32* a, const u32* b) {
    asm volatile("mma.sync.aligned.m16n8k16.row.col.f32.bf16.bf16.f32 "
        "{%0,%1,%2,%3}, {%4,%5,%6,%7}, {%8,%9}, {%0,%1,%2,%3};"
        : "+f"(c[0]), "+f"(c[1]), "+f"(c[2]), "+f"(c[3])
        : "r"(a[0]), "r"(a[1]), "r"(a[2]), "r"(a[3]), "r"(b[0]), "r"(b[1]));
}
__device__ __forceinline__ uint4 pkA(float4 v1, float4 v2) {
    return make_uint4(pk2(v1.x,v1.y), pk2(v1.z,v1.w), pk2(v2.x,v2.y), pk2(v2.z,v2.w));
}
__device__ __forceinline__ uint4 pkB(float4 r1, float4 r2) {
    return make_uint4(pk2(r1.x,r2.x), pk2(r1.y,r2.y), pk2(r1.z,r2.z), pk2(r1.w,r2.w));
}

__global__ void init_kernel() { g_max0 = 0u; g_max1 = 0u; }

__global__ __launch_bounds__(128) void ln_kernel(const float* __restrict__ x,
                                                 const float* __restrict__ gamma,
                                                 const float* __restrict__ beta) {
    int t = blockIdx.x, tid = threadIdx.x;
    const float4* xr = (const float4*)(x + (size_t)t * DD);
    float4 v = xr[tid];
    float s  = v.x + v.y + v.z + v.w;
    float sq = v.x*v.x + v.y*v.y + v.z*v.z + v.w*v.w;
    __shared__ float sb[8];
    #pragma unroll
    for (int o = 16; o; o >>= 1) {
        s  += __shfl_xor_sync(0xffffffffu, s, o);
        sq += __shfl_xor_sync(0xffffffffu, sq, o);
    }
    int w = tid >> 5, l = tid & 31;
    if (l == 0) { sb[w] = s; sb[4 + w] = sq; }
    __syncthreads();
    if (tid == 0) { sb[0] = sb[0]+sb[1]+sb[2]+sb[3]; sb[4] = sb[4]+sb[5]+sb[6]+sb[7]; }
    __syncthreads();
    float mu  = sb[0] * (1.f / DD);
    float var = sb[4] * (1.f / DD) - mu * mu;
    float rs  = rsqrtf(var + 1e-5f);
    float4 g4 = ((const float4*)gamma)[tid];
    float4 b4 = ((const float4*)beta)[tid];
    float4 o;
    o.x = (v.x - mu) * rs * g4.x + b4.x;
    o.y = (v.y - mu) * rs * g4.y + b4.y;
    o.z = (v.z - mu) * rs * g4.z + b4.z;
    o.w = (v.w - mu) * rs * g4.w + b4.w;
    ((float4*)(g_xn + (size_t)t * DD))[tid] = o;
}

__global__ void landmark_kernel() {
    int bh = blockIdx.x, m = blockIdx.y, d = threadIdx.x;
    size_t base = ((size_t)bh * NSEQ + m * LLM) * DH + d;
    float sq = 0.f, sk = 0.f;
    #pragma unroll 8
    for (int i = 0; i < LLM; i++) { sq += g_q[base + (size_t)i * DH]; sk += g_k[base + (size_t)i * DH]; }
    g_ql[(bh * MM + m) * DH + d] = sq * (1.f / LLM);
    g_kl[(bh * MM + m) * DH + d] = sk * (1.f / LLM);
}

__global__ __launch_bounds__(256) void sim2_kernel() {
    int bh = blockIdx.x >> 8, i = blockIdx.x & 255;
    int tid = threadIdx.x;
    __shared__ float qs[DH];
    __shared__ float red[8];
    if (tid < DH) qs[tid] = g_ql[(bh * MM + i) * DH + tid];
    __syncthreads();
    const float* kr = &g_kl[(bh * MM + tid) * DH];
    float s = 0.f;
    #pragma unroll
    for (int d = 0; d < DH; d += 4) {
        float4 kv = *(const float4*)&kr[d];
        s += qs[d]*kv.x + qs[d+1]*kv.y + qs[d+2]*kv.z + qs[d+3]*kv.w;
    }
    float m = s;
    #pragma unroll
    for (int o = 16; o; o >>= 1) m = fmaxf(m, __shfl_xor_sync(0xffffffffu, m, o));
    int w = tid >> 5, l = tid & 31;
    if (l == 0) red[w] = m;
    __syncthreads();
    if (w == 0) {
        float t = red[l & 7];
        #pragma unroll
        for (int o = 4; o; o >>= 1) t = fmaxf(t, __shfl_xor_sync(0xffffffffu, t, o));
        if (l == 0) red[0] = t;
    }
    __syncthreads();
    m = red[0];
    __syncthreads();
    float e = __expf(s - m);
    float su = e;
    #pragma unroll
    for (int o = 16; o; o >>= 1) su += __shfl_xor_sync(0xffffffffu, su, o);
    if (l == 0) red[w] = su;
    __syncthreads();
    if (w == 0) {
        float t = red[l & 7];
        #pragma unroll
        for (int o = 4; o; o >>= 1) t += __shfl_xor_sync(0xffffffffu, t, o);
        if (l == 0) red[0] = t;
    }
    __syncthreads();
    g_a2[((size_t)bh * MM + i) * MM + tid] = e / red[0];
}

__global__ __launch_bounds__(256) void absmax_kernel() {
    int bh = blockIdx.x, mode = blockIdx.y, tid = threadIdx.x;
    const float* A = &g_a2[(size_t)bh * MM * MM];
    float s = 0.f;
    if (mode == 0) { for (int j = 0; j < MM; j++) s += fabsf(A[tid * MM + j]); }
    else           { for (int i = 0; i < MM; i++) s += fabsf(A[i * MM + tid]); }
    float m = s;
    #pragma unroll
    for (int o = 16; o; o >>= 1) m = fmaxf(m, __shfl_xor_sync(0xffffffffu, m, o));
    __shared__ float red[8];
    int w = tid >> 5, l = tid & 31;
    if (l == 0) red[w] = m;
    __syncthreads();
    if (tid == 0) {
        float t = red[0];
        for (int u = 1; u < 8; u++) t = fmaxf(t, red[u]);
        atomicMax(mode == 0 ? &g_max0 : &g_max1, __float_as_uint(t));
    }
}

__global__ __launch_bounds__(256) void zinit_kernel() {
    int bh = blockIdx.x >> 8, i = blockIdx.x & 255, j = threadIdx.x;
    float inv = 1.f / (__uint_as_float(g_max0) * __uint_as_float(g_max1));
    g_za[((size_t)bh * MM + i) * MM + j] = g_a2[((size_t)bh * MM + j) * MM + i] * inv;
}

__global__ __launch_bounds__(256) void conv_kernel(const float* __restrict__ wres) {
    __shared__ float sv[160 * 64];
    __shared__ float wl[KERN];
    int bh = blockIdx.y, h = bh & 1;
    int n0 = blockIdx.x * 128;
    int tid = threadIdx.x;
    if (tid < KERN) wl[tid] = wres[h * KERN + tid];
    #pragma unroll
    for (int u = 0; u < 10; u++) {
        int e4 = tid + u * 256;
        int li = e4 >> 4, d4 = (e4 & 15) * 4;
        int n = n0 - 16 + li;
        float4 val = make_float4(0.f, 0.f, 0.f, 0.f);
        if (n >= 0 && n < NSEQ) val = *(const float4*)&g_v[((size_t)bh * NSEQ + n) * DH + d4];
        *(float4*)&sv[li * 64 + d4] = val;
    }
    __syncthreads();
    int d = tid & 63, rg = tid >> 6;
    for (int i = 0; i < 32; i++) {
        int rl = rg * 32 + i;
        float s = 0.f;
        #pragma unroll
        for (int t = 0; t < KERN; t++) s += wl[t] * sv[(rl + t) * 64 + d];
        g_out1[((size_t)bh * NSEQ + n0 + rl) * DH + d] += s;
    }
}

// ---------- bf16 packed GEMMs ----------
// qkv: xn(32768x512)@wqkv(512x384). BM=128 BN=128 BK=32, double-buffered, bf16 packed.
__global__ __launch_bounds__(256) void qkv_mma(const float* __restrict__ wqkv) {
    __shared__ u32 SA[2][128*20];   // [m][k/2], stride 20
    __shared__ u32 SB[2][16*132];   // [k/2][n], stride 132
    int tid = threadIdx.x;
    int row0 = blockIdx.x * 128, col0 = blockIdx.y * 128;
    int lane = tid & 31, wid = tid >> 5;
    int g = lane >> 2, t = lane & 3;
    int wm = (wid & 1) * 64, wn = (wid >> 1) * 32;
    float acc[4][4][4];
    #pragma unroll
    for (int i = 0; i < 4; i++) for (int j = 0; j < 4; j++) for (int u = 0; u < 4; u++) acc[i][j][u] = 0.f;
    float4 a1[2], a2[2], b1[2], b2[2];
    auto LOAD = [&](int kt) {
        #pragma unroll
        for (int p = 0; p < 2; p++) {
            int idx = tid + p * 256; int m = idx >> 2, kg = idx & 3;
            const float* src = &g_xn[(size_t)(row0 + m) * DD + kt + kg * 8];
            a1[p] = *(const float4*)src;
            a2[p] = *(const float4*)(src + 4);
        }
        #pragma unroll
        for (int p = 0; p < 2; p++) {
            int idx = tid + p * 256; int kp = idx >> 5, n4 = (idx & 31) * 4;
            int k = kt + kp * 2;
            b1[p] = *(const float4*)&wqkv[(size_t)k * 384 + col0 + n4];
            b2[p] = *(const float4*)&wqkv[(size_t)(k + 1) * 384 + col0 + n4];
        }
    };
    auto STS = [&](int buf) {
        #pragma unroll
        for (int p = 0; p < 2; p++) {
            int idx = tid + p * 256; int m = idx >> 2, kg = idx & 3;
            *(uint4*)&SA[buf][m * 20 + kg * 4] = pkA(a1[p], a2[p]);
        }
        #pragma unroll
        for (int p = 0; p < 2; p++) {
            int idx = tid + p * 256; int kp = idx >> 5, n4 = (idx & 31) * 4;
            *(uint4*)&SB[buf][kp * 132 + n4] = pkB(b1[p], b2[p]);
        }
    };
    auto COMP = [&](int buf) {
        #pragma unroll
        for (int s = 0; s < 2; s++) {
            int kp = 8 * s + t;
            u32 af[4][4], bf[4][2];
            #pragma unroll
            for (int i = 0; i < 4; i++) {
                int r = wm + 16 * i + g;
                af[i][0] = SA[buf][r * 20 + kp];
                af[i][1] = SA[buf][(r + 8) * 20 + kp];
                af[i][2] = SA[buf][r * 20 + kp + 4];
                af[i][3] = SA[buf][(r + 8) * 20 + kp + 4];
            }
            #pragma unroll
            for (int j = 0; j < 4; j++) {
                int n = wn + 8 * j + g;
                bf[j][0] = SB[buf][kp * 132 + n];
                bf[j][1] = SB[buf][(kp + 4) * 132 + n];
            }
            #pragma unroll
            for (int i = 0; i < 4; i++)
                #pragma unroll
                for (int j = 0; j < 4; j++) mmab(acc[i][j], af[i], bf[j]);
        }
    };
    LOAD(0); STS(0); __syncthreads();
    for (int it = 0; it < 16; it++) {
        if (it + 1 < 16) LOAD((it + 1) * 32);
        COMP(it & 1);
        if (it + 1 < 16) { STS((it + 1) & 1); __syncthreads(); }
    }
    auto STORE = [&](int tok, int c, float v) {
        int bb = tok >> 13, n = tok & 8191;
        int which = c >> 7, hd = c & 127, h = hd >> 6, d = hd & 63;
        size_t dst = (((size_t)(bb * HH + h)) * NSEQ + n) * DH + d;
        if (which == 0)      g_q[dst] = v * 0.125f;
        else if (which == 1) g_k[dst] = v;
        else                 g_v[dst] = v;
    };
    #pragma unroll
    for (int i = 0; i < 4; i++) {
        int row = row0 + wm + 16 * i + g;
        #pragma unroll
        for (int j = 0; j < 4; j++) {
            int col = col0 + wn + 8 * j + 2 * t;
            STORE(row, col, acc[i][j][0]);
            STORE(row, col + 1, acc[i][j][1]);
            STORE(row + 8, col, acc[i][j][2]);
            STORE(row + 8, col + 1, acc[i][j][3]);
        }
    }
}

// outgemm: gather(out1)(32768x128)@wout(128x512) + bias + x, bf16 packed.
__global__ __launch_bounds__(256) void outgemm_mma(const float* __restrict__ x,
                                                   const float* __restrict__ wout,
                                                   const float* __restrict__ bout,
                                                   float* __restrict__ out) {
    __shared__ u32 SA[2][128*20];
    __shared__ u32 SB[2][16*132];
    int tid = threadIdx.x;
    int row0 = blockIdx.x * 128, col0 = blockIdx.y * 128;
    int lane = tid & 31, wid = tid >> 5;
    int g = lane >> 2, t = lane & 3;
    int wm = (wid & 1) * 64, wn = (wid >> 1) * 32;
    float acc[4][4][4];
    #pragma unroll
    for (int i = 0; i < 4; i++) for (int j = 0; j < 4; j++) for (int u = 0; u < 4; u++) acc[i][j][u] = 0.f;
    float4 a1[2], a2[2], b1[2], b2[2];
    auto LOAD = [&](int kt) {
        #pragma unroll
        for (int p = 0; p < 2; p++) {
            int idx = tid + p * 256; int m = idx >> 2, kg = idx & 3;
            int tok = row0 + m; int bb = tok >> 13, n = tok & 8191;
            int k = kt + kg * 8; int h = k >> 6, d = k & 63;
            const float* src = &g_out1[(((size_t)(bb * HH + h)) * NSEQ + n) * DH + d];
            a1[p] = *(const float4*)src;
            a2[p] = *(const float4*)(src + 4);
        }
        #pragma unroll
        for (int p = 0; p < 2; p++) {
            int idx = tid + p * 256; int kp = idx >> 5, n4 = (idx & 31) * 4;
            int k = kt + kp * 2;
            b1[p] = *(const float4*)&wout[(size_t)k * DD + col0 + n4];
            b2[p] = *(const float4*)&wout[(size_t)(k + 1) * DD + col0 + n4];
        }
    };
    auto STS = [&](int buf) {
        #pragma unroll
        for (int p = 0; p < 2; p++) {
            int idx = tid + p * 256; int m = idx >> 2, kg = idx & 3;
            *(uint4*)&SA[buf][m * 20 + kg * 4] = pkA(a1[p], a2[p]);
        }
        #pragma unroll
        for (int p = 0; p < 2; p++) {
            int idx = tid + p * 256; int kp = idx >> 5, n4 = (idx & 31) * 4;
            *(uint4*)&SB[buf][kp * 132 + n4] = pkB(b1[p], b2[p]);
        }
    };
    auto COMP = [&](int buf) {
        #pragma unroll
        for (int s = 0; s < 2; s++) {
            int kp = 8 * s + t;
            u32 af[4][4], bf[4][2];
            #pragma unroll
            for (int i = 0; i < 4; i++) {
                int r = wm + 16 * i + g;
                af[i][0] = SA[buf][r * 20 + kp];
                af[i][1] = SA[buf][(r + 8) * 20 + kp];
                af[i][2] = SA[buf][r * 20 + kp + 4];
                af[i][3] = SA[buf][(r + 8) * 20 + kp + 4];
            }
            #pragma unroll
            for (int j = 0; j < 4; j++) {
                int n = wn + 8 * j + g;
                bf[j][0] = SB[buf][kp * 132 + n];
                bf[j][1] = SB[buf][(kp + 4) * 132 + n];
            }
            #pragma unroll
            for (int i = 0; i < 4; i++)
                #pragma unroll
                for (int j = 0; j < 4; j++) mmab(acc[i][j], af[i], bf[j]);
        }
    };
    LOAD(0); STS(0); __syncthreads();
    for (int it = 0; it < 4; it++) {
        if (it + 1 < 4) LOAD((it + 1) * 32);
        COMP(it & 1);
        if (it + 1 < 4) { STS((it + 1) & 1); __syncthreads(); }
    }
    #pragma unroll
    for (int i = 0; i < 4; i++) {
        int row = row0 + wm + 16 * i + g;
        #pragma unroll
        for (int j = 0; j < 4; j++) {
            int col = col0 + wn + 8 * j + 2 * t;
            out[(size_t)row*DD + col]       = acc[i][j][0] + bout[col]   + x[(size_t)row*DD + col];
            out[(size_t)row*DD + col+1]     = acc[i][j][1] + bout[col+1] + x[(size_t)row*DD + col+1];
            out[(size_t)(row+8)*DD + col]   = acc[i][j][2] + bout[col]   + x[(size_t)(row+8)*DD + col];
            out[(size_t)(row+8)*DD + col+1] = acc[i][j][3] + bout[col+1] + x[(size_t)(row+8)*DD + col+1];
        }
    }
}

// pinv bmm: 256x256x256, C = alpha*(A@B) + beta*A + gamma*I. bf16 packed, 256 thr, double-buffered.
__global__ __launch_bounds__(256) void bmm_mma(const float* __restrict__ A,
                                               const float* __restrict__ Bm,
                                               float* __restrict__ C,
                                               float alpha, float beta, float gam) {
    __shared__ u32 SA[2][64*20];
    __shared__ u32 SB[2][16*68];
    int bh = blockIdx.z;
    size_t base = (size_t)bh * MM * MM;
    int i0 = blockIdx.x * 64, j0 = blockIdx.y * 64;
    int tid = threadIdx.x;
    int lane = tid & 31, wid = tid >> 5;
    int g = lane >> 2, t = lane & 3;
    int wm = (wid & 3) * 16, wn = (wid >> 2) * 32;
    float acc[4][4];
    #pragma unroll
    for (int j = 0; j < 4; j++) for (int u = 0; u < 4; u++) acc[j][u] = 0.f;
    int am = tid >> 2, akg = tid & 3;
    int bkp = tid >> 4, bn4 = (tid & 15) * 4;
    float4 a1, a2, b1, b2;
    auto LOAD = [&](int kt) {
        const float* src = &A[base + (size_t)(i0 + am) * MM + kt + akg * 8];
        a1 = *(const float4*)src;
        a2 = *(const float4*)(src + 4);
        int k = kt + bkp * 2;
        b1 = *(const float4*)&Bm[base + (size_t)k * MM + j0 + bn4];
        b2 = *(const float4*)&Bm[base + (size_t)(k + 1) * MM + j0 + bn4];
    };
    auto STS = [&](int buf) {
        *(uint4*)&SA[buf][am * 20 + akg * 4] = pkA(a1, a2);
        *(uint4*)&SB[buf][bkp * 68 + bn4] = pkB(b1, b2);
    };
    auto COMP = [&](int buf) {
        #pragma unroll
        for (int s = 0; s < 2; s++) {
            int kp = 8 * s + t;
            u32 af[4], bf[4][2];
            int r = wm + g;
            af[0] = SA[buf][r * 20 + kp];
            af[1] = SA[buf][(r + 8) * 20 + kp];
            af[2] = SA[buf][r * 20 + kp + 4];
            af[3] = SA[buf][(r + 8) * 20 + kp + 4];
            #pragma unroll
            for (int j = 0; j < 4; j++) {
                int n = wn + 8 * j + g;
                bf[j][0] = SB[buf][kp * 68 + n];
                bf[j][1] = SB[buf][(kp + 4) * 68 + n];
            }
            #pragma unroll
            for (int j = 0; j < 4; j++) mmab(acc[j], af, bf[j]);
        }
    };
    LOAD(0); STS(0); __syncthreads();
    for (int it = 0; it < 8; it++) {
        if (it + 1 < 8) LOAD((it + 1) * 32);
        COMP(it & 1);
        if (it + 1 < 8) { STS((it + 1) & 1); __syncthreads(); }
    }
    #pragma unroll
    for (int j = 0; j < 4; j++) {
        #pragma unroll
        for (int u = 0; u < 4; u++) {
            int row = i0 + wm + g + (u >> 1) * 8;
            int col = j0 + wn + 8 * j + 2 * t + (u & 1);
            float r = alpha * acc[j][u];
            if (beta != 0.f) r += beta * A[base + (size_t)row * MM + col];
            if (row == col) r += gam;
            C[base + (size_t)row * MM + col] = r;
        }
    }
}

// NN, N=64 tf32 (W2 = Z @ a3v only)
__global__ __launch_bounds__(128) void nn64_mma(const float* __restrict__ A,
                                                const float* __restrict__ B,
                                                float* __restrict__ C,
                                                int lda, size_t aBatch, size_t bBatch,
                                                size_t cBatch, int kchunk) {
    __shared__ unsigned As[64*36];
    __shared__ unsigned Bs[32*72];
    int bh = blockIdx.z;
    int m0 = blockIdx.x * 64;
    const float* Ab = A + (size_t)bh * aBatch + (size_t)m0 * lda;
    const float* Bb = B + (size_t)bh * bBatch;
    int tid = threadIdx.x;
    int lane = tid & 31, wid = tid >> 5;
    int g = lane >> 2, t = lane & 3;
    int wm = (wid & 1) * 32, wn = (wid >> 1) * 32;
    float acc[2][4][4];
    #pragma unroll
    for (int i = 0; i < 2; i++) for (int j = 0; j < 4; j++) for (int u = 0; u < 4; u++) acc[i][j][u] = 0.f;
    int iters = kchunk / 32;
    for (int it = 0; it < iters; it++) {
        #pragma unroll
        for (int p = 0; p < 4; p++) {
            int idx = tid + p * 128; int m = idx >> 3, c = (idx & 7) * 4;
            float4 v = *(const float4*)&Ab[(size_t)m * lda + it*32 + c];
            *(uint4*)&As[m*36+c] = make_uint4(f2tf(v.x), f2tf(v.y), f2tf(v.z), f2tf(v.w));
        }
        #pragma unroll
        for (int p = 0; p < 4; p++) {
            int idx = tid + p * 128; int k = idx >> 4, c = (idx & 15) * 4;
            float4 v = *(const float4*)&Bb[(size_t)(it*32 + k) * 64 + c];
            *(uint4*)&Bs[k*72+c] = make_uint4(f2tf(v.x), f2tf(v.y), f2tf(v.z), f2tf(v.w));
        }
        __syncthreads();
        #pragma unroll
        for (int s = 0; s < 4; s++) {
            unsigned af[2][4], bf[4][2];
            #pragma unroll
            for (int i = 0; i < 2; i++) {
                const unsigned* p = &As[(wm + 16*i + g)*36 + 8*s + t];
                af[i][0] = p[0]; af[i][1] = p[288]; af[i][2] = p[4]; af[i][3] = p[292];
            }
            #pragma unroll
            for (int j = 0; j < 4; j++) {
                const unsigned* p = &Bs[(8*s + t)*72 + wn + 8*j + g];
                bf[j][0] = p[0]; bf[j][1] = p[288];
            }
            #pragma unroll
            for (int i = 0; i < 2; i++)
                #pragma unroll
                for (int j = 0; j < 4; j++) mma8(acc[i][j], af[i], bf[j]);
        }
        __syncthreads();
    }
    float* Cb = C + (size_t)bh * cBatch + (size_t)m0 * 64;
    #pragma unroll
    for (int i = 0; i < 2; i++) {
        int row = wm + 16*i + g;
        #pragma unroll
        for (int j = 0; j < 4; j++) {
            int col = wn + 8*j + 2*t;
            Cb[(size_t)row*64 + col]       = acc[i][j][0];
            Cb[(size_t)row*64 + col+1]     = acc[i][j][1];
            Cb[(size_t)(row+8)*64 + col]   = acc[i][j][2];
            Cb[(size_t)(row+8)*64 + col+1] = acc[i][j][3];
        }
    }
}

// ---------- fused flash kernels (R5-proven, tf32) ----------
__global__ __launch_bounds__(256) void attn3_kernel() {
    extern __shared__ float smf[];
    u32* QS = (u32*)smf;
    u32* KS = QS + 64*68;
    u32* VS = KS + 128*72;
    float* SS = (float*)(VS + 128*72);
    float* sm_m = SS + 64*132;
    float* sm_l = sm_m + 64;
    float* sm_sc = sm_l + 64;
    int tid = threadIdx.x;
    int r0 = blockIdx.x * 64;
    int sp = blockIdx.y;
    int bh = blockIdx.z;
    int lane = tid & 31, wid = tid >> 5;
    int g = lane >> 2, t = lane & 3;
    #pragma unroll
    for (int p = 0; p < 4; p++) {
        int idx = tid + p * 256; int m = idx >> 4, c = (idx & 15) * 4;
        float4 v = *(const float4*)&g_ql[((size_t)bh * MM + r0 + m) * DH + c];
        *(uint4*)&QS[m*68 + c] = make_uint4(f2tf(v.x), f2tf(v.y), f2tf(v.z), f2tf(v.w));
    }
    if (tid < 64) { sm_m[tid] = -1e30f; sm_l[tid] = 0.f; }
    int m0 = (wid & 3) * 16;
    int n0s = (wid >> 2) * 64;
    int n0o = (wid >> 2) * 32;
    float acco[4][4];
    #pragma unroll
    for (int j = 0; j < 4; j++) for (int u = 0; u < 4; u++) acco[j][u] = 0.f;
    __syncthreads();
    for (int ch = 0; ch < 16; ch++) {
        int k0 = sp * 2048 + ch * 128;
        #pragma unroll
        for (int p = 0; p < 8; p++) {
            int idx = tid + p * 256; int key = idx >> 4, c = (idx & 15) * 4;
            float4 kv = *(const float4*)&g_k[((size_t)bh * NSEQ + k0 + key) * DH + c];
            *(uint4*)&KS[key*72 + c] = make_uint4(f2tf(kv.x), f2tf(kv.y), f2tf(kv.z), f2tf(kv.w));
            float4 vv = *(const float4*)&g_v[((size_t)bh * NSEQ + k0 + key) * DH + c];
            *(uint4*)&VS[key*72 + c] = make_uint4(f2tf(vv.x), f2tf(vv.y), f2tf(vv.z), f2tf(vv.w));
        }
        __syncthreads();
        float accs[8][4];
        #pragma unroll
        for (int j = 0; j < 8; j++) for (int u = 0; u < 4; u++) accs[j][u] = 0.f;
        #pragma unroll
        for (int s = 0; s < 8; s++) {
            int ks = 8*s + t;
            u32 af[4];
            af[0] = QS[(m0+g)*68 + ks];   af[1] = QS[(m0+g+8)*68 + ks];
            af[2] = QS[(m0+g)*68 + ks+4]; af[3] = QS[(m0+g+8)*68 + ks+4];
            #pragma unroll
            for (int j = 0; j < 8; j++) {
                int n = n0s + 8*j + g;
                u32 bf2[2];
                bf2[0] = KS[n*72 + ks]; bf2[1] = KS[n*72 + ks + 4];
                mma8(accs[j], af, bf2);
            }
        }
        #pragma unroll
        for (int j = 0; j < 8; j++) {
            int col = n0s + 8*j + 2*t;
            *(float2*)&SS[(m0+g)*132 + col]   = make_float2(accs[j][0], accs[j][1]);
            *(float2*)&SS[(m0+g+8)*132 + col] = make_float2(accs[j][2], accs[j][3]);
        }
        __syncthreads();
        {
            int row = tid >> 2, t2 = tid & 3;
            float* Sr = &SS[row*132 + t2*32];
            float cmax = -1e30f;
            #pragma unroll
            for (int c = 0; c < 32; c++) cmax = fmaxf(cmax, Sr[c]);
            cmax = fmaxf(cmax, __shfl_xor_sync(0xffffffffu, cmax, 1));
            cmax = fmaxf(cmax, __shfl_xor_sync(0xffffffffu, cmax, 2));
            float mold = sm_m[row];
            float mnew = fmaxf(mold, cmax);
            float csum = 0.f;
            u32* Pr = (u32*)Sr;
            #pragma unroll
            for (int c = 0; c < 32; c++) {
                float pv = __expf(Sr[c] - mnew);
                csum += pv;
                Pr[c] = f2tf(pv);
            }
            csum += __shfl_xor_sync(0xffffffffu, csum, 1);
            csum += __shfl_xor_sync(0xffffffffu, csum, 2);
            if (t2 == 0) {
                float scv = __expf(mold - mnew);
                sm_sc[row] = scv;
                sm_l[row] = sm_l[row] * scv + csum;
                sm_m[row] = mnew;
            }
        }
        __syncthreads();
        {
            float s0 = sm_sc[m0 + g], s1 = sm_sc[m0 + g + 8];
            #pragma unroll
            for (int j = 0; j < 4; j++) {
                acco[j][0] *= s0; acco[j][1] *= s0;
                acco[j][2] *= s1; acco[j][3] *= s1;
            }
            const u32* PS = (const u32*)SS;
            #pragma unroll
            for (int s = 0; s < 16; s++) {
                int ks = 8*s + t;
                u32 af[4];
                af[0] = PS[(m0+g)*132 + ks];   af[1] = PS[(m0+g+8)*132 + ks];
                af[2] = PS[(m0+g)*132 + ks+4]; af[3] = PS[(m0+g+8)*132 + ks+4];
                #pragma unroll
                for (int j = 0; j < 4; j++) {
                    int n = n0o + 8*j + g;
                    u32 bf2[2];
                    bf2[0] = VS[ks*72 + n]; bf2[1] = VS[(ks+4)*72 + n];
                    mma8(acco[j], af, bf2);
                }
            }
        }
        __syncthreads();
    }
    size_t pb = ((size_t)(bh*4 + sp) * MM + r0);
    #pragma unroll
    for (int j = 0; j < 4; j++) {
        int col = n0o + 8*j + 2*t;
        *(float2*)&g_part[(pb + m0 + g) * DH + col]     = make_float2(acco[j][0], acco[j][1]);
        *(float2*)&g_part[(pb + m0 + g + 8) * DH + col] = make_float2(acco[j][2], acco[j][3]);
    }
    if (tid < 64) {
        g_m[(bh*4 + sp) * MM + r0 + tid] = sm_m[tid];
        g_l[(bh*4 + sp) * MM + r0 + tid] = sm_l[tid];
    }
}

__global__ void attn_combine() {
    int idx = blockIdx.x * 256 + threadIdx.x;
    int bh = idx >> 14, rem = idx & 16383, row = rem >> 6, d = rem & 63;
    float ms = -1e30f;
    #pragma unroll
    for (int s = 0; s < 4; s++) ms = fmaxf(ms, g_m[(bh*4+s)*MM + row]);
    float num = 0.f, den = 0.f;
    #pragma unroll
    for (int s = 0; s < 4; s++) {
        float e = __expf(g_m[(bh*4+s)*MM + row] - ms);
        num += g_part[((size_t)(bh*4+s)*MM + row)*DH + d] * e;
        den += g_l[(bh*4+s)*MM + row] * e;
    }
    g_a3v[((size_t)bh*MM + row)*DH + d] = num / den;
}

__global__ __launch_bounds__(256) void attn1_kernel() {
    extern __shared__ float smf[];
    u32* QS  = (u32*)smf;
    u32* KLS = QS + 64*68;
    u32* W2S = KLS + 256*72;
    float* sm_l = (float*)(W2S + 256*72);
    float* SS = (float*)KLS;
    int tid = threadIdx.x;
    int r0 = blockIdx.x * 64;
    int bh = blockIdx.y;
    int lane = tid & 31, wid = tid >> 5;
    int g = lane >> 2, t = lane & 3;
    #pragma unroll
    for (int p = 0; p < 4; p++) {
        int idx = tid + p * 256; int m = idx >> 4, c = (idx & 15) * 4;
        float4 v = *(const float4*)&g_q[((size_t)bh * NSEQ + r0 + m) * DH + c];
        *(uint4*)&QS[m*68 + c] = make_uint4(f2tf(v.x), f2tf(v.y), f2tf(v.z), f2tf(v.w));
    }
    #pragma unroll
    for (int p = 0; p < 16; p++) {
        int idx = tid + p * 256; int m = idx >> 4, c = (idx & 15) * 4;
        float4 v = *(const float4*)&g_kl[((size_t)bh * MM + m) * DH + c];
        *(uint4*)&KLS[m*72 + c] = make_uint4(f2tf(v.x), f2tf(v.y), f2tf(v.z), f2tf(v.w));
        float4 w = *(const float4*)&g_w2[((size_t)bh * MM + m) * DH + c];
        *(uint4*)&W2S[m*72 + c] = make_uint4(f2tf(w.x), f2tf(w.y), f2tf(w.z), f2tf(w.w));
    }
    __syncthreads();
    int m0 = (wid & 3) * 16;
    int n0s = (wid >> 2) * 128;
    float accs[16][4];
    #pragma unroll
    for (int j = 0; j < 16; j++) for (int u = 0; u < 4; u++) accs[j][u] = 0.f;
    #pragma unroll
    for (int s = 0; s < 8; s++) {
        int ks = 8*s + t;
        u32 af[4];
        af[0] = QS[(m0+g)*68 + ks];   af[1] = QS[(m0+g+8)*68 + ks];
        af[2] = QS[(m0+g)*68 + ks+4]; af[3] = QS[(m0+g+8)*68 + ks+4];
        #pragma unroll
        for (int j = 0; j < 16; j++) {
            int n = n0s + 8*j + g;
            u32 bf2[2];
            bf2[0] = KLS[n*72 + ks]; bf2[1] = KLS[n*72 + ks + 4];
            mma8(accs[j], af, bf2);
        }
    }
    __syncthreads();
    #pragma unroll
    for (int j = 0; j < 16; j++) {
        int col = n0s + 8*j + 2*t;
        *(float2*)&SS[(m0+g)*264 + col]   = make_float2(accs[j][0], accs[j][1]);
        *(float2*)&SS[(m0+g+8)*264 + col] = make_float2(accs[j][2], accs[j][3]);
    }
    __syncthreads();
    {
        int row = tid >> 2, t2 = tid & 3;
        float* Sr = &SS[row*264 + t2*64];
        float cmax = -1e30f;
        #pragma unroll
        for (int c = 0; c < 64; c++) cmax = fmaxf(cmax, Sr[c]);
        cmax = fmaxf(cmax, __shfl_xor_sync(0xffffffffu, cmax, 1));
        cmax = fmaxf(cmax, __shfl_xor_sync(0xffffffffu, cmax, 2));
        float csum = 0.f;
        u32* Pr = (u32*)Sr;
        #pragma unroll
        for (int c = 0; c < 64; c++) {
            float pv = __expf(Sr[c] - cmax);
            csum += pv;
            Pr[c] = f2tf(pv);
        }
        csum += __shfl_xor_sync(0xffffffffu, csum, 1);
        csum += __shfl_xor_sync(0xffffffffu, csum, 2);
        if (t2 == 0) sm_l[row] = csum;
    }
    __syncthreads();
    int n0o = (wid >> 2) * 32;
    float acco[4][4];
    #pragma unroll
    for (int j = 0; j < 4; j++) for (int u = 0; u < 4; u++) acco[j][u] = 0.f;
    const u32* PS = (const u32*)SS;
    #pragma unroll
    for (int s = 0; s < 32; s++) {
        int ks = 8*s + t;
        u32 af[4];
        af[0] = PS[(m0+g)*264 + ks];   af[1] = PS[(m0+g+8)*264 + ks];
        af[2] = PS[(m0+g)*264 + ks+4]; af[3] = PS[(m0+g+8)*264 + ks+4];
        #pragma unroll
        for (int j = 0; j < 4; j++) {
            int n = n0o + 8*j + g;
            u32 bf2[2];
            bf2[0] = W2S[ks*72 + n]; bf2[1] = W2S[(ks+4)*72 + n];
            mma8(acco[j], af, bf2);
        }
    }
    float il0 = 1.f / sm_l[m0 + g], il1 = 1.f / sm_l[m0 + g + 8];
    size_t ob = (size_t)bh * NSEQ + r0;
    #pragma unroll
    for (int j = 0; j < 4; j++) {
        int col = n0o + 8*j + 2*t;
        *(float2*)&g_out1[(ob + m0 + g) * DH + col]     = make_float2(acco[j][0]*il0, acco[j][1]*il0);
        *(float2*)&g_out1[(ob + m0 + g + 8) * DH + col] = make_float2(acco[j][2]*il1, acco[j][3]*il1);
    }
}

// ---------------- launch ----------------
extern "C" void kernel_launch(void* const* d_in, const int* in_sizes, int n_in,
                              void* d_out, int out_size) {
    const float* x     = (const float*)d_in[0];
    const float* gamma = (const float*)d_in[1];
    const float* beta  = (const float*)d_in[2];
    const float* wqkv  = (const float*)d_in[3];
    const float* wout  = (const float*)d_in[4];
    const float* bout  = (const float*)d_in[5];
    const float* wres  = (const float*)d_in[6];
    float* out = (float*)d_out;

    float *pA2, *pXZ, *pT1, *pT2, *pZA, *pZB, *pA3V, *pW2;
    cudaGetSymbolAddress((void**)&pA2, g_a2);
    cudaGetSymbolAddress((void**)&pXZ, g_xz);
    cudaGetSymbolAddress((void**)&pT1, g_t1);
    cudaGetSymbolAddress((void**)&pT2, g_t2);
    cudaGetSymbolAddress((void**)&pZA, g_za);
    cudaGetSymbolAddress((void**)&pZB, g_zb);
    cudaGetSymbolAddress((void**)&pA3V, g_a3v);
    cudaGetSymbolAddress((void**)&pW2, g_w2);

    cudaFuncSetAttribute(attn3_kernel, cudaFuncAttributeMaxDynamicSharedMemorySize, 125696);
    cudaFuncSetAttribute(attn1_kernel, cudaFuncAttributeMaxDynamicSharedMemorySize, 165120);

    init_kernel<<<1, 1>>>();
    ln_kernel<<<TOK, 128>>>(x, gamma, beta);
    qkv_mma<<<dim3(TOK / 128, 3), 256>>>(wqkv);
    landmark_kernel<<<dim3(BH, MM), 64>>>();
    sim2_kernel<<<BH * MM, 256>>>();
    absmax_kernel<<<dim3(BH, 2), 256>>>();
    zinit_kernel<<<BH * MM, 256>>>();

    float* zc = pZA;
    float* zn = pZB;
    for (int it = 0; it < 6; it++) {
        bmm_mma<<<dim3(4, 4, BH), 256>>>(pA2, zc, pXZ, 1.f, 0.f, 0.f);
        bmm_mma<<<dim3(4, 4, BH), 256>>>(pXZ, pXZ, pT1, 1.f, -7.f, 15.f);
        bmm_mma<<<dim3(4, 4, BH), 256>>>(pXZ, pT1, pT2, -1.f, 0.f, 13.f);
        bmm_mma<<<dim3(4, 4, BH), 256>>>(zc, pT2, zn, 0.25f, 0.f, 0.f);
        float* t = zc; zc = zn; zn = t;
    }

    attn3_kernel<<<dim3(4, 4, BH), 256, 125696>>>();
    attn_combine<<<512, 256>>>();
    nn64_mma<<<dim3(4, 1, BH), 128>>>(zc, pA3V, pW2, MM,
        (size_t)MM * MM, (size_t)MM * 64, (size_t)MM * 64, MM);
    attn1_kernel<<<dim3(NSEQ / 64, BH), 256, 165120>>>();
    conv_kernel<<<dim3(NSEQ / 128, BH), 256>>>(wres);
    outgemm_mma<<<dim3(TOK / 128, 4), 256>>>(x, wout, bout, out);
}

// round 7
// speedup vs baseline: 1.4803x; 1.0185x over previous
#include <cuda_runtime.h>
#include <math.h>

#define BB 4
#define NSEQ 8192
#define DD 512
#define HH 2
#define DH 64
#define INNER 128
#define MM 256
#define LLM 32
#define BH (BB*HH)
#define TOK (BB*NSEQ)
#define KERN 33

typedef unsigned u32;

__device__ u32   g_xnh[(size_t)TOK*256];        // layernormed x, bf16x2 packed [tok][k/2]
__device__ u32   g_wqkvh[256*384];              // w_qkv bf16x2 packed [k/2][n]
__device__ u32   g_wouth[64*512];               // w_out bf16x2 packed [k/2][n]
__device__ float g_q[(size_t)BH*NSEQ*DH];
__device__ float g_k[(size_t)BH*NSEQ*DH];
__device__ float g_v[(size_t)BH*NSEQ*DH];
__device__ float g_ql[BH*MM*DH];
__device__ float g_kl[BH*MM*DH];
__device__ float g_a2[BH*MM*MM];
__device__ float g_xz[BH*MM*MM];
__device__ float g_t1[BH*MM*MM];
__device__ float g_t2[BH*MM*MM];
__device__ float g_za[BH*MM*MM];
__device__ float g_zb[BH*MM*MM];
__device__ float g_a3v[BH*MM*DH];
__device__ float g_w2[BH*MM*DH];
__device__ u32   g_out1h[(size_t)BH*NSEQ*32];   // out1 bf16x2 packed [bh][n][d/2]
__device__ float g_part[BH*8*MM*DH];
__device__ float g_m[BH*4*MM];
__device__ float g_l[BH*4*MM];
__device__ unsigned g_max0, g_max1;

// ---- tf32 helpers (attn kernels) ----
__device__ __forceinline__ unsigned f2tf(float f) {
    unsigned r; asm("cvt.rna.tf32.f32 %0, %1;" : "=r"(r) : "f"(f)); return r;
}
__device__ __forceinline__ void mma8(float* c, const unsigned* a, const unsigned* b) {
    asm volatile("mma.sync.aligned.m16n8k8.row.col.f32.tf32.tf32.f32 "
        "{%0,%1,%2,%3}, {%4,%5,%6,%7}, {%8,%9}, {%0,%1,%2,%3};"
        : "+f"(c[0]), "+f"(c[1]), "+f"(c[2]), "+f"(c[3])
        : "r"(a[0]), "r"(a[1]), "r"(a[2]), "r"(a[3]), "r"(b[0]), "r"(b[1]));
}
// ---- bf16 helpers ----
__device__ __forceinline__ u32 pk2(float lo, float hi) {
    u32 r; asm("cvt.rn.bf16x2.f32 %0, %2, %1;" : "=r"(r) : "f"(lo), "f"(hi)); return r;
}
__device__ __forceinline__ void mmab(float* c, const u32* a, const u32* b) {
    asm volatile("mma.sync.aligned.m16n8k16.row.col.f32.bf16.bf16.f32 "
        "{%0,%1,%2,%3}, {%4,%5,%6,%7}, {%8,%9}, {%0,%1,%2,%3};"
        : "+f"(c[0]), "+f"(c[1]), "+f"(c[2]), "+f"(c[3])
        : "r"(a[0]), "r"(a[1]), "r"(a[2]), "r"(a[3]), "r"(b[0]), "r"(b[1]));
}
__device__ __forceinline__ uint4 pkA(float4 v1, float4 v2) {
    return make_uint4(pk2(v1.x,v1.y), pk2(v1.z,v1.w), pk2(v2.x,v2.y), pk2(v2.z,v2.w));
}
__device__ __forceinline__ uint4 pkB(float4 r1, float4 r2) {
    return make_uint4(pk2(r1.x,r2.x), pk2(r1.y,r2.y), pk2(r1.z,r2.z), pk2(r1.w,r2.w));
}

__global__ void init_kernel() { g_max0 = 0u; g_max1 = 0u; }

// prepack w_qkv and w_out into bf16x2 [k/2][n]
__global__ void prepack_kernel(const float* __restrict__ wqkv, const float* __restrict__ wout) {
    int idx = blockIdx.x * 256 + threadIdx.x;
    if (idx < 256 * 384) {
        int kp = idx / 384, n = idx % 384;
        g_wqkvh[idx] = pk2(wqkv[(size_t)(2*kp) * 384 + n], wqkv[(size_t)(2*kp+1) * 384 + n]);
    } else {
        int j = idx - 256 * 384;
        int kp = j / 512, n = j % 512;
        g_wouth[j] = pk2(wout[(size_t)(2*kp) * 512 + n], wout[(size_t)(2*kp+1) * 512 + n]);
    }
}

__global__ __launch_bounds__(128) void ln_kernel(const float* __restrict__ x,
                                                 const float* __restrict__ gamma,
                                                 const float* __restrict__ beta) {
    int t = blockIdx.x, tid = threadIdx.x;
    const float4* xr = (const float4*)(x + (size_t)t * DD);
    float4 v = xr[tid];
    float s  = v.x + v.y + v.z + v.w;
    float sq = v.x*v.x + v.y*v.y + v.z*v.z + v.w*v.w;
    __shared__ float sb[8];
    #pragma unroll
    for (int o = 16; o; o >>= 1) {
        s  += __shfl_xor_sync(0xffffffffu, s, o);
        sq += __shfl_xor_sync(0xffffffffu, sq, o);
    }
    int w = tid >> 5, l = tid & 31;
    if (l == 0) { sb[w] = s; sb[4 + w] = sq; }
    __syncthreads();
    if (tid == 0) { sb[0] = sb[0]+sb[1]+sb[2]+sb[3]; sb[4] = sb[4]+sb[5]+sb[6]+sb[7]; }
    __syncthreads();
    float mu  = sb[0] * (1.f / DD);
    float var = sb[4] * (1.f / DD) - mu * mu;
    float rs  = rsqrtf(var + 1e-5f);
    float4 g4 = ((const float4*)gamma)[tid];
    float4 b4 = ((const float4*)beta)[tid];
    float4 o;
    o.x = (v.x - mu) * rs * g4.x + b4.x;
    o.y = (v.y - mu) * rs * g4.y + b4.y;
    o.z = (v.z - mu) * rs * g4.z + b4.z;
    o.w = (v.w - mu) * rs * g4.w + b4.w;
    uint2 pr = make_uint2(pk2(o.x, o.y), pk2(o.z, o.w));
    *(uint2*)&g_xnh[(size_t)t * 256 + tid * 2] = pr;
}

__global__ void landmark_kernel() {
    int bh = blockIdx.x, m = blockIdx.y, d = threadIdx.x;
    size_t base = ((size_t)bh * NSEQ + m * LLM) * DH + d;
    float sq = 0.f, sk = 0.f;
    #pragma unroll 8
    for (int i = 0; i < LLM; i++) { sq += g_q[base + (size_t)i * DH]; sk += g_k[base + (size_t)i * DH]; }
    g_ql[(bh * MM + m) * DH + d] = sq * (1.f / LLM);
    g_kl[(bh * MM + m) * DH + d] = sk * (1.f / LLM);
}

__global__ __launch_bounds__(256) void sim2_kernel() {
    int bh = blockIdx.x >> 8, i = blockIdx.x & 255;
    int tid = threadIdx.x;
    __shared__ float qs[DH];
    __shared__ float red[8];
    if (tid < DH) qs[tid] = g_ql[(bh * MM + i) * DH + tid];
    __syncthreads();
    const float* kr = &g_kl[(bh * MM + tid) * DH];
    float s = 0.f;
    #pragma unroll
    for (int d = 0; d < DH; d += 4) {
        float4 kv = *(const float4*)&kr[d];
        s += qs[d]*kv.x + qs[d+1]*kv.y + qs[d+2]*kv.z + qs[d+3]*kv.w;
    }
    float m = s;
    #pragma unroll
    for (int o = 16; o; o >>= 1) m = fmaxf(m, __shfl_xor_sync(0xffffffffu, m, o));
    int w = tid >> 5, l = tid & 31;
    if (l == 0) red[w] = m;
    __syncthreads();
    if (w == 0) {
        float t = red[l & 7];
        #pragma unroll
        for (int o = 4; o; o >>= 1) t = fmaxf(t, __shfl_xor_sync(0xffffffffu, t, o));
        if (l == 0) red[0] = t;
    }
    __syncthreads();
    m = red[0];
    __syncthreads();
    float e = __expf(s - m);
    float su = e;
    #pragma unroll
    for (int o = 16; o; o >>= 1) su += __shfl_xor_sync(0xffffffffu, su, o);
    if (l == 0) red[w] = su;
    __syncthreads();
    if (w == 0) {
        float t = red[l & 7];
        #pragma unroll
        for (int o = 4; o; o >>= 1) t += __shfl_xor_sync(0xffffffffu, t, o);
        if (l == 0) red[0] = t;
    }
    __syncthreads();
    g_a2[((size_t)bh * MM + i) * MM + tid] = e / red[0];
}

__global__ __launch_bounds__(256) void absmax_kernel() {
    int bh = blockIdx.x, mode = blockIdx.y, tid = threadIdx.x;
    const float* A = &g_a2[(size_t)bh * MM * MM];
    float s = 0.f;
    if (mode == 0) { for (int j = 0; j < MM; j++) s += fabsf(A[tid * MM + j]); }
    else           { for (int i = 0; i < MM; i++) s += fabsf(A[i * MM + tid]); }
    float m = s;
    #pragma unroll
    for (int o = 16; o; o >>= 1) m = fmaxf(m, __shfl_xor_sync(0xffffffffu, m, o));
    __shared__ float red[8];
    int w = tid >> 5, l = tid & 31;
    if (l == 0) red[w] = m;
    __syncthreads();
    if (tid == 0) {
        float t = red[0];
        for (int u = 1; u < 8; u++) t = fmaxf(t, red[u]);
        atomicMax(mode == 0 ? &g_max0 : &g_max1, __float_as_uint(t));
    }
}

__global__ __launch_bounds__(256) void zinit_kernel() {
    int bh = blockIdx.x >> 8, i = blockIdx.x & 255, j = threadIdx.x;
    float inv = 1.f / (__uint_as_float(g_max0) * __uint_as_float(g_max1));
    g_za[((size_t)bh * MM + i) * MM + j] = g_a2[((size_t)bh * MM + j) * MM + i] * inv;
}

// ---------- bf16 packed GEMMs ----------
// qkv: xnh(32768x512 bf16)@wqkvh -> q,k,v. BM=128 BN=128 BK=32, double-buffered, raw copies.
__global__ __launch_bounds__(256) void qkv_mma() {
    __shared__ u32 SA[2][128*20];   // [m][k/2], stride 20
    __shared__ u32 SB[2][16*132];   // [k/2][n], stride 132
    int tid = threadIdx.x;
    int row0 = blockIdx.x * 128, col0 = blockIdx.y * 128;
    int lane = tid & 31, wid = tid >> 5;
    int g = lane >> 2, t = lane & 3;
    int wm = (wid & 1) * 64, wn = (wid >> 1) * 32;
    float acc[4][4][4];
    #pragma unroll
    for (int i = 0; i < 4; i++) for (int j = 0; j < 4; j++) for (int u = 0; u < 4; u++) acc[i][j][u] = 0.f;
    uint4 ua[2], ub[2];
    auto LOAD = [&](int kt) {
        int kp0 = kt >> 1;
        #pragma unroll
        for (int p = 0; p < 2; p++) {
            int idx = tid + p * 256; int m = idx >> 2, kg = idx & 3;
            ua[p] = *(const uint4*)&g_xnh[(size_t)(row0 + m) * 256 + kp0 + kg * 4];
        }
        #pragma unroll
        for (int p = 0; p < 2; p++) {
            int idx = tid + p * 256; int kp = idx >> 5, n4 = (idx & 31) * 4;
            ub[p] = *(const uint4*)&g_wqkvh[(size_t)(kp0 + kp) * 384 + col0 + n4];
        }
    };
    auto STS = [&](int buf) {
        #pragma unroll
        for (int p = 0; p < 2; p++) {
            int idx = tid + p * 256; int m = idx >> 2, kg = idx & 3;
            *(uint4*)&SA[buf][m * 20 + kg * 4] = ua[p];
        }
        #pragma unroll
        for (int p = 0; p < 2; p++) {
            int idx = tid + p * 256; int kp = idx >> 5, n4 = (idx & 31) * 4;
            *(uint4*)&SB[buf][kp * 132 + n4] = ub[p];
        }
    };
    auto COMP = [&](int buf) {
        #pragma unroll
        for (int s = 0; s < 2; s++) {
            int kp = 8 * s + t;
            u32 af[4][4], bf[4][2];
            #pragma unroll
            for (int i = 0; i < 4; i++) {
                int r = wm + 16 * i + g;
                af[i][0] = SA[buf][r * 20 + kp];
                af[i][1] = SA[buf][(r + 8) * 20 + kp];
                af[i][2] = SA[buf][r * 20 + kp + 4];
                af[i][3] = SA[buf][(r + 8) * 20 + kp + 4];
            }
            #pragma unroll
            for (int j = 0; j < 4; j++) {
                int n = wn + 8 * j + g;
                bf[j][0] = SB[buf][kp * 132 + n];
                bf[j][1] = SB[buf][(kp + 4) * 132 + n];
            }
            #pragma unroll
            for (int i = 0; i < 4; i++)
                #pragma unroll
                for (int j = 0; j < 4; j++) mmab(acc[i][j], af[i], bf[j]);
        }
    };
    LOAD(0); STS(0); __syncthreads();
    for (int it = 0; it < 16; it++) {
        if (it + 1 < 16) LOAD((it + 1) * 32);
        COMP(it & 1);
        if (it + 1 < 16) { STS((it + 1) & 1); __syncthreads(); }
    }
    auto STORE = [&](int tok, int c, float v) {
        int bb = tok >> 13, n = tok & 8191;
        int which = c >> 7, hd = c & 127, h = hd >> 6, d = hd & 63;
        size_t dst = (((size_t)(bb * HH + h)) * NSEQ + n) * DH + d;
        if (which == 0)      g_q[dst] = v * 0.125f;
        else if (which == 1) g_k[dst] = v;
        else                 g_v[dst] = v;
    };
    #pragma unroll
    for (int i = 0; i < 4; i++) {
        int row = row0 + wm + 16 * i + g;
        #pragma unroll
        for (int j = 0; j < 4; j++) {
            int col = col0 + wn + 8 * j + 2 * t;
            STORE(row, col, acc[i][j][0]);
            STORE(row, col + 1, acc[i][j][1]);
            STORE(row + 8, col, acc[i][j][2]);
            STORE(row + 8, col + 1, acc[i][j][3]);
        }
    }
}

// outgemm: out1h(32768x128 bf16)@wouth(128x512) + bias + x
__global__ __launch_bounds__(256) void outgemm_mma(const float* __restrict__ x,
                                                   const float* __restrict__ bout,
                                                   float* __restrict__ out) {
    __shared__ u32 SA[2][128*20];
    __shared__ u32 SB[2][16*132];
    int tid = threadIdx.x;
    int row0 = blockIdx.x * 128, col0 = blockIdx.y * 128;
    int lane = tid & 31, wid = tid >> 5;
    int g = lane >> 2, t = lane & 3;
    int wm = (wid & 1) * 64, wn = (wid >> 1) * 32;
    float acc[4][4][4];
    #pragma unroll
    for (int i = 0; i < 4; i++) for (int j = 0; j < 4; j++) for (int u = 0; u < 4; u++) acc[i][j][u] = 0.f;
    uint4 ua[2], ub[2];
    auto LOAD = [&](int kt) {
        int kp0 = kt >> 1;
        #pragma unroll
        for (int p = 0; p < 2; p++) {
            int idx = tid + p * 256; int m = idx >> 2, kg = idx & 3;
            int tok = row0 + m; int bb = tok >> 13, n = tok & 8191;
            int kp = kp0 + kg * 4;
            int h = kp >> 5, dp = kp & 31;
            ua[p] = *(const uint4*)&g_out1h[(((size_t)(bb * HH + h)) * NSEQ + n) * 32 + dp];
        }
        #pragma unroll
        for (int p = 0; p < 2; p++) {
            int idx = tid + p * 256; int kp = idx >> 5, n4 = (idx & 31) * 4;
            ub[p] = *(const uint4*)&g_wouth[(size_t)(kp0 + kp) * 512 + col0 + n4];
        }
    };
    auto STS = [&](int buf) {
        #pragma unroll
        for (int p = 0; p < 2; p++) {
            int idx = tid + p * 256; int m = idx >> 2, kg = idx & 3;
            *(uint4*)&SA[buf][m * 20 + kg * 4] = ua[p];
        }
        #pragma unroll
        for (int p = 0; p < 2; p++) {
            int idx = tid + p * 256; int kp = idx >> 5, n4 = (idx & 31) * 4;
            *(uint4*)&SB[buf][kp * 132 + n4] = ub[p];
        }
    };
    auto COMP = [&](int buf) {
        #pragma unroll
        for (int s = 0; s < 2; s++) {
            int kp = 8 * s + t;
            u32 af[4][4], bf[4][2];
            #pragma unroll
            for (int i = 0; i < 4; i++) {
                int r = wm + 16 * i + g;
                af[i][0] = SA[buf][r * 20 + kp];
                af[i][1] = SA[buf][(r + 8) * 20 + kp];
                af[i][2] = SA[buf][r * 20 + kp + 4];
                af[i][3] = SA[buf][(r + 8) * 20 + kp + 4];
            }
            #pragma unroll
            for (int j = 0; j < 4; j++) {
                int n = wn + 8 * j + g;
                bf[j][0] = SB[buf][kp * 132 + n];
                bf[j][1] = SB[buf][(kp + 4) * 132 + n];
            }
            #pragma unroll
            for (int i = 0; i < 4; i++)
                #pragma unroll
                for (int j = 0; j < 4; j++) mmab(acc[i][j], af[i], bf[j]);
        }
    };
    LOAD(0); STS(0); __syncthreads();
    for (int it = 0; it < 4; it++) {
        if (it + 1 < 4) LOAD((it + 1) * 32);
        COMP(it & 1);
        if (it + 1 < 4) { STS((it + 1) & 1); __syncthreads(); }
    }
    #pragma unroll
    for (int i = 0; i < 4; i++) {
        int row = row0 + wm + 16 * i + g;
        #pragma unroll
        for (int j = 0; j < 4; j++) {
            int col = col0 + wn + 8 * j + 2 * t;
            out[(size_t)row*DD + col]       = acc[i][j][0] + bout[col]   + x[(size_t)row*DD + col];
            out[(size_t)row*DD + col+1]     = acc[i][j][1] + bout[col+1] + x[(size_t)row*DD + col+1];
            out[(size_t)(row+8)*DD + col]   = acc[i][j][2] + bout[col]   + x[(size_t)(row+8)*DD + col];
            out[(size_t)(row+8)*DD + col+1] = acc[i][j][3] + bout[col+1] + x[(size_t)(row+8)*DD + col+1];
        }
    }
}

// pinv bmm: 256x256x256, C = alpha*(A@B) + beta*A + gamma*I. bf16 packed, 256 thr (R6-proven).
__global__ __launch_bounds__(256) void bmm_mma(const float* __restrict__ A,
                                               const float* __restrict__ Bm,
                                               float* __restrict__ C,
                                               float alpha, float beta, float gam) {
    __shared__ u32 SA[2][64*20];
    __shared__ u32 SB[2][16*68];
    int bh = blockIdx.z;
    size_t base = (size_t)bh * MM * MM;
    int i0 = blockIdx.x * 64, j0 = blockIdx.y * 64;
    int tid = threadIdx.x;
    int lane = tid & 31, wid = tid >> 5;
    int g = lane >> 2, t = lane & 3;
    int wm = (wid & 3) * 16, wn = (wid >> 2) * 32;
    float acc[4][4];
    #pragma unroll
    for (int j = 0; j < 4; j++) for (int u = 0; u < 4; u++) acc[j][u] = 0.f;
    int am = tid >> 2, akg = tid & 3;
    int bkp = tid >> 4, bn4 = (tid & 15) * 4;
    float4 a1, a2, b1, b2;
    auto LOAD = [&](int kt) {
        const float* src = &A[base + (size_t)(i0 + am) * MM + kt + akg * 8];
        a1 = *(const float4*)src;
        a2 = *(const float4*)(src + 4);
        int k = kt + bkp * 2;
        b1 = *(const float4*)&Bm[base + (size_t)k * MM + j0 + bn4];
        b2 = *(const float4*)&Bm[base + (size_t)(k + 1) * MM + j0 + bn4];
    };
    auto STS = [&](int buf) {
        *(uint4*)&SA[buf][am * 20 + akg * 4] = pkA(a1, a2);
        *(uint4*)&SB[buf][bkp * 68 + bn4] = pkB(b1, b2);
    };
    auto COMP = [&](int buf) {
        #pragma unroll
        for (int s = 0; s < 2; s++) {
            int kp = 8 * s + t;
            u32 af[4], bf[4][2];
            int r = wm + g;
            af[0] = SA[buf][r * 20 + kp];
            af[1] = SA[buf][(r + 8) * 20 + kp];
            af[2] = SA[buf][r * 20 + kp + 4];
            af[3] = SA[buf][(r + 8) * 20 + kp + 4];
            #pragma unroll
            for (int j = 0; j < 4; j++) {
                int n = wn + 8 * j + g;
                bf[j][0] = SB[buf][kp * 68 + n];
                bf[j][1] = SB[buf][(kp + 4) * 68 + n];
            }
            #pragma unroll
            for (int j = 0; j < 4; j++) mmab(acc[j], af, bf[j]);
        }
    };
    LOAD(0); STS(0); __syncthreads();
    for (int it = 0; it < 8; it++) {
        if (it + 1 < 8) LOAD((it + 1) * 32);
        COMP(it & 1);
        if (it + 1 < 8) { STS((it + 1) & 1); __syncthreads(); }
    }
    #pragma unroll
    for (int j = 0; j < 4; j++) {
        #pragma unroll
        for (int u = 0; u < 4; u++) {
            int row = i0 + wm + g + (u >> 1) * 8;
            int col = j0 + wn + 8 * j + 2 * t + (u & 1);
            float r = alpha * acc[j][u];
            if (beta != 0.f) r += beta * A[base + (size_t)row * MM + col];
            if (row == col) r += gam;
            C[base + (size_t)row * MM + col] = r;
        }
    }
}

// NN, N=64 tf32 (W2 = Z @ a3v only)
__global__ __launch_bounds__(128) void nn64_mma(const float* __restrict__ A,
                                                const float* __restrict__ B,
                                                float* __restrict__ C,
                                                int lda, size_t aBatch, size_t bBatch,
                                                size_t cBatch, int kchunk) {
    __shared__ unsigned As[64*36];
    __shared__ unsigned Bs[32*72];
    int bh = blockIdx.z;
    int m0 = blockIdx.x * 64;
    const float* Ab = A + (size_t)bh * aBatch + (size_t)m0 * lda;
    const float* Bb = B + (size_t)bh * bBatch;
    int tid = threadIdx.x;
    int lane = tid & 31, wid = tid >> 5;
    int g = lane >> 2, t = lane & 3;
    int wm = (wid & 1) * 32, wn = (wid >> 1) * 32;
    float acc[2][4][4];
    #pragma unroll
    for (int i = 0; i < 2; i++) for (int j = 0; j < 4; j++) for (int u = 0; u < 4; u++) acc[i][j][u] = 0.f;
    int iters = kchunk / 32;
    for (int it = 0; it < iters; it++) {
        #pragma unroll
        for (int p = 0; p < 4; p++) {
            int idx = tid + p * 128; int m = idx >> 3, c = (idx & 7) * 4;
            float4 v = *(const float4*)&Ab[(size_t)m * lda + it*32 + c];
            *(uint4*)&As[m*36+c] = make_uint4(f2tf(v.x), f2tf(v.y), f2tf(v.z), f2tf(v.w));
        }
        #pragma unroll
        for (int p = 0; p < 4; p++) {
            int idx = tid + p * 128; int k = idx >> 4, c = (idx & 15) * 4;
            float4 v = *(const float4*)&Bb[(size_t)(it*32 + k) * 64 + c];
            *(uint4*)&Bs[k*72+c] = make_uint4(f2tf(v.x), f2tf(v.y), f2tf(v.z), f2tf(v.w));
        }
        __syncthreads();
        #pragma unroll
        for (int s = 0; s < 4; s++) {
            unsigned af[2][4], bf[4][2];
            #pragma unroll
            for (int i = 0; i < 2; i++) {
                const unsigned* p = &As[(wm + 16*i + g)*36 + 8*s + t];
                af[i][0] = p[0]; af[i][1] = p[288]; af[i][2] = p[4]; af[i][3] = p[292];
            }
            #pragma unroll
            for (int j = 0; j < 4; j++) {
                const unsigned* p = &Bs[(8*s + t)*72 + wn + 8*j + g];
                bf[j][0] = p[0]; bf[j][1] = p[288];
            }
            #pragma unroll
            for (int i = 0; i < 2; i++)
                #pragma unroll
                for (int j = 0; j < 4; j++) mma8(acc[i][j], af[i], bf[j]);
        }
        __syncthreads();
    }
    float* Cb = C + (size_t)bh * cBatch + (size_t)m0 * 64;
    #pragma unroll
    for (int i = 0; i < 2; i++) {
        int row = wm + 16*i + g;
        #pragma unroll
        for (int j = 0; j < 4; j++) {
            int col = wn + 8*j + 2*t;
            Cb[(size_t)row*64 + col]       = acc[i][j][0];
            Cb[(size_t)row*64 + col+1]     = acc[i][j][1];
            Cb[(size_t)(row+8)*64 + col]   = acc[i][j][2];
            Cb[(size_t)(row+8)*64 + col+1] = acc[i][j][3];
        }
    }
}

// ---------- fused flash kernels ----------
__global__ __launch_bounds__(256) void attn3_kernel() {
    extern __shared__ float smf[];
    u32* QS = (u32*)smf;
    u32* KS = QS + 64*68;
    u32* VS = KS + 128*72;
    float* SS = (float*)(VS + 128*72);
    float* sm_m = SS + 64*132;
    float* sm_l = sm_m + 64;
    float* sm_sc = sm_l + 64;
    int tid = threadIdx.x;
    int r0 = blockIdx.x * 64;
    int sp = blockIdx.y;
    int bh = blockIdx.z;
    int lane = tid & 31, wid = tid >> 5;
    int g = lane >> 2, t = lane & 3;
    #pragma unroll
    for (int p = 0; p < 4; p++) {
        int idx = tid + p * 256; int m = idx >> 4, c = (idx & 15) * 4;
        float4 v = *(const float4*)&g_ql[((size_t)bh * MM + r0 + m) * DH + c];
        *(uint4*)&QS[m*68 + c] = make_uint4(f2tf(v.x), f2tf(v.y), f2tf(v.z), f2tf(v.w));
    }
    if (tid < 64) { sm_m[tid] = -1e30f; sm_l[tid] = 0.f; }
    int m0 = (wid & 3) * 16;
    int n0s = (wid >> 2) * 64;
    int n0o = (wid >> 2) * 32;
    float acco[4][4];
    #pragma unroll
    for (int j = 0; j < 4; j++) for (int u = 0; u < 4; u++) acco[j][u] = 0.f;
    __syncthreads();
    for (int ch = 0; ch < 16; ch++) {
        int k0 = sp * 2048 + ch * 128;
        #pragma unroll
        for (int p = 0; p < 8; p++) {
            int idx = tid + p * 256; int key = idx >> 4, c = (idx & 15) * 4;
            float4 kv = *(const float4*)&g_k[((size_t)bh * NSEQ + k0 + key) * DH + c];
            *(uint4*)&KS[key*72 + c] = make_uint4(f2tf(kv.x), f2tf(kv.y), f2tf(kv.z), f2tf(kv.w));
            float4 vv = *(const float4*)&g_v[((size_t)bh * NSEQ + k0 + key) * DH + c];
            *(uint4*)&VS[key*72 + c] = make_uint4(f2tf(vv.x), f2tf(vv.y), f2tf(vv.z), f2tf(vv.w));
        }
        __syncthreads();
        float accs[8][4];
        #pragma unroll
        for (int j = 0; j < 8; j++) for (int u = 0; u < 4; u++) accs[j][u] = 0.f;
        #pragma unroll
        for (int s = 0; s < 8; s++) {
            int ks = 8*s + t;
            u32 af[4];
            af[0] = QS[(m0+g)*68 + ks];   af[1] = QS[(m0+g+8)*68 + ks];
            af[2] = QS[(m0+g)*68 + ks+4]; af[3] = QS[(m0+g+8)*68 + ks+4];
            #pragma unroll
            for (int j = 0; j < 8; j++) {
                int n = n0s + 8*j + g;
                u32 bf2[2];
                bf2[0] = KS[n*72 + ks]; bf2[1] = KS[n*72 + ks + 4];
                mma8(accs[j], af, bf2);
            }
        }
        #pragma unroll
        for (int j = 0; j < 8; j++) {
            int col = n0s + 8*j + 2*t;
            *(float2*)&SS[(m0+g)*132 + col]   = make_float2(accs[j][0], accs[j][1]);
            *(float2*)&SS[(m0+g+8)*132 + col] = make_float2(accs[j][2], accs[j][3]);
        }
        __syncthreads();
        {
            int row = tid >> 2, t2 = tid & 3;
            float* Sr = &SS[row*132 + t2*32];
            float cmax = -1e30f;
            #pragma unroll
            for (int c = 0; c < 32; c++) cmax = fmaxf(cmax, Sr[c]);
            cmax = fmaxf(cmax, __shfl_xor_sync(0xffffffffu, cmax, 1));
            cmax = fmaxf(cmax, __shfl_xor_sync(0xffffffffu, cmax, 2));
            float mold = sm_m[row];
            float mnew = fmaxf(mold, cmax);
            float csum = 0.f;
            u32* Pr = (u32*)Sr;
            #pragma unroll
            for (int c = 0; c < 32; c++) {
                float pv = __expf(Sr[c] - mnew);
                csum += pv;
                Pr[c] = f2tf(pv);
            }
            csum += __shfl_xor_sync(0xffffffffu, csum, 1);
            csum += __shfl_xor_sync(0xffffffffu, csum, 2);
            if (t2 == 0) {
                float scv = __expf(mold - mnew);
                sm_sc[row] = scv;
                sm_l[row] = sm_l[row] * scv + csum;
                sm_m[row] = mnew;
            }
        }
        __syncthreads();
        {
            float s0 = sm_sc[m0 + g], s1 = sm_sc[m0 + g + 8];
            #pragma unroll
            for (int j = 0; j < 4; j++) {
                acco[j][0] *= s0; acco[j][1] *= s0;
                acco[j][2] *= s1; acco[j][3] *= s1;
            }
            const u32* PS = (const u32*)SS;
            #pragma unroll
            for (int s = 0; s < 16; s++) {
                int ks = 8*s + t;
                u32 af[4];
                af[0] = PS[(m0+g)*132 + ks];   af[1] = PS[(m0+g+8)*132 + ks];
                af[2] = PS[(m0+g)*132 + ks+4]; af[3] = PS[(m0+g+8)*132 + ks+4];
                #pragma unroll
                for (int j = 0; j < 4; j++) {
                    int n = n0o + 8*j + g;
                    u32 bf2[2];
                    bf2[0] = VS[ks*72 + n]; bf2[1] = VS[(ks+4)*72 + n];
                    mma8(acco[j], af, bf2);
                }
            }
        }
        __syncthreads();
    }
    size_t pb = ((size_t)(bh*4 + sp) * MM + r0);
    #pragma unroll
    for (int j = 0; j < 4; j++) {
        int col = n0o + 8*j + 2*t;
        *(float2*)&g_part[(pb + m0 + g) * DH + col]     = make_float2(acco[j][0], acco[j][1]);
        *(float2*)&g_part[(pb + m0 + g + 8) * DH + col] = make_float2(acco[j][2], acco[j][3]);
    }
    if (tid < 64) {
        g_m[(bh*4 + sp) * MM + r0 + tid] = sm_m[tid];
        g_l[(bh*4 + sp) * MM + r0 + tid] = sm_l[tid];
    }
}

__global__ void attn_combine() {
    int idx = blockIdx.x * 256 + threadIdx.x;
    int bh = idx >> 14, rem = idx & 16383, row = rem >> 6, d = rem & 63;
    float ms = -1e30f;
    #pragma unroll
    for (int s = 0; s < 4; s++) ms = fmaxf(ms, g_m[(bh*4+s)*MM + row]);
    float num = 0.f, den = 0.f;
    #pragma unroll
    for (int s = 0; s < 4; s++) {
        float e = __expf(g_m[(bh*4+s)*MM + row] - ms);
        num += g_part[((size_t)(bh*4+s)*MM + row)*DH + d] * e;
        den += g_l[(bh*4+s)*MM + row] * e;
    }
    g_a3v[((size_t)bh*MM + row)*DH + d] = num / den;
}

// attn1 + fused depthwise conv; writes bf16-packed out1.
__global__ __launch_bounds__(256) void attn1_kernel(const float* __restrict__ wres) {
    extern __shared__ float smf[];
    u32* QS  = (u32*)smf;                       // 64*68
    u32* KLS = QS + 64*68;                      // 256*72 -> reused as SS [64][264]
    u32* W2S = KLS + 256*72;                    // 256*72
    float* sm_l = (float*)(W2S + 256*72);       // 64
    float* VC   = sm_l + 64;                    // 96*68
    float* CONV = VC + 96*68;                   // 64*66
    float* wl   = CONV + 64*66;                 // 33
    float* SS = (float*)KLS;
    int tid = threadIdx.x;
    int r0 = blockIdx.x * 64;
    int bh = blockIdx.y;
    int lane = tid & 31, wid = tid >> 5;
    int g = lane >> 2, t = lane & 3;
    if (tid < KERN) wl[tid] = wres[(bh & 1) * KERN + tid];
    #pragma unroll
    for (int p = 0; p < 4; p++) {
        int idx = tid + p * 256; int m = idx >> 4, c = (idx & 15) * 4;
        float4 v = *(const float4*)&g_q[((size_t)bh * NSEQ + r0 + m) * DH + c];
        *(uint4*)&QS[m*68 + c] = make_uint4(f2tf(v.x), f2tf(v.y), f2tf(v.z), f2tf(v.w));
    }
    #pragma unroll
    for (int p = 0; p < 16; p++) {
        int idx = tid + p * 256; int m = idx >> 4, c = (idx & 15) * 4;
        float4 v = *(const float4*)&g_kl[((size_t)bh * MM + m) * DH + c];
        *(uint4*)&KLS[m*72 + c] = make_uint4(f2tf(v.x), f2tf(v.y), f2tf(v.z), f2tf(v.w));
        float4 w = *(const float4*)&g_w2[((size_t)bh * MM + m) * DH + c];
        *(uint4*)&W2S[m*72 + c] = make_uint4(f2tf(w.x), f2tf(w.y), f2tf(w.z), f2tf(w.w));
    }
    #pragma unroll
    for (int p = 0; p < 6; p++) {
        int idx = tid + p * 256; int li = idx >> 4, d4 = (idx & 15) * 4;
        int n = r0 - 16 + li;
        float4 val = make_float4(0.f, 0.f, 0.f, 0.f);
        if (n >= 0 && n < NSEQ) val = *(const float4*)&g_v[((size_t)bh * NSEQ + n) * DH + d4];
        *(float4*)&VC[li * 68 + d4] = val;
    }
    __syncthreads();
    int m0 = (wid & 3) * 16;
    int n0s = (wid >> 2) * 128;
    float accs[16][4];
    #pragma unroll
    for (int j = 0; j < 16; j++) for (int u = 0; u < 4; u++) accs[j][u] = 0.f;
    #pragma unroll
    for (int s = 0; s < 8; s++) {
        int ks = 8*s + t;
        u32 af[4];
        af[0] = QS[(m0+g)*68 + ks];   af[1] = QS[(m0+g+8)*68 + ks];
        af[2] = QS[(m0+g)*68 + ks+4]; af[3] = QS[(m0+g+8)*68 + ks+4];
        #pragma unroll
        for (int j = 0; j < 16; j++) {
            int n = n0s + 8*j + g;
            u32 bf2[2];
            bf2[0] = KLS[n*72 + ks]; bf2[1] = KLS[n*72 + ks + 4];
            mma8(accs[j], af, bf2);
        }
    }
    __syncthreads();
    #pragma unroll
    for (int j = 0; j < 16; j++) {
        int col = n0s + 8*j + 2*t;
        *(float2*)&SS[(m0+g)*264 + col]   = make_float2(accs[j][0], accs[j][1]);
        *(float2*)&SS[(m0+g+8)*264 + col] = make_float2(accs[j][2], accs[j][3]);
    }
    __syncthreads();
    {
        int row = tid >> 2, t2 = tid & 3;
        float* Sr = &SS[row*264 + t2*64];
        float cmax = -1e30f;
        #pragma unroll
        for (int c = 0; c < 64; c++) cmax = fmaxf(cmax, Sr[c]);
        cmax = fmaxf(cmax, __shfl_xor_sync(0xffffffffu, cmax, 1));
        cmax = fmaxf(cmax, __shfl_xor_sync(0xffffffffu, cmax, 2));
        float csum = 0.f;
        u32* Pr = (u32*)Sr;
        #pragma unroll
        for (int c = 0; c < 64; c++) {
            float pv = __expf(Sr[c] - cmax);
            csum += pv;
            Pr[c] = f2tf(pv);
        }
        csum += __shfl_xor_sync(0xffffffffu, csum, 1);
        csum += __shfl_xor_sync(0xffffffffu, csum, 2);
        if (t2 == 0) sm_l[row] = csum;
    }
    // conv: each thread computes 16 d-values for one output row
    {
        int rr = tid >> 2, ds = (tid & 3) * 16;
        #pragma unroll
        for (int d4 = 0; d4 < 4; d4++) {
            float4 a4 = make_float4(0.f, 0.f, 0.f, 0.f);
            #pragma unroll
            for (int tap = 0; tap < KERN; tap++) {
                float w = wl[tap];
                float4 vv = *(const float4*)&VC[(rr + tap) * 68 + ds + d4 * 4];
                a4.x += w * vv.x; a4.y += w * vv.y; a4.z += w * vv.z; a4.w += w * vv.w;
            }
            CONV[rr * 66 + ds + d4 * 4 + 0] = a4.x;
            CONV[rr * 66 + ds + d4 * 4 + 1] = a4.y;
            CONV[rr * 66 + ds + d4 * 4 + 2] = a4.z;
            CONV[rr * 66 + ds + d4 * 4 + 3] = a4.w;
        }
    }
    __syncthreads();
    int n0o = (wid >> 2) * 32;
    float acco[4][4];
    #pragma unroll
    for (int j = 0; j < 4; j++) for (int u = 0; u < 4; u++) acco[j][u] = 0.f;
    const u32* PS = (const u32*)SS;
    #pragma unroll
    for (int s = 0; s < 32; s++) {
        int ks = 8*s + t;
        u32 af[4];
        af[0] = PS[(m0+g)*264 + ks];   af[1] = PS[(m0+g+8)*264 + ks];
        af[2] = PS[(m0+g)*264 + ks+4]; af[3] = PS[(m0+g+8)*264 + ks+4];
        #pragma unroll
        for (int j = 0; j < 4; j++) {
            int n = n0o + 8*j + g;
            u32 bf2[2];
            bf2[0] = W2S[ks*72 + n]; bf2[1] = W2S[(ks+4)*72 + n];
            mma8(acco[j], af, bf2);
        }
    }
    float il0 = 1.f / sm_l[m0 + g], il1 = 1.f / sm_l[m0 + g + 8];
    size_t ob = (size_t)bh * NSEQ + r0;
    int row0l = m0 + g, row1l = m0 + g + 8;
    #pragma unroll
    for (int j = 0; j < 4; j++) {
        int col = n0o + 8*j + 2*t;
        int dp = col >> 1;
        float v00 = acco[j][0]*il0 + CONV[row0l*66 + col];
        float v01 = acco[j][1]*il0 + CONV[row0l*66 + col + 1];
        float v10 = acco[j][2]*il1 + CONV[row1l*66 + col];
        float v11 = acco[j][3]*il1 + CONV[row1l*66 + col + 1];
        g_out1h[(ob + row0l) * 32 + dp] = pk2(v00, v01);
        g_out1h[(ob + row1l) * 32 + dp] = pk2(v10, v11);
    }
}

// ---------------- launch ----------------
extern "C" void kernel_launch(void* const* d_in, const int* in_sizes, int n_in,
                              void* d_out, int out_size) {
    const float* x     = (const float*)d_in[0];
    const float* gamma = (const float*)d_in[1];
    const float* beta  = (const float*)d_in[2];
    const float* wqkv  = (const float*)d_in[3];
    const float* wout  = (const float*)d_in[4];
    const float* bout  = (const float*)d_in[5];
    const float* wres  = (const float*)d_in[6];
    float* out = (float*)d_out;

    float *pA2, *pXZ, *pT1, *pT2, *pZA, *pZB, *pA3V, *pW2;
    cudaGetSymbolAddress((void**)&pA2, g_a2);
    cudaGetSymbolAddress((void**)&pXZ, g_xz);
    cudaGetSymbolAddress((void**)&pT1, g_t1);
    cudaGetSymbolAddress((void**)&pT2, g_t2);
    cudaGetSymbolAddress((void**)&pZA, g_za);
    cudaGetSymbolAddress((void**)&pZB, g_zb);
    cudaGetSymbolAddress((void**)&pA3V, g_a3v);
    cudaGetSymbolAddress((void**)&pW2, g_w2);

    cudaFuncSetAttribute(attn3_kernel, cudaFuncAttributeMaxDynamicSharedMemorySize, 125696);
    cudaFuncSetAttribute(attn1_kernel, cudaFuncAttributeMaxDynamicSharedMemorySize, 210000);

    init_kernel<<<1, 1>>>();
    prepack_kernel<<<512, 256>>>(wqkv, wout);
    ln_kernel<<<TOK, 128>>>(x, gamma, beta);
    qkv_mma<<<dim3(TOK / 128, 3), 256>>>();
    landmark_kernel<<<dim3(BH, MM), 64>>>();
    sim2_kernel<<<BH * MM, 256>>>();
    absmax_kernel<<<dim3(BH, 2), 256>>>();
    zinit_kernel<<<BH * MM, 256>>>();

    float* zc = pZA;
    float* zn = pZB;
    for (int it = 0; it < 6; it++) {
        bmm_mma<<<dim3(4, 4, BH), 256>>>(pA2, zc, pXZ, 1.f, 0.f, 0.f);
        bmm_mma<<<dim3(4, 4, BH), 256>>>(pXZ, pXZ, pT1, 1.f, -7.f, 15.f);
        bmm_mma<<<dim3(4, 4, BH), 256>>>(pXZ, pT1, pT2, -1.f, 0.f, 13.f);
        bmm_mma<<<dim3(4, 4, BH), 256>>>(zc, pT2, zn, 0.25f, 0.f, 0.f);
        float* t = zc; zc = zn; zn = t;
    }

    attn3_kernel<<<dim3(4, 4, BH), 256, 125696>>>();
    attn_combine<<<512, 256>>>();
    nn64_mma<<<dim3(4, 1, BH), 128>>>(zc, pA3V, pW2, MM,
        (size_t)MM * MM, (size_t)MM * 64, (size_t)MM * 64, MM);
    attn1_kernel<<<dim3(NSEQ / 64, BH), 256, 210000>>>(wres);
    outgemm_mma<<<dim3(TOK / 128, 4), 256>>>(x, bout, out);
}

// round 8
// speedup vs baseline: 1.5536x; 1.0495x over previous
#include <cuda_runtime.h>
#include <math.h>

#define BB 4
#define NSEQ 8192
#define DD 512
#define HH 2
#define DH 64
#define INNER 128
#define MM 256
#define LLM 32
#define BH (BB*HH)
#define TOK (BB*NSEQ)
#define KERN 33

typedef unsigned u32;

__device__ u32   g_xnh[(size_t)TOK*256];        // layernormed x, bf16x2 packed [tok][k/2]
__device__ u32   g_wqkvh[256*384];              // w_qkv bf16x2 packed [k/2][n]
__device__ u32   g_wouth[64*512];               // w_out bf16x2 packed [k/2][n]
__device__ float g_q[(size_t)BH*NSEQ*DH];
__device__ float g_k[(size_t)BH*NSEQ*DH];
__device__ float g_v[(size_t)BH*NSEQ*DH];
__device__ float g_ql[BH*MM*DH];
__device__ float g_kl[BH*MM*DH];
__device__ float g_a2[BH*MM*MM];
__device__ float g_xz[BH*MM*MM];
__device__ float g_t1[BH*MM*MM];
__device__ float g_t2[BH*MM*MM];
__device__ float g_za[BH*MM*MM];
__device__ float g_zb[BH*MM*MM];
__device__ float g_a3v[BH*MM*DH];
__device__ float g_w2[BH*MM*DH];
__device__ u32   g_out1h[(size_t)BH*NSEQ*32];   // out1 bf16x2 packed [bh][n][d/2]
__device__ float g_part[BH*8*MM*DH];
__device__ float g_m[BH*4*MM];
__device__ float g_l[BH*4*MM];
__device__ unsigned g_max0, g_max1;

// ---- tf32 helpers (attn kernels) ----
__device__ __forceinline__ unsigned f2tf(float f) {
    unsigned r; asm("cvt.rna.tf32.f32 %0, %1;" : "=r"(r) : "f"(f)); return r;
}
__device__ __forceinline__ void mma8(float* c, const unsigned* a, const unsigned* b) {
    asm volatile("mma.sync.aligned.m16n8k8.row.col.f32.tf32.tf32.f32 "
        "{%0,%1,%2,%3}, {%4,%5,%6,%7}, {%8,%9}, {%0,%1,%2,%3};"
        : "+f"(c[0]), "+f"(c[1]), "+f"(c[2]), "+f"(c[3])
        : "r"(a[0]), "r"(a[1]), "r"(a[2]), "r"(a[3]), "r"(b[0]), "r"(b[1]));
}
// ---- bf16 helpers ----
__device__ __forceinline__ u32 pk2(float lo, float hi) {
    u32 r; asm("cvt.rn.bf16x2.f32 %0, %2, %1;" : "=r"(r) : "f"(lo), "f"(hi)); return r;
}
__device__ __forceinline__ void mmab(float* c, const u32* a, const u32* b) {
    asm volatile("mma.sync.aligned.m16n8k16.row.col.f32.bf16.bf16.f32 "
        "{%0,%1,%2,%3}, {%4,%5,%6,%7}, {%8,%9}, {%0,%1,%2,%3};"
        : "+f"(c[0]), "+f"(c[1]), "+f"(c[2]), "+f"(c[3])
        : "r"(a[0]), "r"(a[1]), "r"(a[2]), "r"(a[3]), "r"(b[0]), "r"(b[1]));
}
__device__ __forceinline__ uint4 pkA(float4 v1, float4 v2) {
    return make_uint4(pk2(v1.x,v1.y), pk2(v1.z,v1.w), pk2(v2.x,v2.y), pk2(v2.z,v2.w));
}
__device__ __forceinline__ uint4 pkB(float4 r1, float4 r2) {
    return make_uint4(pk2(r1.x,r2.x), pk2(r1.y,r2.y), pk2(r1.z,r2.z), pk2(r1.w,r2.w));
}
// ldmatrix x4: loads a 16x16 bf16 A-fragment (4 regs) in one instruction
__device__ __forceinline__ void ldsm4(u32* r, u32 addr) {
    asm volatile("ldmatrix.sync.aligned.m8n8.x4.shared.b16 {%0,%1,%2,%3}, [%4];"
        : "=r"(r[0]), "=r"(r[1]), "=r"(r[2]), "=r"(r[3]) : "r"(addr));
}

__global__ void init_kernel() { g_max0 = 0u; g_max1 = 0u; }

__global__ void prepack_kernel(const float* __restrict__ wqkv, const float* __restrict__ wout) {
    int idx = blockIdx.x * 256 + threadIdx.x;
    if (idx < 256 * 384) {
        int kp = idx / 384, n = idx % 384;
        g_wqkvh[idx] = pk2(wqkv[(size_t)(2*kp) * 384 + n], wqkv[(size_t)(2*kp+1) * 384 + n]);
    } else {
        int j = idx - 256 * 384;
        int kp = j / 512, n = j % 512;
        g_wouth[j] = pk2(wout[(size_t)(2*kp) * 512 + n], wout[(size_t)(2*kp+1) * 512 + n]);
    }
}

__global__ __launch_bounds__(128) void ln_kernel(const float* __restrict__ x,
                                                 const float* __restrict__ gamma,
                                                 const float* __restrict__ beta) {
    int t = blockIdx.x, tid = threadIdx.x;
    const float4* xr = (const float4*)(x + (size_t)t * DD);
    float4 v = xr[tid];
    float s  = v.x + v.y + v.z + v.w;
    float sq = v.x*v.x + v.y*v.y + v.z*v.z + v.w*v.w;
    __shared__ float sb[8];
    #pragma unroll
    for (int o = 16; o; o >>= 1) {
        s  += __shfl_xor_sync(0xffffffffu, s, o);
        sq += __shfl_xor_sync(0xffffffffu, sq, o);
    }
    int w = tid >> 5, l = tid & 31;
    if (l == 0) { sb[w] = s; sb[4 + w] = sq; }
    __syncthreads();
    if (tid == 0) { sb[0] = sb[0]+sb[1]+sb[2]+sb[3]; sb[4] = sb[4]+sb[5]+sb[6]+sb[7]; }
    __syncthreads();
    float mu  = sb[0] * (1.f / DD);
    float var = sb[4] * (1.f / DD) - mu * mu;
    float rs  = rsqrtf(var + 1e-5f);
    float4 g4 = ((const float4*)gamma)[tid];
    float4 b4 = ((const float4*)beta)[tid];
    float4 o;
    o.x = (v.x - mu) * rs * g4.x + b4.x;
    o.y = (v.y - mu) * rs * g4.y + b4.y;
    o.z = (v.z - mu) * rs * g4.z + b4.z;
    o.w = (v.w - mu) * rs * g4.w + b4.w;
    uint2 pr = make_uint2(pk2(o.x, o.y), pk2(o.z, o.w));
    *(uint2*)&g_xnh[(size_t)t * 256 + tid * 2] = pr;
}

__global__ void landmark_kernel() {
    int bh = blockIdx.x, m = blockIdx.y, d = threadIdx.x;
    size_t base = ((size_t)bh * NSEQ + m * LLM) * DH + d;
    float sq = 0.f, sk = 0.f;
    #pragma unroll 8
    for (int i = 0; i < LLM; i++) { sq += g_q[base + (size_t)i * DH]; sk += g_k[base + (size_t)i * DH]; }
    g_ql[(bh * MM + m) * DH + d] = sq * (1.f / LLM);
    g_kl[(bh * MM + m) * DH + d] = sk * (1.f / LLM);
}

__global__ __launch_bounds__(256) void sim2_kernel() {
    int bh = blockIdx.x >> 8, i = blockIdx.x & 255;
    int tid = threadIdx.x;
    __shared__ float qs[DH];
    __shared__ float red[8];
    if (tid < DH) qs[tid] = g_ql[(bh * MM + i) * DH + tid];
    __syncthreads();
    const float* kr = &g_kl[(bh * MM + tid) * DH];
    float s = 0.f;
    #pragma unroll
    for (int d = 0; d < DH; d += 4) {
        float4 kv = *(const float4*)&kr[d];
        s += qs[d]*kv.x + qs[d+1]*kv.y + qs[d+2]*kv.z + qs[d+3]*kv.w;
    }
    float m = s;
    #pragma unroll
    for (int o = 16; o; o >>= 1) m = fmaxf(m, __shfl_xor_sync(0xffffffffu, m, o));
    int w = tid >> 5, l = tid & 31;
    if (l == 0) red[w] = m;
    __syncthreads();
    if (w == 0) {
        float t = red[l & 7];
        #pragma unroll
        for (int o = 4; o; o >>= 1) t = fmaxf(t, __shfl_xor_sync(0xffffffffu, t, o));
        if (l == 0) red[0] = t;
    }
    __syncthreads();
    m = red[0];
    __syncthreads();
    float e = __expf(s - m);
    float su = e;
    #pragma unroll
    for (int o = 16; o; o >>= 1) su += __shfl_xor_sync(0xffffffffu, su, o);
    if (l == 0) red[w] = su;
    __syncthreads();
    if (w == 0) {
        float t = red[l & 7];
        #pragma unroll
        for (int o = 4; o; o >>= 1) t += __shfl_xor_sync(0xffffffffu, t, o);
        if (l == 0) red[0] = t;
    }
    __syncthreads();
    g_a2[((size_t)bh * MM + i) * MM + tid] = e / red[0];
}

__global__ __launch_bounds__(256) void absmax_kernel() {
    int bh = blockIdx.x, mode = blockIdx.y, tid = threadIdx.x;
    const float* A = &g_a2[(size_t)bh * MM * MM];
    float s = 0.f;
    if (mode == 0) { for (int j = 0; j < MM; j++) s += fabsf(A[tid * MM + j]); }
    else           { for (int i = 0; i < MM; i++) s += fabsf(A[i * MM + tid]); }
    float m = s;
    #pragma unroll
    for (int o = 16; o; o >>= 1) m = fmaxf(m, __shfl_xor_sync(0xffffffffu, m, o));
    __shared__ float red[8];
    int w = tid >> 5, l = tid & 31;
    if (l == 0) red[w] = m;
    __syncthreads();
    if (tid == 0) {
        float t = red[0];
        for (int u = 1; u < 8; u++) t = fmaxf(t, red[u]);
        atomicMax(mode == 0 ? &g_max0 : &g_max1, __float_as_uint(t));
    }
}

__global__ __launch_bounds__(256) void zinit_kernel() {
    int bh = blockIdx.x >> 8, i = blockIdx.x & 255, j = threadIdx.x;
    float inv = 1.f / (__uint_as_float(g_max0) * __uint_as_float(g_max1));
    g_za[((size_t)bh * MM + i) * MM + j] = g_a2[((size_t)bh * MM + j) * MM + i] * inv;
}

// ---------- bf16 packed GEMMs ----------
__global__ __launch_bounds__(256) void qkv_mma() {
    __shared__ u32 SA[2][128*20];
    __shared__ u32 SB[2][16*132];
    int tid = threadIdx.x;
    int row0 = blockIdx.x * 128, col0 = blockIdx.y * 128;
    int lane = tid & 31, wid = tid >> 5;
    int g = lane >> 2, t = lane & 3;
    int wm = (wid & 1) * 64, wn = (wid >> 1) * 32;
    int mi = lane >> 3;
    int lrow = (lane & 7) + (mi & 1) * 8;
    int lcol = (mi >> 1) * 4;
    float acc[4][4][4];
    #pragma unroll
    for (int i = 0; i < 4; i++) for (int j = 0; j < 4; j++) for (int u = 0; u < 4; u++) acc[i][j][u] = 0.f;
    uint4 ua[2], ub[2];
    auto LOAD = [&](int kt) {
        int kp0 = kt >> 1;
        #pragma unroll
        for (int p = 0; p < 2; p++) {
            int idx = tid + p * 256; int m = idx >> 2, kg = idx & 3;
            ua[p] = *(const uint4*)&g_xnh[(size_t)(row0 + m) * 256 + kp0 + kg * 4];
        }
        #pragma unroll
        for (int p = 0; p < 2; p++) {
            int idx = tid + p * 256; int kp = idx >> 5, n4 = (idx & 31) * 4;
            ub[p] = *(const uint4*)&g_wqkvh[(size_t)(kp0 + kp) * 384 + col0 + n4];
        }
    };
    auto STS = [&](int buf) {
        #pragma unroll
        for (int p = 0; p < 2; p++) {
            int idx = tid + p * 256; int m = idx >> 2, kg = idx & 3;
            *(uint4*)&SA[buf][m * 20 + kg * 4] = ua[p];
        }
        #pragma unroll
        for (int p = 0; p < 2; p++) {
            int idx = tid + p * 256; int kp = idx >> 5, n4 = (idx & 31) * 4;
            *(uint4*)&SB[buf][kp * 132 + n4] = ub[p];
        }
    };
    auto COMP = [&](int buf) {
        u32 sa0 = (u32)__cvta_generic_to_shared(&SA[buf][(wm + lrow) * 20 + lcol]);
        #pragma unroll
        for (int s = 0; s < 2; s++) {
            int kp = 8 * s + t;
            u32 af[4][4], bf[4][2];
            #pragma unroll
            for (int i = 0; i < 4; i++)
                ldsm4(af[i], sa0 + ((16 * i * 20 + 8 * s) << 2));
            #pragma unroll
            for (int j = 0; j < 4; j++) {
                int n = wn + 8 * j + g;
                bf[j][0] = SB[buf][kp * 132 + n];
                bf[j][1] = SB[buf][(kp + 4) * 132 + n];
            }
            #pragma unroll
            for (int i = 0; i < 4; i++)
                #pragma unroll
                for (int j = 0; j < 4; j++) mmab(acc[i][j], af[i], bf[j]);
        }
    };
    LOAD(0); STS(0); __syncthreads();
    for (int it = 0; it < 16; it++) {
        if (it + 1 < 16) LOAD((it + 1) * 32);
        COMP(it & 1);
        if (it + 1 < 16) { STS((it + 1) & 1); __syncthreads(); }
    }
    auto STORE2 = [&](int tok, int c, float v0, float v1) {
        int bb = tok >> 13, n = tok & 8191;
        int which = c >> 7, hd = c & 127, h = hd >> 6, d = hd & 63;
        size_t dst = (((size_t)(bb * HH + h)) * NSEQ + n) * DH + d;
        if (which == 0)      *(float2*)&g_q[dst] = make_float2(v0 * 0.125f, v1 * 0.125f);
        else if (which == 1) *(float2*)&g_k[dst] = make_float2(v0, v1);
        else                 *(float2*)&g_v[dst] = make_float2(v0, v1);
    };
    #pragma unroll
    for (int i = 0; i < 4; i++) {
        int row = row0 + wm + 16 * i + g;
        #pragma unroll
        for (int j = 0; j < 4; j++) {
            int col = col0 + wn + 8 * j + 2 * t;
            STORE2(row, col, acc[i][j][0], acc[i][j][1]);
            STORE2(row + 8, col, acc[i][j][2], acc[i][j][3]);
        }
    }
}

__global__ __launch_bounds__(256) void outgemm_mma(const float* __restrict__ x,
                                                   const float* __restrict__ bout,
                                                   float* __restrict__ out) {
    __shared__ u32 SA[2][128*20];
    __shared__ u32 SB[2][16*132];
    int tid = threadIdx.x;
    int row0 = blockIdx.x * 128, col0 = blockIdx.y * 128;
    int lane = tid & 31, wid = tid >> 5;
    int g = lane >> 2, t = lane & 3;
    int wm = (wid & 1) * 64, wn = (wid >> 1) * 32;
    int mi = lane >> 3;
    int lrow = (lane & 7) + (mi & 1) * 8;
    int lcol = (mi >> 1) * 4;
    float acc[4][4][4];
    #pragma unroll
    for (int i = 0; i < 4; i++) for (int j = 0; j < 4; j++) for (int u = 0; u < 4; u++) acc[i][j][u] = 0.f;
    uint4 ua[2], ub[2];
    auto LOAD = [&](int kt) {
        int kp0 = kt >> 1;
        #pragma unroll
        for (int p = 0; p < 2; p++) {
            int idx = tid + p * 256; int m = idx >> 2, kg = idx & 3;
            int tok = row0 + m; int bb = tok >> 13, n = tok & 8191;
            int kp = kp0 + kg * 4;
            int h = kp >> 5, dp = kp & 31;
            ua[p] = *(const uint4*)&g_out1h[(((size_t)(bb * HH + h)) * NSEQ + n) * 32 + dp];
        }
        #pragma unroll
        for (int p = 0; p < 2; p++) {
            int idx = tid + p * 256; int kp = idx >> 5, n4 = (idx & 31) * 4;
            ub[p] = *(const uint4*)&g_wouth[(size_t)(kp0 + kp) * 512 + col0 + n4];
        }
    };
    auto STS = [&](int buf) {
        #pragma unroll
        for (int p = 0; p < 2; p++) {
            int idx = tid + p * 256; int m = idx >> 2, kg = idx & 3;
            *(uint4*)&SA[buf][m * 20 + kg * 4] = ua[p];
        }
        #pragma unroll
        for (int p = 0; p < 2; p++) {
            int idx = tid + p * 256; int kp = idx >> 5, n4 = (idx & 31) * 4;
            *(uint4*)&SB[buf][kp * 132 + n4] = ub[p];
        }
    };
    auto COMP = [&](int buf) {
        u32 sa0 = (u32)__cvta_generic_to_shared(&SA[buf][(wm + lrow) * 20 + lcol]);
        #pragma unroll
        for (int s = 0; s < 2; s++) {
            int kp = 8 * s + t;
            u32 af[4][4], bf[4][2];
            #pragma unroll
            for (int i = 0; i < 4; i++)
                ldsm4(af[i], sa0 + ((16 * i * 20 + 8 * s) << 2));
            #pragma unroll
            for (int j = 0; j < 4; j++) {
                int n = wn + 8 * j + g;
                bf[j][0] = SB[buf][kp * 132 + n];
                bf[j][1] = SB[buf][(kp + 4) * 132 + n];
            }
            #pragma unroll
            for (int i = 0; i < 4; i++)
                #pragma unroll
                for (int j = 0; j < 4; j++) mmab(acc[i][j], af[i], bf[j]);
        }
    };
    LOAD(0); STS(0); __syncthreads();
    for (int it = 0; it < 4; it++) {
        if (it + 1 < 4) LOAD((it + 1) * 32);
        COMP(it & 1);
        if (it + 1 < 4) { STS((it + 1) & 1); __syncthreads(); }
    }
    #pragma unroll
    for (int i = 0; i < 4; i++) {
        int row = row0 + wm + 16 * i + g;
        #pragma unroll
        for (int j = 0; j < 4; j++) {
            int col = col0 + wn + 8 * j + 2 * t;
            float2 bb = *(const float2*)&bout[col];
            float2 x0 = *(const float2*)&x[(size_t)row*DD + col];
            float2 x1 = *(const float2*)&x[(size_t)(row+8)*DD + col];
            *(float2*)&out[(size_t)row*DD + col] =
                make_float2(acc[i][j][0] + bb.x + x0.x, acc[i][j][1] + bb.y + x0.y);
            *(float2*)&out[(size_t)(row+8)*DD + col] =
                make_float2(acc[i][j][2] + bb.x + x1.x, acc[i][j][3] + bb.y + x1.y);
        }
    }
}

// pinv bmm: 256x256x256, C = alpha*(A@B) + beta*A + gamma*I. bf16 packed + LDSM.
__global__ __launch_bounds__(256) void bmm_mma(const float* __restrict__ A,
                                               const float* __restrict__ Bm,
                                               float* __restrict__ C,
                                               float alpha, float beta, float gam) {
    __shared__ u32 SA[2][64*20];
    __shared__ u32 SB[2][16*68];
    int bh = blockIdx.z;
    size_t base = (size_t)bh * MM * MM;
    int i0 = blockIdx.x * 64, j0 = blockIdx.y * 64;
    int tid = threadIdx.x;
    int lane = tid & 31, wid = tid >> 5;
    int g = lane >> 2, t = lane & 3;
    int wm = (wid & 3) * 16, wn = (wid >> 2) * 32;
    int mi = lane >> 3;
    int lrow = (lane & 7) + (mi & 1) * 8;
    int lcol = (mi >> 1) * 4;
    float acc[4][4];
    #pragma unroll
    for (int j = 0; j < 4; j++) for (int u = 0; u < 4; u++) acc[j][u] = 0.f;
    int am = tid >> 2, akg = tid & 3;
    int bkp = tid >> 4, bn4 = (tid & 15) * 4;
    float4 a1, a2, b1, b2;
    auto LOAD = [&](int kt) {
        const float* src = &A[base + (size_t)(i0 + am) * MM + kt + akg * 8];
        a1 = *(const float4*)src;
        a2 = *(const float4*)(src + 4);
        int k = kt + bkp * 2;
        b1 = *(const float4*)&Bm[base + (size_t)k * MM + j0 + bn4];
        b2 = *(const float4*)&Bm[base + (size_t)(k + 1) * MM + j0 + bn4];
    };
    auto STS = [&](int buf) {
        *(uint4*)&SA[buf][am * 20 + akg * 4] = pkA(a1, a2);
        *(uint4*)&SB[buf][bkp * 68 + bn4] = pkB(b1, b2);
    };
    auto COMP = [&](int buf) {
        u32 sa0 = (u32)__cvta_generic_to_shared(&SA[buf][(wm + lrow) * 20 + lcol]);
        #pragma unroll
        for (int s = 0; s < 2; s++) {
            int kp = 8 * s + t;
            u32 af[4], bf[4][2];
            ldsm4(af, sa0 + ((8 * s) << 2));
            #pragma unroll
            for (int j = 0; j < 4; j++) {
                int n = wn + 8 * j + g;
                bf[j][0] = SB[buf][kp * 68 + n];
                bf[j][1] = SB[buf][(kp + 4) * 68 + n];
            }
            #pragma unroll
            for (int j = 0; j < 4; j++) mmab(acc[j], af, bf[j]);
        }
    };
    LOAD(0); STS(0); __syncthreads();
    for (int it = 0; it < 8; it++) {
        if (it + 1 < 8) LOAD((it + 1) * 32);
        COMP(it & 1);
        if (it + 1 < 8) { STS((it + 1) & 1); __syncthreads(); }
    }
    #pragma unroll
    for (int j = 0; j < 4; j++) {
        #pragma unroll
        for (int u = 0; u < 4; u++) {
            int row = i0 + wm + g + (u >> 1) * 8;
            int col = j0 + wn + 8 * j + 2 * t + (u & 1);
            float r = alpha * acc[j][u];
            if (beta != 0.f) r += beta * A[base + (size_t)row * MM + col];
            if (row == col) r += gam;
            C[base + (size_t)row * MM + col] = r;
        }
    }
}

// NN, N=64 tf32 (W2 = Z @ a3v only)
__global__ __launch_bounds__(128) void nn64_mma(const float* __restrict__ A,
                                                const float* __restrict__ B,
                                                float* __restrict__ C,
                                                int lda, size_t aBatch, size_t bBatch,
                                                size_t cBatch, int kchunk) {
    __shared__ unsigned As[64*36];
    __shared__ unsigned Bs[32*72];
    int bh = blockIdx.z;
    int m0 = blockIdx.x * 64;
    const float* Ab = A + (size_t)bh * aBatch + (size_t)m0 * lda;
    const float* Bb = B + (size_t)bh * bBatch;
    int tid = threadIdx.x;
    int lane = tid & 31, wid = tid >> 5;
    int g = lane >> 2, t = lane & 3;
    int wm = (wid & 1) * 32, wn = (wid >> 1) * 32;
    float acc[2][4][4];
    #pragma unroll
    for (int i = 0; i < 2; i++) for (int j = 0; j < 4; j++) for (int u = 0; u < 4; u++) acc[i][j][u] = 0.f;
    int iters = kchunk / 32;
    for (int it = 0; it < iters; it++) {
        #pragma unroll
        for (int p = 0; p < 4; p++) {
            int idx = tid + p * 128; int m = idx >> 3, c = (idx & 7) * 4;
            float4 v = *(const float4*)&Ab[(size_t)m * lda + it*32 + c];
            *(uint4*)&As[m*36+c] = make_uint4(f2tf(v.x), f2tf(v.y), f2tf(v.z), f2tf(v.w));
        }
        #pragma unroll
        for (int p = 0; p < 4; p++) {
            int idx = tid + p * 128; int k = idx >> 4, c = (idx & 15) * 4;
            float4 v = *(const float4*)&Bb[(size_t)(it*32 + k) * 64 + c];
            *(uint4*)&Bs[k*72+c] = make_uint4(f2tf(v.x), f2tf(v.y), f2tf(v.z), f2tf(v.w));
        }
        __syncthreads();
        #pragma unroll
        for (int s = 0; s < 4; s++) {
            unsigned af[2][4], bf[4][2];
            #pragma unroll
            for (int i = 0; i < 2; i++) {
                const unsigned* p = &As[(wm + 16*i + g)*36 + 8*s + t];
                af[i][0] = p[0]; af[i][1] = p[288]; af[i][2] = p[4]; af[i][3] = p[292];
            }
            #pragma unroll
            for (int j = 0; j < 4; j++) {
                const unsigned* p = &Bs[(8*s + t)*72 + wn + 8*j + g];
                bf[j][0] = p[0]; bf[j][1] = p[288];
            }
            #pragma unroll
            for (int i = 0; i < 2; i++)
                #pragma unroll
                for (int j = 0; j < 4; j++) mma8(acc[i][j], af[i], bf[j]);
        }
        __syncthreads();
    }
    float* Cb = C + (size_t)bh * cBatch + (size_t)m0 * 64;
    #pragma unroll
    for (int i = 0; i < 2; i++) {
        int row = wm + 16*i + g;
        #pragma unroll
        for (int j = 0; j < 4; j++) {
            int col = wn + 8*j + 2*t;
            Cb[(size_t)row*64 + col]       = acc[i][j][0];
            Cb[(size_t)row*64 + col+1]     = acc[i][j][1];
            Cb[(size_t)(row+8)*64 + col]   = acc[i][j][2];
            Cb[(size_t)(row+8)*64 + col+1] = acc[i][j][3];
        }
    }
}

// ---------- fused flash kernels ----------
__global__ __launch_bounds__(256) void attn3_kernel() {
    extern __shared__ float smf[];
    u32* QS = (u32*)smf;
    u32* KS = QS + 64*68;
    u32* VS = KS + 128*72;
    float* SS = (float*)(VS + 128*72);
    float* sm_m = SS + 64*132;
    float* sm_l = sm_m + 64;
    float* sm_sc = sm_l + 64;
    int tid = threadIdx.x;
    int r0 = blockIdx.x * 64;
    int sp = blockIdx.y;
    int bh = blockIdx.z;
    int lane = tid & 31, wid = tid >> 5;
    int g = lane >> 2, t = lane & 3;
    #pragma unroll
    for (int p = 0; p < 4; p++) {
        int idx = tid + p * 256; int m = idx >> 4, c = (idx & 15) * 4;
        float4 v = *(const float4*)&g_ql[((size_t)bh * MM + r0 + m) * DH + c];
        *(uint4*)&QS[m*68 + c] = make_uint4(f2tf(v.x), f2tf(v.y), f2tf(v.z), f2tf(v.w));
    }
    if (tid < 64) { sm_m[tid] = -1e30f; sm_l[tid] = 0.f; }
    int m0 = (wid & 3) * 16;
    int n0s = (wid >> 2) * 64;
    int n0o = (wid >> 2) * 32;
    float acco[4][4];
    #pragma unroll
    for (int j = 0; j < 4; j++) for (int u = 0; u < 4; u++) acco[j][u] = 0.f;
    __syncthreads();
    for (int ch = 0; ch < 16; ch++) {
        int k0 = sp * 2048 + ch * 128;
        #pragma unroll
        for (int p = 0; p < 8; p++) {
            int idx = tid + p * 256; int key = idx >> 4, c = (idx & 15) * 4;
            float4 kv = *(const float4*)&g_k[((size_t)bh * NSEQ + k0 + key) * DH + c];
            *(uint4*)&KS[key*72 + c] = make_uint4(f2tf(kv.x), f2tf(kv.y), f2tf(kv.z), f2tf(kv.w));
            float4 vv = *(const float4*)&g_v[((size_t)bh * NSEQ + k0 + key) * DH + c];
            *(uint4*)&VS[key*72 + c] = make_uint4(f2tf(vv.x), f2tf(vv.y), f2tf(vv.z), f2tf(vv.w));
        }
        __syncthreads();
        float accs[8][4];
        #pragma unroll
        for (int j = 0; j < 8; j++) for (int u = 0; u < 4; u++) accs[j][u] = 0.f;
        #pragma unroll
        for (int s = 0; s < 8; s++) {
            int ks = 8*s + t;
            u32 af[4];
            af[0] = QS[(m0+g)*68 + ks];   af[1] = QS[(m0+g+8)*68 + ks];
            af[2] = QS[(m0+g)*68 + ks+4]; af[3] = QS[(m0+g+8)*68 + ks+4];
            #pragma unroll
            for (int j = 0; j < 8; j++) {
                int n = n0s + 8*j + g;
                u32 bf2[2];
                bf2[0] = KS[n*72 + ks]; bf2[1] = KS[n*72 + ks + 4];
                mma8(accs[j], af, bf2);
            }
        }
        #pragma unroll
        for (int j = 0; j < 8; j++) {
            int col = n0s + 8*j + 2*t;
            *(float2*)&SS[(m0+g)*132 + col]   = make_float2(accs[j][0], accs[j][1]);
            *(float2*)&SS[(m0+g+8)*132 + col] = make_float2(accs[j][2], accs[j][3]);
        }
        __syncthreads();
        {
            int row = tid >> 2, t2 = tid & 3;
            float* Sr = &SS[row*132 + t2*32];
            float cmax = -1e30f;
            #pragma unroll
            for (int c = 0; c < 32; c++) cmax = fmaxf(cmax, Sr[c]);
            cmax = fmaxf(cmax, __shfl_xor_sync(0xffffffffu, cmax, 1));
            cmax = fmaxf(cmax, __shfl_xor_sync(0xffffffffu, cmax, 2));
            float mold = sm_m[row];
            float mnew = fmaxf(mold, cmax);
            float csum = 0.f;
            u32* Pr = (u32*)Sr;
            #pragma unroll
            for (int c = 0; c < 32; c++) {
                float pv = __expf(Sr[c] - mnew);
                csum += pv;
                Pr[c] = f2tf(pv);
            }
            csum += __shfl_xor_sync(0xffffffffu, csum, 1);
            csum += __shfl_xor_sync(0xffffffffu, csum, 2);
            if (t2 == 0) {
                float scv = __expf(mold - mnew);
                sm_sc[row] = scv;
                sm_l[row] = sm_l[row] * scv + csum;
                sm_m[row] = mnew;
            }
        }
        __syncthreads();
        {
            float s0 = sm_sc[m0 + g], s1 = sm_sc[m0 + g + 8];
            #pragma unroll
            for (int j = 0; j < 4; j++) {
                acco[j][0] *= s0; acco[j][1] *= s0;
                acco[j][2] *= s1; acco[j][3] *= s1;
            }
            const u32* PS = (const u32*)SS;
            #pragma unroll
            for (int s = 0; s < 16; s++) {
                int ks = 8*s + t;
                u32 af[4];
                af[0] = PS[(m0+g)*132 + ks];   af[1] = PS[(m0+g+8)*132 + ks];
                af[2] = PS[(m0+g)*132 + ks+4]; af[3] = PS[(m0+g+8)*132 + ks+4];
                #pragma unroll
                for (int j = 0; j < 4; j++) {
                    int n = n0o + 8*j + g;
                    u32 bf2[2];
                    bf2[0] = VS[ks*72 + n]; bf2[1] = VS[(ks+4)*72 + n];
                    mma8(acco[j], af, bf2);
                }
            }
        }
        __syncthreads();
    }
    size_t pb = ((size_t)(bh*4 + sp) * MM + r0);
    #pragma unroll
    for (int j = 0; j < 4; j++) {
        int col = n0o + 8*j + 2*t;
        *(float2*)&g_part[(pb + m0 + g) * DH + col]     = make_float2(acco[j][0], acco[j][1]);
        *(float2*)&g_part[(pb + m0 + g + 8) * DH + col] = make_float2(acco[j][2], acco[j][3]);
    }
    if (tid < 64) {
        g_m[(bh*4 + sp) * MM + r0 + tid] = sm_m[tid];
        g_l[(bh*4 + sp) * MM + r0 + tid] = sm_l[tid];
    }
}

__global__ void attn_combine() {
    int idx = blockIdx.x * 256 + threadIdx.x;
    int bh = idx >> 14, rem = idx & 16383, row = rem >> 6, d = rem & 63;
    float ms = -1e30f;
    #pragma unroll
    for (int s = 0; s < 4; s++) ms = fmaxf(ms, g_m[(bh*4+s)*MM + row]);
    float num = 0.f, den = 0.f;
    #pragma unroll
    for (int s = 0; s < 4; s++) {
        float e = __expf(g_m[(bh*4+s)*MM + row] - ms);
        num += g_part[((size_t)(bh*4+s)*MM + row)*DH + d] * e;
        den += g_l[(bh*4+s)*MM + row] * e;
    }
    g_a3v[((size_t)bh*MM + row)*DH + d] = num / den;
}

// attn1 + fused depthwise conv; writes bf16-packed out1.
__global__ __launch_bounds__(256) void attn1_kernel(const float* __restrict__ wres) {
    extern __shared__ float smf[];
    u32* QS  = (u32*)smf;
    u32* KLS = QS + 64*68;
    u32* W2S = KLS + 256*72;
    float* sm_l = (float*)(W2S + 256*72);
    float* VC   = sm_l + 64;
    float* CONV = VC + 96*68;
    float* wl   = CONV + 64*66;
    float* SS = (float*)KLS;
    int tid = threadIdx.x;
    int r0 = blockIdx.x * 64;
    int bh = blockIdx.y;
    int lane = tid & 31, wid = tid >> 5;
    int g = lane >> 2, t = lane & 3;
    if (tid < KERN) wl[tid] = wres[(bh & 1) * KERN + tid];
    #pragma unroll
    for (int p = 0; p < 4; p++) {
        int idx = tid + p * 256; int m = idx >> 4, c = (idx & 15) * 4;
        float4 v = *(const float4*)&g_q[((size_t)bh * NSEQ + r0 + m) * DH + c];
        *(uint4*)&QS[m*68 + c] = make_uint4(f2tf(v.x), f2tf(v.y), f2tf(v.z), f2tf(v.w));
    }
    #pragma unroll
    for (int p = 0; p < 16; p++) {
        int idx = tid + p * 256; int m = idx >> 4, c = (idx & 15) * 4;
        float4 v = *(const float4*)&g_kl[((size_t)bh * MM + m) * DH + c];
        *(uint4*)&KLS[m*72 + c] = make_uint4(f2tf(v.x), f2tf(v.y), f2tf(v.z), f2tf(v.w));
        float4 w = *(const float4*)&g_w2[((size_t)bh * MM + m) * DH + c];
        *(uint4*)&W2S[m*72 + c] = make_uint4(f2tf(w.x), f2tf(w.y), f2tf(w.z), f2tf(w.w));
    }
    #pragma unroll
    for (int p = 0; p < 6; p++) {
        int idx = tid + p * 256; int li = idx >> 4, d4 = (idx & 15) * 4;
        int n = r0 - 16 + li;
        float4 val = make_float4(0.f, 0.f, 0.f, 0.f);
        if (n >= 0 && n < NSEQ) val = *(const float4*)&g_v[((size_t)bh * NSEQ + n) * DH + d4];
        *(float4*)&VC[li * 68 + d4] = val;
    }
    __syncthreads();
    int m0 = (wid & 3) * 16;
    int n0s = (wid >> 2) * 128;
    float accs[16][4];
    #pragma unroll
    for (int j = 0; j < 16; j++) for (int u = 0; u < 4; u++) accs[j][u] = 0.f;
    #pragma unroll
    for (int s = 0; s < 8; s++) {
        int ks = 8*s + t;
        u32 af[4];
        af[0] = QS[(m0+g)*68 + ks];   af[1] = QS[(m0+g+8)*68 + ks];
        af[2] = QS[(m0+g)*68 + ks+4]; af[3] = QS[(m0+g+8)*68 + ks+4];
        #pragma unroll
        for (int j = 0; j < 16; j++) {
            int n = n0s + 8*j + g;
            u32 bf2[2];
            bf2[0] = KLS[n*72 + ks]; bf2[1] = KLS[n*72 + ks + 4];
            mma8(accs[j], af, bf2);
        }
    }
    __syncthreads();
    #pragma unroll
    for (int j = 0; j < 16; j++) {
        int col = n0s + 8*j + 2*t;
        *(float2*)&SS[(m0+g)*264 + col]   = make_float2(accs[j][0], accs[j][1]);
        *(float2*)&SS[(m0+g+8)*264 + col] = make_float2(accs[j][2], accs[j][3]);
    }
    __syncthreads();
    {
        int row = tid >> 2, t2 = tid & 3;
        float* Sr = &SS[row*264 + t2*64];
        float cmax = -1e30f;
        #pragma unroll
        for (int c = 0; c < 64; c++) cmax = fmaxf(cmax, Sr[c]);
        cmax = fmaxf(cmax, __shfl_xor_sync(0xffffffffu, cmax, 1));
        cmax = fmaxf(cmax, __shfl_xor_sync(0xffffffffu, cmax, 2));
        float csum = 0.f;
        u32* Pr = (u32*)Sr;
        #pragma unroll
        for (int c = 0; c < 64; c++) {
            float pv = __expf(Sr[c] - cmax);
            csum += pv;
            Pr[c] = f2tf(pv);
        }
        csum += __shfl_xor_sync(0xffffffffu, csum, 1);
        csum += __shfl_xor_sync(0xffffffffu, csum, 2);
        if (t2 == 0) sm_l[row] = csum;
    }
    {
        int rr = tid >> 2, ds = (tid & 3) * 16;
        #pragma unroll
        for (int d4 = 0; d4 < 4; d4++) {
            float4 a4 = make_float4(0.f, 0.f, 0.f, 0.f);
            #pragma unroll
            for (int tap = 0; tap < KERN; tap++) {
                float w = wl[tap];
                float4 vv = *(const float4*)&VC[(rr + tap) * 68 + ds + d4 * 4];
                a4.x += w * vv.x; a4.y += w * vv.y; a4.z += w * vv.z; a4.w += w * vv.w;
            }
            CONV[rr * 66 + ds + d4 * 4 + 0] = a4.x;
            CONV[rr * 66 + ds + d4 * 4 + 1] = a4.y;
            CONV[rr * 66 + ds + d4 * 4 + 2] = a4.z;
            CONV[rr * 66 + ds + d4 * 4 + 3] = a4.w;
        }
    }
    __syncthreads();
    int n0o = (wid >> 2) * 32;
    float acco[4][4];
    #pragma unroll
    for (int j = 0; j < 4; j++) for (int u = 0; u < 4; u++) acco[j][u] = 0.f;
    const u32* PS = (const u32*)SS;
    #pragma unroll
    for (int s = 0; s < 32; s++) {
        int ks = 8*s + t;
        u32 af[4];
        af[0] = PS[(m0+g)*264 + ks];   af[1] = PS[(m0+g+8)*264 + ks];
        af[2] = PS[(m0+g)*264 + ks+4]; af[3] = PS[(m0+g+8)*264 + ks+4];
        #pragma unroll
        for (int j = 0; j < 4; j++) {
            int n = n0o + 8*j + g;
            u32 bf2[2];
            bf2[0] = W2S[ks*72 + n]; bf2[1] = W2S[(ks+4)*72 + n];
            mma8(acco[j], af, bf2);
        }
    }
    float il0 = 1.f / sm_l[m0 + g], il1 = 1.f / sm_l[m0 + g + 8];
    size_t ob = (size_t)bh * NSEQ + r0;
    int row0l = m0 + g, row1l = m0 + g + 8;
    #pragma unroll
    for (int j = 0; j < 4; j++) {
        int col = n0o + 8*j + 2*t;
        int dp = col >> 1;
        float v00 = acco[j][0]*il0 + CONV[row0l*66 + col];
        float v01 = acco[j][1]*il0 + CONV[row0l*66 + col + 1];
        float v10 = acco[j][2]*il1 + CONV[row1l*66 + col];
        float v11 = acco[j][3]*il1 + CONV[row1l*66 + col + 1];
        g_out1h[(ob + row0l) * 32 + dp] = pk2(v00, v01);
        g_out1h[(ob + row1l) * 32 + dp] = pk2(v10, v11);
    }
}

// ---------------- launch ----------------
extern "C" void kernel_launch(void* const* d_in, const int* in_sizes, int n_in,
                              void* d_out, int out_size) {
    const float* x     = (const float*)d_in[0];
    const float* gamma = (const float*)d_in[1];
    const float* beta  = (const float*)d_in[2];
    const float* wqkv  = (const float*)d_in[3];
    const float* wout  = (const float*)d_in[4];
    const float* bout  = (const float*)d_in[5];
    const float* wres  = (const float*)d_in[6];
    float* out = (float*)d_out;

    float *pA2, *pXZ, *pT1, *pT2, *pZA, *pZB, *pA3V, *pW2;
    cudaGetSymbolAddress((void**)&pA2, g_a2);
    cudaGetSymbolAddress((void**)&pXZ, g_xz);
    cudaGetSymbolAddress((void**)&pT1, g_t1);
    cudaGetSymbolAddress((void**)&pT2, g_t2);
    cudaGetSymbolAddress((void**)&pZA, g_za);
    cudaGetSymbolAddress((void**)&pZB, g_zb);
    cudaGetSymbolAddress((void**)&pA3V, g_a3v);
    cudaGetSymbolAddress((void**)&pW2, g_w2);

    cudaFuncSetAttribute(attn3_kernel, cudaFuncAttributeMaxDynamicSharedMemorySize, 125696);
    cudaFuncSetAttribute(attn1_kernel, cudaFuncAttributeMaxDynamicSharedMemorySize, 210000);

    init_kernel<<<1, 1>>>();
    prepack_kernel<<<512, 256>>>(wqkv, wout);
    ln_kernel<<<TOK, 128>>>(x, gamma, beta);
    qkv_mma<<<dim3(TOK / 128, 3), 256>>>();
    landmark_kernel<<<dim3(BH, MM), 64>>>();
    sim2_kernel<<<BH * MM, 256>>>();
    absmax_kernel<<<dim3(BH, 2), 256>>>();
    zinit_kernel<<<BH * MM, 256>>>();

    float* zc = pZA;
    float* zn = pZB;
    for (int it = 0; it < 6; it++) {
        bmm_mma<<<dim3(4, 4, BH), 256>>>(pA2, zc, pXZ, 1.f, 0.f, 0.f);
        bmm_mma<<<dim3(4, 4, BH), 256>>>(pXZ, pXZ, pT1, 1.f, -7.f, 15.f);
        bmm_mma<<<dim3(4, 4, BH), 256>>>(pXZ, pT1, pT2, -1.f, 0.f, 13.f);
        bmm_mma<<<dim3(4, 4, BH), 256>>>(zc, pT2, zn, 0.25f, 0.f, 0.f);
        float* t = zc; zc = zn; zn = t;
    }

    attn3_kernel<<<dim3(4, 4, BH), 256, 125696>>>();
    attn_combine<<<512, 256>>>();
    nn64_mma<<<dim3(4, 1, BH), 128>>>(zc, pA3V, pW2, MM,
        (size_t)MM * MM, (size_t)MM * 64, (size_t)MM * 64, MM);
    attn1_kernel<<<dim3(NSEQ / 64, BH), 256, 210000>>>(wres);
    outgemm_mma<<<dim3(TOK / 128, 4), 256>>>(x, bout, out);
}

// round 9
// speedup vs baseline: 1.7333x; 1.1156x over previous
#include <cuda_runtime.h>
#include <math.h>

#define BB 4
#define NSEQ 8192
#define DD 512
#define HH 2
#define DH 64
#define INNER 128
#define MM 256
#define LLM 32
#define BH (BB*HH)
#define TOK (BB*NSEQ)
#define KERN 33

typedef unsigned u32;

__device__ u32   g_xnh[(size_t)TOK*256];
__device__ u32   g_wqkvh[256*384];
__device__ u32   g_wouth[64*512];
__device__ float g_q[(size_t)BH*NSEQ*DH];
__device__ float g_k[(size_t)BH*NSEQ*DH];
__device__ float g_v[(size_t)BH*NSEQ*DH];
__device__ float g_ql[BH*MM*DH];
__device__ float g_kl[BH*MM*DH];
__device__ float g_a2[BH*MM*MM];
__device__ float g_xz[BH*MM*MM];
__device__ float g_t1[BH*MM*MM];
__device__ float g_t2[BH*MM*MM];
__device__ float g_za[BH*MM*MM];
__device__ float g_zb[BH*MM*MM];
__device__ float g_a3v[BH*MM*DH];
__device__ float g_w2[BH*MM*DH];
__device__ u32   g_out1h[(size_t)BH*NSEQ*32];
__device__ float g_part[BH*8*MM*DH];
__device__ float g_m[BH*4*MM];
__device__ float g_l[BH*4*MM];
__device__ unsigned g_max0, g_max1;

// ---- tf32 helpers (nn64 only) ----
__device__ __forceinline__ unsigned f2tf(float f) {
    unsigned r; asm("cvt.rna.tf32.f32 %0, %1;" : "=r"(r) : "f"(f)); return r;
}
__device__ __forceinline__ void mma8(float* c, const unsigned* a, const unsigned* b) {
    asm volatile("mma.sync.aligned.m16n8k8.row.col.f32.tf32.tf32.f32 "
        "{%0,%1,%2,%3}, {%4,%5,%6,%7}, {%8,%9}, {%0,%1,%2,%3};"
        : "+f"(c[0]), "+f"(c[1]), "+f"(c[2]), "+f"(c[3])
        : "r"(a[0]), "r"(a[1]), "r"(a[2]), "r"(a[3]), "r"(b[0]), "r"(b[1]));
}
// ---- bf16 helpers ----
__device__ __forceinline__ u32 pk2(float lo, float hi) {
    u32 r; asm("cvt.rn.bf16x2.f32 %0, %2, %1;" : "=r"(r) : "f"(lo), "f"(hi)); return r;
}
__device__ __forceinline__ void mmab(float* c, const u32* a, const u32* b) {
    asm volatile("mma.sync.aligned.m16n8k16.row.col.f32.bf16.bf16.f32 "
        "{%0,%1,%2,%3}, {%4,%5,%6,%7}, {%8,%9}, {%0,%1,%2,%3};"
        : "+f"(c[0]), "+f"(c[1]), "+f"(c[2]), "+f"(c[3])
        : "r"(a[0]), "r"(a[1]), "r"(a[2]), "r"(a[3]), "r"(b[0]), "r"(b[1]));
}
__device__ __forceinline__ uint4 pkA(float4 v1, float4 v2) {
    return make_uint4(pk2(v1.x,v1.y), pk2(v1.z,v1.w), pk2(v2.x,v2.y), pk2(v2.z,v2.w));
}
__device__ __forceinline__ uint4 pkB(float4 r1, float4 r2) {
    return make_uint4(pk2(r1.x,r2.x), pk2(r1.y,r2.y), pk2(r1.z,r2.z), pk2(r1.w,r2.w));
}
__device__ __forceinline__ void ldsm4(u32* r, u32 addr) {
    asm volatile("ldmatrix.sync.aligned.m8n8.x4.shared.b16 {%0,%1,%2,%3}, [%4];"
        : "=r"(r[0]), "=r"(r[1]), "=r"(r[2]), "=r"(r[3]) : "r"(addr));
}

__global__ void init_kernel() { g_max0 = 0u; g_max1 = 0u; }

__global__ void prepack_kernel(const float* __restrict__ wqkv, const float* __restrict__ wout) {
    int idx = blockIdx.x * 256 + threadIdx.x;
    if (idx < 256 * 384) {
        int kp = idx / 384, n = idx % 384;
        g_wqkvh[idx] = pk2(wqkv[(size_t)(2*kp) * 384 + n], wqkv[(size_t)(2*kp+1) * 384 + n]);
    } else {
        int j = idx - 256 * 384;
        int kp = j / 512, n = j % 512;
        g_wouth[j] = pk2(wout[(size_t)(2*kp) * 512 + n], wout[(size_t)(2*kp+1) * 512 + n]);
    }
}

__global__ __launch_bounds__(128) void ln_kernel(const float* __restrict__ x,
                                                 const float* __restrict__ gamma,
                                                 const float* __restrict__ beta) {
    int t = blockIdx.x, tid = threadIdx.x;
    const float4* xr = (const float4*)(x + (size_t)t * DD);
    float4 v = xr[tid];
    float s  = v.x + v.y + v.z + v.w;
    float sq = v.x*v.x + v.y*v.y + v.z*v.z + v.w*v.w;
    __shared__ float sb[8];
    #pragma unroll
    for (int o = 16; o; o >>= 1) {
        s  += __shfl_xor_sync(0xffffffffu, s, o);
        sq += __shfl_xor_sync(0xffffffffu, sq, o);
    }
    int w = tid >> 5, l = tid & 31;
    if (l == 0) { sb[w] = s; sb[4 + w] = sq; }
    __syncthreads();
    if (tid == 0) { sb[0] = sb[0]+sb[1]+sb[2]+sb[3]; sb[4] = sb[4]+sb[5]+sb[6]+sb[7]; }
    __syncthreads();
    float mu  = sb[0] * (1.f / DD);
    float var = sb[4] * (1.f / DD) - mu * mu;
    float rs  = rsqrtf(var + 1e-5f);
    float4 g4 = ((const float4*)gamma)[tid];
    float4 b4 = ((const float4*)beta)[tid];
    float4 o;
    o.x = (v.x - mu) * rs * g4.x + b4.x;
    o.y = (v.y - mu) * rs * g4.y + b4.y;
    o.z = (v.z - mu) * rs * g4.z + b4.z;
    o.w = (v.w - mu) * rs * g4.w + b4.w;
    uint2 pr = make_uint2(pk2(o.x, o.y), pk2(o.z, o.w));
    *(uint2*)&g_xnh[(size_t)t * 256 + tid * 2] = pr;
}

__global__ void landmark_kernel() {
    int bh = blockIdx.x, m = blockIdx.y, d = threadIdx.x;
    size_t base = ((size_t)bh * NSEQ + m * LLM) * DH + d;
    float sq = 0.f, sk = 0.f;
    #pragma unroll 8
    for (int i = 0; i < LLM; i++) { sq += g_q[base + (size_t)i * DH]; sk += g_k[base + (size_t)i * DH]; }
    g_ql[(bh * MM + m) * DH + d] = sq * (1.f / LLM);
    g_kl[(bh * MM + m) * DH + d] = sk * (1.f / LLM);
}

__global__ __launch_bounds__(256) void sim2_kernel() {
    int bh = blockIdx.x >> 8, i = blockIdx.x & 255;
    int tid = threadIdx.x;
    __shared__ float qs[DH];
    __shared__ float red[8];
    if (tid < DH) qs[tid] = g_ql[(bh * MM + i) * DH + tid];
    __syncthreads();
    const float* kr = &g_kl[(bh * MM + tid) * DH];
    float s = 0.f;
    #pragma unroll
    for (int d = 0; d < DH; d += 4) {
        float4 kv = *(const float4*)&kr[d];
        s += qs[d]*kv.x + qs[d+1]*kv.y + qs[d+2]*kv.z + qs[d+3]*kv.w;
    }
    float m = s;
    #pragma unroll
    for (int o = 16; o; o >>= 1) m = fmaxf(m, __shfl_xor_sync(0xffffffffu, m, o));
    int w = tid >> 5, l = tid & 31;
    if (l == 0) red[w] = m;
    __syncthreads();
    if (w == 0) {
        float t = red[l & 7];
        #pragma unroll
        for (int o = 4; o; o >>= 1) t = fmaxf(t, __shfl_xor_sync(0xffffffffu, t, o));
        if (l == 0) red[0] = t;
    }
    __syncthreads();
    m = red[0];
    __syncthreads();
    float e = __expf(s - m);
    float su = e;
    #pragma unroll
    for (int o = 16; o; o >>= 1) su += __shfl_xor_sync(0xffffffffu, su, o);
    if (l == 0) red[w] = su;
    __syncthreads();
    if (w == 0) {
        float t = red[l & 7];
        #pragma unroll
        for (int o = 4; o; o >>= 1) t += __shfl_xor_sync(0xffffffffu, t, o);
        if (l == 0) red[0] = t;
    }
    __syncthreads();
    g_a2[((size_t)bh * MM + i) * MM + tid] = e / red[0];
}

__global__ __launch_bounds__(256) void absmax_kernel() {
    int bh = blockIdx.x, mode = blockIdx.y, tid = threadIdx.x;
    const float* A = &g_a2[(size_t)bh * MM * MM];
    float s = 0.f;
    if (mode == 0) { for (int j = 0; j < MM; j++) s += fabsf(A[tid * MM + j]); }
    else           { for (int i = 0; i < MM; i++) s += fabsf(A[i * MM + tid]); }
    float m = s;
    #pragma unroll
    for (int o = 16; o; o >>= 1) m = fmaxf(m, __shfl_xor_sync(0xffffffffu, m, o));
    __shared__ float red[8];
    int w = tid >> 5, l = tid & 31;
    if (l == 0) red[w] = m;
    __syncthreads();
    if (tid == 0) {
        float t = red[0];
        for (int u = 1; u < 8; u++) t = fmaxf(t, red[u]);
        atomicMax(mode == 0 ? &g_max0 : &g_max1, __float_as_uint(t));
    }
}

__global__ __launch_bounds__(256) void zinit_kernel() {
    int bh = blockIdx.x >> 8, i = blockIdx.x & 255, j = threadIdx.x;
    float inv = 1.f / (__uint_as_float(g_max0) * __uint_as_float(g_max1));
    g_za[((size_t)bh * MM + i) * MM + j] = g_a2[((size_t)bh * MM + j) * MM + i] * inv;
}

// ---------- bf16 packed GEMMs ----------
__global__ __launch_bounds__(256) void qkv_mma() {
    __shared__ u32 SA[2][128*20];
    __shared__ u32 SB[2][16*136];
    int tid = threadIdx.x;
    int row0 = blockIdx.x * 128, col0 = blockIdx.y * 128;
    int lane = tid & 31, wid = tid >> 5;
    int g = lane >> 2, t = lane & 3;
    int wm = (wid & 1) * 64, wn = (wid >> 1) * 32;
    int mi = lane >> 3;
    int lrow = (lane & 7) + (mi & 1) * 8;
    int lcol = (mi >> 1) * 4;
    float acc[4][4][4];
    #pragma unroll
    for (int i = 0; i < 4; i++) for (int j = 0; j < 4; j++) for (int u = 0; u < 4; u++) acc[i][j][u] = 0.f;
    uint4 ua[2], ub[2];
    auto LOAD = [&](int kt) {
        int kp0 = kt >> 1;
        #pragma unroll
        for (int p = 0; p < 2; p++) {
            int idx = tid + p * 256; int m = idx >> 2, kg = idx & 3;
            ua[p] = *(const uint4*)&g_xnh[(size_t)(row0 + m) * 256 + kp0 + kg * 4];
        }
        #pragma unroll
        for (int p = 0; p < 2; p++) {
            int idx = tid + p * 256; int kp = idx >> 5, n4 = (idx & 31) * 4;
            ub[p] = *(const uint4*)&g_wqkvh[(size_t)(kp0 + kp) * 384 + col0 + n4];
        }
    };
    auto STS = [&](int buf) {
        #pragma unroll
        for (int p = 0; p < 2; p++) {
            int idx = tid + p * 256; int m = idx >> 2, kg = idx & 3;
            *(uint4*)&SA[buf][m * 20 + kg * 4] = ua[p];
        }
        #pragma unroll
        for (int p = 0; p < 2; p++) {
            int idx = tid + p * 256; int kp = idx >> 5, n4 = (idx & 31) * 4;
            *(uint4*)&SB[buf][kp * 136 + n4] = ub[p];
        }
    };
    auto COMP = [&](int buf) {
        u32 sa0 = (u32)__cvta_generic_to_shared(&SA[buf][(wm + lrow) * 20 + lcol]);
        #pragma unroll
        for (int s = 0; s < 2; s++) {
            int kp = 8 * s + t;
            u32 af[4][4], bf[4][2];
            #pragma unroll
            for (int i = 0; i < 4; i++)
                ldsm4(af[i], sa0 + ((16 * i * 20 + 8 * s) << 2));
            #pragma unroll
            for (int j = 0; j < 4; j++) {
                int n = wn + 8 * j + g;
                bf[j][0] = SB[buf][kp * 136 + n];
                bf[j][1] = SB[buf][(kp + 4) * 136 + n];
            }
            #pragma unroll
            for (int i = 0; i < 4; i++)
                #pragma unroll
                for (int j = 0; j < 4; j++) mmab(acc[i][j], af[i], bf[j]);
        }
    };
    LOAD(0); STS(0); __syncthreads();
    for (int it = 0; it < 16; it++) {
        if (it + 1 < 16) LOAD((it + 1) * 32);
        COMP(it & 1);
        if (it + 1 < 16) { STS((it + 1) & 1); __syncthreads(); }
    }
    auto STORE2 = [&](int tok, int c, float v0, float v1) {
        int bb = tok >> 13, n = tok & 8191;
        int which = c >> 7, hd = c & 127, h = hd >> 6, d = hd & 63;
        size_t dst = (((size_t)(bb * HH + h)) * NSEQ + n) * DH + d;
        if (which == 0)      *(float2*)&g_q[dst] = make_float2(v0 * 0.125f, v1 * 0.125f);
        else if (which == 1) *(float2*)&g_k[dst] = make_float2(v0, v1);
        else                 *(float2*)&g_v[dst] = make_float2(v0, v1);
    };
    #pragma unroll
    for (int i = 0; i < 4; i++) {
        int row = row0 + wm + 16 * i + g;
        #pragma unroll
        for (int j = 0; j < 4; j++) {
            int col = col0 + wn + 8 * j + 2 * t;
            STORE2(row, col, acc[i][j][0], acc[i][j][1]);
            STORE2(row + 8, col, acc[i][j][2], acc[i][j][3]);
        }
    }
}

__global__ __launch_bounds__(256) void outgemm_mma(const float* __restrict__ x,
                                                   const float* __restrict__ bout,
                                                   float* __restrict__ out) {
    __shared__ u32 SA[2][128*20];
    __shared__ u32 SB[2][16*136];
    int tid = threadIdx.x;
    int row0 = blockIdx.x * 128, col0 = blockIdx.y * 128;
    int lane = tid & 31, wid = tid >> 5;
    int g = lane >> 2, t = lane & 3;
    int wm = (wid & 1) * 64, wn = (wid >> 1) * 32;
    int mi = lane >> 3;
    int lrow = (lane & 7) + (mi & 1) * 8;
    int lcol = (mi >> 1) * 4;
    float acc[4][4][4];
    #pragma unroll
    for (int i = 0; i < 4; i++) for (int j = 0; j < 4; j++) for (int u = 0; u < 4; u++) acc[i][j][u] = 0.f;
    uint4 ua[2], ub[2];
    auto LOAD = [&](int kt) {
        int kp0 = kt >> 1;
        #pragma unroll
        for (int p = 0; p < 2; p++) {
            int idx = tid + p * 256; int m = idx >> 2, kg = idx & 3;
            int tok = row0 + m; int bb = tok >> 13, n = tok & 8191;
            int kp = kp0 + kg * 4;
            int h = kp >> 5, dp = kp & 31;
            ua[p] = *(const uint4*)&g_out1h[(((size_t)(bb * HH + h)) * NSEQ + n) * 32 + dp];
        }
        #pragma unroll
        for (int p = 0; p < 2; p++) {
            int idx = tid + p * 256; int kp = idx >> 5, n4 = (idx & 31) * 4;
            ub[p] = *(const uint4*)&g_wouth[(size_t)(kp0 + kp) * 512 + col0 + n4];
        }
    };
    auto STS = [&](int buf) {
        #pragma unroll
        for (int p = 0; p < 2; p++) {
            int idx = tid + p * 256; int m = idx >> 2, kg = idx & 3;
            *(uint4*)&SA[buf][m * 20 + kg * 4] = ua[p];
        }
        #pragma unroll
        for (int p = 0; p < 2; p++) {
            int idx = tid + p * 256; int kp = idx >> 5, n4 = (idx & 31) * 4;
            *(uint4*)&SB[buf][kp * 136 + n4] = ub[p];
        }
    };
    auto COMP = [&](int buf) {
        u32 sa0 = (u32)__cvta_generic_to_shared(&SA[buf][(wm + lrow) * 20 + lcol]);
        #pragma unroll
        for (int s = 0; s < 2; s++) {
            int kp = 8 * s + t;
            u32 af[4][4], bf[4][2];
            #pragma unroll
            for (int i = 0; i < 4; i++)
                ldsm4(af[i], sa0 + ((16 * i * 20 + 8 * s) << 2));
            #pragma unroll
            for (int j = 0; j < 4; j++) {
                int n = wn + 8 * j + g;
                bf[j][0] = SB[buf][kp * 136 + n];
                bf[j][1] = SB[buf][(kp + 4) * 136 + n];
            }
            #pragma unroll
            for (int i = 0; i < 4; i++)
                #pragma unroll
                for (int j = 0; j < 4; j++) mmab(acc[i][j], af[i], bf[j]);
        }
    };
    LOAD(0); STS(0); __syncthreads();
    for (int it = 0; it < 4; it++) {
        if (it + 1 < 4) LOAD((it + 1) * 32);
        COMP(it & 1);
        if (it + 1 < 4) { STS((it + 1) & 1); __syncthreads(); }
    }
    #pragma unroll
    for (int i = 0; i < 4; i++) {
        int row = row0 + wm + 16 * i + g;
        #pragma unroll
        for (int j = 0; j < 4; j++) {
            int col = col0 + wn + 8 * j + 2 * t;
            float2 bb = *(const float2*)&bout[col];
            float2 x0 = *(const float2*)&x[(size_t)row*DD + col];
            float2 x1 = *(const float2*)&x[(size_t)(row+8)*DD + col];
            *(float2*)&out[(size_t)row*DD + col] =
                make_float2(acc[i][j][0] + bb.x + x0.x, acc[i][j][1] + bb.y + x0.y);
            *(float2*)&out[(size_t)(row+8)*DD + col] =
                make_float2(acc[i][j][2] + bb.x + x1.x, acc[i][j][3] + bb.y + x1.y);
        }
    }
}

__global__ __launch_bounds__(256) void bmm_mma(const float* __restrict__ A,
                                               const float* __restrict__ Bm,
                                               float* __restrict__ C,
                                               float alpha, float beta, float gam) {
    __shared__ u32 SA[2][64*20];
    __shared__ u32 SB[2][16*72];
    int bh = blockIdx.z;
    size_t base = (size_t)bh * MM * MM;
    int i0 = blockIdx.x * 64, j0 = blockIdx.y * 64;
    int tid = threadIdx.x;
    int lane = tid & 31, wid = tid >> 5;
    int g = lane >> 2, t = lane & 3;
    int wm = (wid & 3) * 16, wn = (wid >> 2) * 32;
    int mi = lane >> 3;
    int lrow = (lane & 7) + (mi & 1) * 8;
    int lcol = (mi >> 1) * 4;
    float acc[4][4];
    #pragma unroll
    for (int j = 0; j < 4; j++) for (int u = 0; u < 4; u++) acc[j][u] = 0.f;
    int am = tid >> 2, akg = tid & 3;
    int bkp = tid >> 4, bn4 = (tid & 15) * 4;
    float4 a1, a2, b1, b2;
    auto LOAD = [&](int kt) {
        const float* src = &A[base + (size_t)(i0 + am) * MM + kt + akg * 8];
        a1 = *(const float4*)src;
        a2 = *(const float4*)(src + 4);
        int k = kt + bkp * 2;
        b1 = *(const float4*)&Bm[base + (size_t)k * MM + j0 + bn4];
        b2 = *(const float4*)&Bm[base + (size_t)(k + 1) * MM + j0 + bn4];
    };
    auto STS = [&](int buf) {
        *(uint4*)&SA[buf][am * 20 + akg * 4] = pkA(a1, a2);
        *(uint4*)&SB[buf][bkp * 72 + bn4] = pkB(b1, b2);
    };
    auto COMP = [&](int buf) {
        u32 sa0 = (u32)__cvta_generic_to_shared(&SA[buf][(wm + lrow) * 20 + lcol]);
        #pragma unroll
        for (int s = 0; s < 2; s++) {
            int kp = 8 * s + t;
            u32 af[4], bf[4][2];
            ldsm4(af, sa0 + ((8 * s) << 2));
            #pragma unroll
            for (int j = 0; j < 4; j++) {
                int n = wn + 8 * j + g;
                bf[j][0] = SB[buf][kp * 72 + n];
                bf[j][1] = SB[buf][(kp + 4) * 72 + n];
            }
            #pragma unroll
            for (int j = 0; j < 4; j++) mmab(acc[j], af, bf[j]);
        }
    };
    LOAD(0); STS(0); __syncthreads();
    for (int it = 0; it < 8; it++) {
        if (it + 1 < 8) LOAD((it + 1) * 32);
        COMP(it & 1);
        if (it + 1 < 8) { STS((it + 1) & 1); __syncthreads(); }
    }
    #pragma unroll
    for (int j = 0; j < 4; j++) {
        #pragma unroll
        for (int u = 0; u < 4; u++) {
            int row = i0 + wm + g + (u >> 1) * 8;
            int col = j0 + wn + 8 * j + 2 * t + (u & 1);
            float r = alpha * acc[j][u];
            if (beta != 0.f) r += beta * A[base + (size_t)row * MM + col];
            if (row == col) r += gam;
            C[base + (size_t)row * MM + col] = r;
        }
    }
}

// NN, N=64 tf32 (W2 = Z @ a3v only)
__global__ __launch_bounds__(128) void nn64_mma(const float* __restrict__ A,
                                                const float* __restrict__ B,
                                                float* __restrict__ C,
                                                int lda, size_t aBatch, size_t bBatch,
                                                size_t cBatch, int kchunk) {
    __shared__ unsigned As[64*36];
    __shared__ unsigned Bs[32*72];
    int bh = blockIdx.z;
    int m0 = blockIdx.x * 64;
    const float* Ab = A + (size_t)bh * aBatch + (size_t)m0 * lda;
    const float* Bb = B + (size_t)bh * bBatch;
    int tid = threadIdx.x;
    int lane = tid & 31, wid = tid >> 5;
    int g = lane >> 2, t = lane & 3;
    int wm = (wid & 1) * 32, wn = (wid >> 1) * 32;
    float acc[2][4][4];
    #pragma unroll
    for (int i = 0; i < 2; i++) for (int j = 0; j < 4; j++) for (int u = 0; u < 4; u++) acc[i][j][u] = 0.f;
    int iters = kchunk / 32;
    for (int it = 0; it < iters; it++) {
        #pragma unroll
        for (int p = 0; p < 4; p++) {
            int idx = tid + p * 128; int m = idx >> 3, c = (idx & 7) * 4;
            float4 v = *(const float4*)&Ab[(size_t)m * lda + it*32 + c];
            *(uint4*)&As[m*36+c] = make_uint4(f2tf(v.x), f2tf(v.y), f2tf(v.z), f2tf(v.w));
        }
        #pragma unroll
        for (int p = 0; p < 4; p++) {
            int idx = tid + p * 128; int k = idx >> 4, c = (idx & 15) * 4;
            float4 v = *(const float4*)&Bb[(size_t)(it*32 + k) * 64 + c];
            *(uint4*)&Bs[k*72+c] = make_uint4(f2tf(v.x), f2tf(v.y), f2tf(v.z), f2tf(v.w));
        }
        __syncthreads();
        #pragma unroll
        for (int s = 0; s < 4; s++) {
            unsigned af[2][4], bf[4][2];
            #pragma unroll
            for (int i = 0; i < 2; i++) {
                const unsigned* p = &As[(wm + 16*i + g)*36 + 8*s + t];
                af[i][0] = p[0]; af[i][1] = p[288]; af[i][2] = p[4]; af[i][3] = p[292];
            }
            #pragma unroll
            for (int j = 0; j < 4; j++) {
                const unsigned* p = &Bs[(8*s + t)*72 + wn + 8*j + g];
                bf[j][0] = p[0]; bf[j][1] = p[288];
            }
            #pragma unroll
            for (int i = 0; i < 2; i++)
                #pragma unroll
                for (int j = 0; j < 4; j++) mma8(acc[i][j], af[i], bf[j]);
        }
        __syncthreads();
    }
    float* Cb = C + (size_t)bh * cBatch + (size_t)m0 * 64;
    #pragma unroll
    for (int i = 0; i < 2; i++) {
        int row = wm + 16*i + g;
        #pragma unroll
        for (int j = 0; j < 4; j++) {
            int col = wn + 8*j + 2*t;
            Cb[(size_t)row*64 + col]       = acc[i][j][0];
            Cb[(size_t)row*64 + col+1]     = acc[i][j][1];
            Cb[(size_t)(row+8)*64 + col]   = acc[i][j][2];
            Cb[(size_t)(row+8)*64 + col+1] = acc[i][j][3];
        }
    }
}

// ---------- fused flash kernels (bf16) ----------
__global__ __launch_bounds__(256) void attn3_kernel() {
    extern __shared__ u32 smu[];
    u32* QS = smu;                      // [64][36]
    u32* KS = QS + 64*36;               // [128][36]
    u32* VS = KS + 128*36;              // [64][72]
    float* SS = (float*)(VS + 64*72);   // [64][132]
    u32* PS = (u32*)(SS + 64*132);      // [64][68]
    float* sm_m = (float*)(PS + 64*68);
    float* sm_l = sm_m + 64;
    float* sm_sc = sm_l + 64;
    int tid = threadIdx.x;
    int r0 = blockIdx.x * 64, sp = blockIdx.y, bh = blockIdx.z;
    int lane = tid & 31, wid = tid >> 5;
    int g = lane >> 2, t = lane & 3;
    int mi = lane >> 3;
    int lrow = (lane & 7) + (mi & 1) * 8;
    int lcol = (mi >> 1) * 4;
    #pragma unroll
    for (int p = 0; p < 2; p++) {
        int idx = tid + p * 256; int m = idx >> 3, kg = idx & 7;
        const float* src = &g_ql[((size_t)bh * MM + r0 + m) * DH + kg * 8];
        *(uint4*)&QS[m*36 + kg*4] = pkA(*(const float4*)src, *(const float4*)(src + 4));
    }
    if (tid < 64) { sm_m[tid] = -1e30f; sm_l[tid] = 0.f; }
    int m0 = (wid & 3) * 16;
    int n0s = (wid >> 2) * 64;
    int n0o = (wid >> 2) * 32;
    float acco[4][4];
    #pragma unroll
    for (int j = 0; j < 4; j++) for (int u = 0; u < 4; u++) acco[j][u] = 0.f;
    __syncthreads();
    for (int ch = 0; ch < 16; ch++) {
        int k0 = sp * 2048 + ch * 128;
        #pragma unroll
        for (int p = 0; p < 4; p++) {
            int idx = tid + p * 256; int key = idx >> 3, kg = idx & 7;
            const float* src = &g_k[((size_t)bh * NSEQ + k0 + key) * DH + kg * 8];
            *(uint4*)&KS[key*36 + kg*4] = pkA(*(const float4*)src, *(const float4*)(src + 4));
        }
        #pragma unroll
        for (int p = 0; p < 4; p++) {
            int idx = tid + p * 256; int kp = idx >> 4, n4 = (idx & 15) * 4;
            const float* s0 = &g_v[((size_t)bh * NSEQ + k0 + 2*kp) * DH + n4];
            *(uint4*)&VS[kp*72 + n4] = pkB(*(const float4*)s0, *(const float4*)(s0 + DH));
        }
        __syncthreads();
        float accs[8][4];
        #pragma unroll
        for (int j = 0; j < 8; j++) for (int u = 0; u < 4; u++) accs[j][u] = 0.f;
        u32 qa = (u32)__cvta_generic_to_shared(&QS[(m0 + lrow)*36 + lcol]);
        #pragma unroll
        for (int s = 0; s < 2; s++) {
            u32 af[4];
            ldsm4(af, qa + ((8 * s) << 2));
            #pragma unroll
            for (int j = 0; j < 8; j++) {
                int n = n0s + 8*j + g;
                u32 bf2[2];
                bf2[0] = KS[n*36 + 8*s + t];
                bf2[1] = KS[n*36 + 8*s + t + 4];
                mmab(accs[j], af, bf2);
            }
        }
        #pragma unroll
        for (int j = 0; j < 8; j++) {
            int col = n0s + 8*j + 2*t;
            *(float2*)&SS[(m0+g)*132 + col]   = make_float2(accs[j][0], accs[j][1]);
            *(float2*)&SS[(m0+g+8)*132 + col] = make_float2(accs[j][2], accs[j][3]);
        }
        __syncthreads();
        {
            int row = tid >> 2, t2 = tid & 3;
            float* Sr = &SS[row*132 + t2*32];
            float cmax = -1e30f;
            #pragma unroll
            for (int c = 0; c < 32; c++) cmax = fmaxf(cmax, Sr[c]);
            cmax = fmaxf(cmax, __shfl_xor_sync(0xffffffffu, cmax, 1));
            cmax = fmaxf(cmax, __shfl_xor_sync(0xffffffffu, cmax, 2));
            float mold = sm_m[row];
            float mnew = fmaxf(mold, cmax);
            float csum = 0.f;
            #pragma unroll
            for (int c = 0; c < 32; c += 2) {
                float pv0 = __expf(Sr[c] - mnew);
                float pv1 = __expf(Sr[c+1] - mnew);
                csum += pv0 + pv1;
                PS[row*68 + t2*16 + (c >> 1)] = pk2(pv0, pv1);
            }
            csum += __shfl_xor_sync(0xffffffffu, csum, 1);
            csum += __shfl_xor_sync(0xffffffffu, csum, 2);
            if (t2 == 0) {
                float scv = __expf(mold - mnew);
                sm_sc[row] = scv;
                sm_l[row] = sm_l[row] * scv + csum;
                sm_m[row] = mnew;
            }
        }
        __syncthreads();
        {
            float s0 = sm_sc[m0 + g], s1 = sm_sc[m0 + g + 8];
            #pragma unroll
            for (int j = 0; j < 4; j++) {
                acco[j][0] *= s0; acco[j][1] *= s0;
                acco[j][2] *= s1; acco[j][3] *= s1;
            }
            u32 pa = (u32)__cvta_generic_to_shared(&PS[(m0 + lrow)*68 + lcol]);
            #pragma unroll
            for (int s = 0; s < 8; s++) {
                u32 af[4];
                ldsm4(af, pa + ((8 * s) << 2));
                #pragma unroll
                for (int j = 0; j < 4; j++) {
                    int n = n0o + 8*j + g;
                    u32 bf2[2];
                    bf2[0] = VS[(8*s + t)*72 + n];
                    bf2[1] = VS[(8*s + t + 4)*72 + n];
                    mmab(acco[j], af, bf2);
                }
            }
        }
        __syncthreads();
    }
    size_t pb = ((size_t)(bh*4 + sp) * MM + r0);
    #pragma unroll
    for (int j = 0; j < 4; j++) {
        int col = n0o + 8*j + 2*t;
        *(float2*)&g_part[(pb + m0 + g) * DH + col]     = make_float2(acco[j][0], acco[j][1]);
        *(float2*)&g_part[(pb + m0 + g + 8) * DH + col] = make_float2(acco[j][2], acco[j][3]);
    }
    if (tid < 64) {
        g_m[(bh*4 + sp) * MM + r0 + tid] = sm_m[tid];
        g_l[(bh*4 + sp) * MM + r0 + tid] = sm_l[tid];
    }
}

__global__ void attn_combine() {
    int idx = blockIdx.x * 256 + threadIdx.x;
    int bh = idx >> 14, rem = idx & 16383, row = rem >> 6, d = rem & 63;
    float ms = -1e30f;
    #pragma unroll
    for (int s = 0; s < 4; s++) ms = fmaxf(ms, g_m[(bh*4+s)*MM + row]);
    float num = 0.f, den = 0.f;
    #pragma unroll
    for (int s = 0; s < 4; s++) {
        float e = __expf(g_m[(bh*4+s)*MM + row] - ms);
        num += g_part[((size_t)(bh*4+s)*MM + row)*DH + d] * e;
        den += g_l[(bh*4+s)*MM + row] * e;
    }
    g_a3v[((size_t)bh*MM + row)*DH + d] = num / den;
}

// attn1 (bf16) + fused depthwise conv; writes bf16-packed out1.
__global__ __launch_bounds__(256) void attn1_kernel(const float* __restrict__ wres) {
    extern __shared__ u32 smu[];
    u32* QS  = smu;                     // [64][36]
    u32* KLS = QS + 64*36;              // [256][36]
    u32* W2S = KLS + 256*36;            // [128][72]
    float* SS = (float*)(W2S + 128*72); // [64][264]; VC aliases SS base [96][68]
    u32* PS = (u32*)(SS + 64*264);      // [64][132]
    float* CONV = (float*)(PS + 64*132);// [64][66]
    float* sm_l = CONV + 64*66;         // [64]
    float* wl = sm_l + 64;              // [33]
    float* VC = SS;
    int tid = threadIdx.x;
    int r0 = blockIdx.x * 64, bh = blockIdx.y;
    int lane = tid & 31, wid = tid >> 5;
    int g = lane >> 2, t = lane & 3;
    int mi = lane >> 3;
    int lrow = (lane & 7) + (mi & 1) * 8;
    int lcol = (mi >> 1) * 4;
    if (tid < KERN) wl[tid] = wres[(bh & 1) * KERN + tid];
    #pragma unroll
    for (int p = 0; p < 2; p++) {
        int idx = tid + p * 256; int m = idx >> 3, kg = idx & 7;
        const float* src = &g_q[((size_t)bh * NSEQ + r0 + m) * DH + kg * 8];
        *(uint4*)&QS[m*36 + kg*4] = pkA(*(const float4*)src, *(const float4*)(src + 4));
    }
    #pragma unroll
    for (int p = 0; p < 8; p++) {
        int idx = tid + p * 256; int m = idx >> 3, kg = idx & 7;
        const float* src = &g_kl[((size_t)bh * MM + m) * DH + kg * 8];
        *(uint4*)&KLS[m*36 + kg*4] = pkA(*(const float4*)src, *(const float4*)(src + 4));
    }
    #pragma unroll
    for (int p = 0; p < 8; p++) {
        int idx = tid + p * 256; int kp = idx >> 4, n4 = (idx & 15) * 4;
        const float* s0 = &g_w2[((size_t)bh * MM + 2*kp) * DH + n4];
        *(uint4*)&W2S[kp*72 + n4] = pkB(*(const float4*)s0, *(const float4*)(s0 + DH));
    }
    #pragma unroll
    for (int p = 0; p < 6; p++) {
        int idx = tid + p * 256; int li = idx >> 4, d4 = (idx & 15) * 4;
        int n = r0 - 16 + li;
        float4 val = make_float4(0.f, 0.f, 0.f, 0.f);
        if (n >= 0 && n < NSEQ) val = *(const float4*)&g_v[((size_t)bh * NSEQ + n) * DH + d4];
        *(float4*)&VC[li * 68 + d4] = val;
    }
    __syncthreads();
    // conv (reads VC which aliases SS; must finish before SS writes)
    {
        int rr = tid >> 2, ds = (tid & 3) * 16;
        #pragma unroll
        for (int d4 = 0; d4 < 4; d4++) {
            float4 a4 = make_float4(0.f, 0.f, 0.f, 0.f);
            #pragma unroll
            for (int tap = 0; tap < KERN; tap++) {
                float w = wl[tap];
                float4 vv = *(const float4*)&VC[(rr + tap) * 68 + ds + d4 * 4];
                a4.x += w * vv.x; a4.y += w * vv.y; a4.z += w * vv.z; a4.w += w * vv.w;
            }
            CONV[rr * 66 + ds + d4 * 4 + 0] = a4.x;
            CONV[rr * 66 + ds + d4 * 4 + 1] = a4.y;
            CONV[rr * 66 + ds + d4 * 4 + 2] = a4.z;
            CONV[rr * 66 + ds + d4 * 4 + 3] = a4.w;
        }
    }
    int m0 = (wid & 3) * 16;
    int n0s = (wid >> 2) * 128;
    float accs[16][4];
    #pragma unroll
    for (int j = 0; j < 16; j++) for (int u = 0; u < 4; u++) accs[j][u] = 0.f;
    u32 qa = (u32)__cvta_generic_to_shared(&QS[(m0 + lrow)*36 + lcol]);
    #pragma unroll
    for (int s = 0; s < 2; s++) {
        u32 af[4];
        ldsm4(af, qa + ((8 * s) << 2));
        #pragma unroll
        for (int j = 0; j < 16; j++) {
            int n = n0s + 8*j + g;
            u32 bf2[2];
            bf2[0] = KLS[n*36 + 8*s + t];
            bf2[1] = KLS[n*36 + 8*s + t + 4];
            mmab(accs[j], af, bf2);
        }
    }
    __syncthreads();   // VC reads (conv) done everywhere before SS overwrite
    #pragma unroll
    for (int j = 0; j < 16; j++) {
        int col = n0s + 8*j + 2*t;
        *(float2*)&SS[(m0+g)*264 + col]   = make_float2(accs[j][0], accs[j][1]);
        *(float2*)&SS[(m0+g+8)*264 + col] = make_float2(accs[j][2], accs[j][3]);
    }
    __syncthreads();
    {
        int row = tid >> 2, t2 = tid & 3;
        float* Sr = &SS[row*264 + t2*64];
        float cmax = -1e30f;
        #pragma unroll
        for (int c = 0; c < 64; c++) cmax = fmaxf(cmax, Sr[c]);
        cmax = fmaxf(cmax, __shfl_xor_sync(0xffffffffu, cmax, 1));
        cmax = fmaxf(cmax, __shfl_xor_sync(0xffffffffu, cmax, 2));
        float csum = 0.f;
        #pragma unroll
        for (int c = 0; c < 64; c += 2) {
            float pv0 = __expf(Sr[c] - cmax);
            float pv1 = __expf(Sr[c+1] - cmax);
            csum += pv0 + pv1;
            PS[row*132 + t2*32 + (c >> 1)] = pk2(pv0, pv1);
        }
        csum += __shfl_xor_sync(0xffffffffu, csum, 1);
        csum += __shfl_xor_sync(0xffffffffu, csum, 2);
        if (t2 == 0) sm_l[row] = csum;
    }
    __syncthreads();
    int n0o = (wid >> 2) * 32;
    float acco[4][4];
    #pragma unroll
    for (int j = 0; j < 4; j++) for (int u = 0; u < 4; u++) acco[j][u] = 0.f;
    u32 pa = (u32)__cvta_generic_to_shared(&PS[(m0 + lrow)*132 + lcol]);
    #pragma unroll
    for (int s = 0; s < 16; s++) {
        u32 af[4];
        ldsm4(af, pa + ((8 * s) << 2));
        #pragma unroll
        for (int j = 0; j < 4; j++) {
            int n = n0o + 8*j + g;
            u32 bf2[2];
            bf2[0] = W2S[(8*s + t)*72 + n];
            bf2[1] = W2S[(8*s + t + 4)*72 + n];
            mmab(acco[j], af, bf2);
        }
    }
    float il0 = 1.f / sm_l[m0 + g], il1 = 1.f / sm_l[m0 + g + 8];
    size_t ob = (size_t)bh * NSEQ + r0;
    int row0l = m0 + g, row1l = m0 + g + 8;
    #pragma unroll
    for (int j = 0; j < 4; j++) {
        int col = n0o + 8*j + 2*t;
        int dp = col >> 1;
        float v00 = acco[j][0]*il0 + CONV[row0l*66 + col];
        float v01 = acco[j][1]*il0 + CONV[row0l*66 + col + 1];
        float v10 = acco[j][2]*il1 + CONV[row1l*66 + col];
        float v11 = acco[j][3]*il1 + CONV[row1l*66 + col + 1];
        g_out1h[(ob + row0l) * 32 + dp] = pk2(v00, v01);
        g_out1h[(ob + row1l) * 32 + dp] = pk2(v10, v11);
    }
}

// ---------------- launch ----------------
extern "C" void kernel_launch(void* const* d_in, const int* in_sizes, int n_in,
                              void* d_out, int out_size) {
    const float* x     = (const float*)d_in[0];
    const float* gamma = (const float*)d_in[1];
    const float* beta  = (const float*)d_in[2];
    const float* wqkv  = (const float*)d_in[3];
    const float* wout  = (const float*)d_in[4];
    const float* bout  = (const float*)d_in[5];
    const float* wres  = (const float*)d_in[6];
    float* out = (float*)d_out;

    float *pA2, *pXZ, *pT1, *pT2, *pZA, *pZB, *pA3V, *pW2;
    cudaGetSymbolAddress((void**)&pA2, g_a2);
    cudaGetSymbolAddress((void**)&pXZ, g_xz);
    cudaGetSymbolAddress((void**)&pT1, g_t1);
    cudaGetSymbolAddress((void**)&pT2, g_t2);
    cudaGetSymbolAddress((void**)&pZA, g_za);
    cudaGetSymbolAddress((void**)&pZB, g_zb);
    cudaGetSymbolAddress((void**)&pA3V, g_a3v);
    cudaGetSymbolAddress((void**)&pW2, g_w2);

    // attn3 smem: (64*36 + 128*36 + 64*72 + 64*132 + 64*68 + 192) * 4 = 98048 B
    cudaFuncSetAttribute(attn3_kernel, cudaFuncAttributeMaxDynamicSharedMemorySize, 98048);
    // attn1 smem: (64*36 + 256*36 + 128*72 + 64*264 + 64*132 + 64*66 + 64 + 40) * 4 = 201632 B
    cudaFuncSetAttribute(attn1_kernel, cudaFuncAttributeMaxDynamicSharedMemorySize, 201664);

    init_kernel<<<1, 1>>>();
    prepack_kernel<<<512, 256>>>(wqkv, wout);
    ln_kernel<<<TOK, 128>>>(x, gamma, beta);
    qkv_mma<<<dim3(TOK / 128, 3), 256>>>();
    landmark_kernel<<<dim3(BH, MM), 64>>>();
    sim2_kernel<<<BH * MM, 256>>>();
    absmax_kernel<<<dim3(BH, 2), 256>>>();
    zinit_kernel<<<BH * MM, 256>>>();

    float* zc = pZA;
    float* zn = pZB;
    for (int it = 0; it < 6; it++) {
        bmm_mma<<<dim3(4, 4, BH), 256>>>(pA2, zc, pXZ, 1.f, 0.f, 0.f);
        bmm_mma<<<dim3(4, 4, BH), 256>>>(pXZ, pXZ, pT1, 1.f, -7.f, 15.f);
        bmm_mma<<<dim3(4, 4, BH), 256>>>(pXZ, pT1, pT2, -1.f, 0.f, 13.f);
        bmm_mma<<<dim3(4, 4, BH), 256>>>(zc, pT2, zn, 0.25f, 0.f, 0.f);
        float* t = zc; zc = zn; zn = t;
    }

    attn3_kernel<<<dim3(4, 4, BH), 256, 98048>>>();
    attn_combine<<<512, 256>>>();
    nn64_mma<<<dim3(4, 1, BH), 128>>>(zc, pA3V, pW2, MM,
        (size_t)MM * MM, (size_t)MM * 64, (size_t)MM * 64, MM);
    attn1_kernel<<<dim3(NSEQ / 64, BH), 256, 201664>>>(wres);
    outgemm_mma<<<dim3(TOK / 128, 4), 256>>>(x, bout, out);
}